// round 2
// baseline (speedup 1.0000x reference)
#include <cuda_runtime.h>

// ---------------- scratch (static device globals; no allocation) ----------------
__device__ float g_buf1[64*64*56*56];     // conv1 output (relu'd)  ~51MB
__device__ float g_wt1[294*64];           // conv1 weights transposed [r][oc]
__device__ float g_wt2[576*256];          // conv2 weights transposed [r][oc]
__device__ float g_part[64*49*256];       // conv2 per-tile pooled partials
__device__ float g_h[64*512];
__device__ float g_mu[64*32];
__device__ float g_kappa[64];
__device__ float g_z[64*32];

// ---------------- packed f32x2 helpers ----------------
static __device__ __forceinline__ unsigned long long pk2(float a, float b){
    unsigned long long r; asm("mov.b64 %0,{%1,%2};" : "=l"(r) : "f"(a), "f"(b)); return r;
}
static __device__ __forceinline__ float2 upk2(unsigned long long v){
    float2 f; asm("mov.b64 {%0,%1},%2;" : "=f"(f.x), "=f"(f.y) : "l"(v)); return f;
}
static __device__ __forceinline__ void ffma2(unsigned long long &d, unsigned long long a, unsigned long long b){
    asm("fma.rn.f32x2 %0,%1,%2,%0;" : "+l"(d) : "l"(a), "l"(b));
}

// ---------------- weight transpose + misc prep ----------------
__global__ void k_prep(const float* __restrict__ W1, const float* __restrict__ W2) {
    int stride = gridDim.x * blockDim.x;
    int i0 = blockIdx.x * blockDim.x + threadIdx.x;
    for (int i = i0; i < 294*64; i += stride) {
        int oc = i / 294, r = i - oc*294;
        g_wt1[r*64 + oc] = W1[i];
    }
    for (int i = i0; i < 576*256; i += stride) {
        int oc = i / 576, r = i - oc*576;
        g_wt2[r*256 + oc] = W2[i];
    }
}

// ---------------- conv1: [64,6,224,224] -> relu -> [64,64,56,56] ----------------
// block: (tile 0..48, n 0..63); 256 threads; tile = 8x8 outputs
#define XS1_PAD 7360    // 35*35*6 = 7350, padded to 16B-align the weight region
#define CONV1_SMEM ((XS1_PAD + 294*64) * 4)
__global__ void __launch_bounds__(256) k_conv1(const float* __restrict__ x, const float* __restrict__ b1) {
    extern __shared__ float sm[];
    float* xs = sm;
    float* ws = sm + XS1_PAD;
    int tile = blockIdx.x, n = blockIdx.y;
    int ty = tile / 7, tx = tile - ty*7;
    int tid = threadIdx.x;

    for (int i = tid; i < 294*64; i += 256) ws[i] = g_wt1[i];

    int y0 = ty*32 - 3, x0 = tx*32 - 3;
    const float* xb = x + (size_t)n*6*224*224;
    for (int i = tid; i < 7350; i += 256) {
        int ic = i / 1225; int rem = i - ic*1225;
        int py = rem / 35, px = rem - py*35;
        int gy = y0 + py, gx = x0 + px;
        float v = 0.0f;
        if ((unsigned)gy < 224u && (unsigned)gx < 224u) v = xb[(ic*224 + gy)*224 + gx];
        xs[i] = v;
    }
    __syncthreads();

    int s = tid & 63, g = tid >> 6;          // 64 spatial, 4 oc-groups of 16
    int sy = s >> 3, sx = s & 7;
    int gofs = g * 16;

    unsigned long long acc[8];
    #pragma unroll
    for (int k = 0; k < 8; k++) acc[k] = pk2(b1[gofs+2*k], b1[gofs+2*k+1]);

    const float* wsp = ws + gofs;
    int r = 0;
    for (int ic = 0; ic < 6; ic++) {
        #pragma unroll
        for (int kh = 0; kh < 7; kh++) {
            const float* xr = xs + ic*1225 + (sy*4 + kh)*35 + sx*4;
            #pragma unroll
            for (int kw = 0; kw < 7; kw++) {
                float xv = xr[kw];
                unsigned long long xx = pk2(xv, xv);
                const ulonglong2* wp = (const ulonglong2*)(wsp + r*64);
                ulonglong2 w0 = wp[0], w1 = wp[1], w2 = wp[2], w3 = wp[3];
                ffma2(acc[0], xx, w0.x); ffma2(acc[1], xx, w0.y);
                ffma2(acc[2], xx, w1.x); ffma2(acc[3], xx, w1.y);
                ffma2(acc[4], xx, w2.x); ffma2(acc[5], xx, w2.y);
                ffma2(acc[6], xx, w3.x); ffma2(acc[7], xx, w3.y);
                r++;
            }
        }
    }

    int oy = ty*8 + sy, ox = tx*8 + sx;
    float* ob = g_buf1 + ((size_t)(n*64 + gofs)*56 + oy)*56 + ox;
    #pragma unroll
    for (int k = 0; k < 8; k++) {
        float2 f = upk2(acc[k]);
        ob[(size_t)(2*k)*3136]   = fmaxf(f.x, 0.0f);
        ob[(size_t)(2*k+1)*3136] = fmaxf(f.y, 0.0f);
    }
}

// ---------------- conv2 + relu + spatial-sum: -> g_part[n][tile][256] ----------------
// block: (tile 0..48, n); 256 threads; tile = 4x4 outputs, 256 oc
#define C2_CHUNK 72
#define CONV2_SMEM ((5184 + C2_CHUNK*256) * 4 + 576*4)
__global__ void __launch_bounds__(256) k_conv2(const float* __restrict__ b2) {
    extern __shared__ float sm[];
    float* xs = sm;                        // 5184
    float* ws = sm + 5184;                 // 72*256
    int*  off = (int*)(sm + 5184 + C2_CHUNK*256); // 576
    int tile = blockIdx.x, n = blockIdx.y;
    int ty = tile / 7, tx = tile - ty*7;
    int tid = threadIdx.x;

    for (int i = tid; i < 576; i += 256) {
        int ic = i / 9, rem = i - ic*9;
        off[i] = ic*81 + (rem/3)*9 + (rem - (rem/3)*3);
    }
    int y0 = ty*8 - 1, x0 = tx*8 - 1;
    const float* xb = g_buf1 + (size_t)n*64*56*56;
    for (int i = tid; i < 5184; i += 256) {
        int ic = i / 81; int rem = i - ic*81;
        int py = rem / 9, px = rem - py*9;
        int gy = y0 + py, gx = x0 + px;
        float v = 0.0f;
        if ((unsigned)gy < 56u && (unsigned)gx < 56u) v = xb[(ic*56 + gy)*56 + gx];
        xs[i] = v;
    }

    int s = tid & 15, g = tid >> 4;        // 16 spatial, 16 oc-groups of 16
    int sy = s >> 2, sx = s & 3;
    int sbase = sy*18 + sx*2;
    int gofs = g * 16;

    unsigned long long acc[8];
    #pragma unroll
    for (int k = 0; k < 8; k++) acc[k] = pk2(b2[gofs+2*k], b2[gofs+2*k+1]);

    for (int c = 0; c < 576/C2_CHUNK; c++) {
        __syncthreads();
        const float* src = g_wt2 + c*C2_CHUNK*256;
        for (int i = tid; i < C2_CHUNK*256; i += 256) ws[i] = src[i];
        __syncthreads();
        #pragma unroll 4
        for (int rr = 0; rr < C2_CHUNK; rr++) {
            int r = c*C2_CHUNK + rr;
            float xv = xs[off[r] + sbase];
            unsigned long long xx = pk2(xv, xv);
            const ulonglong2* wp = (const ulonglong2*)(ws + rr*256 + gofs);
            ulonglong2 w0 = wp[0], w1 = wp[1], w2 = wp[2], w3 = wp[3];
            ffma2(acc[0], xx, w0.x); ffma2(acc[1], xx, w0.y);
            ffma2(acc[2], xx, w1.x); ffma2(acc[3], xx, w1.y);
            ffma2(acc[4], xx, w2.x); ffma2(acc[5], xx, w2.y);
            ffma2(acc[6], xx, w3.x); ffma2(acc[7], xx, w3.y);
        }
    }

    // relu then sum over the 16 spatial positions of this tile (deterministic)
    float vals[16];
    #pragma unroll
    for (int k = 0; k < 8; k++) {
        float2 f = upk2(acc[k]);
        vals[2*k]   = fmaxf(f.x, 0.0f);
        vals[2*k+1] = fmaxf(f.y, 0.0f);
    }
    #pragma unroll
    for (int k = 0; k < 16; k++) {
        float v = vals[k];
        v += __shfl_xor_sync(0xffffffffu, v, 8, 16);
        v += __shfl_xor_sync(0xffffffffu, v, 4, 16);
        v += __shfl_xor_sync(0xffffffffu, v, 2, 16);
        v += __shfl_xor_sync(0xffffffffu, v, 1, 16);
        vals[k] = v;
    }
    if ((tid & 15) == 0) {
        float* pp = g_part + ((size_t)(n*49 + tile))*256 + gofs;
        #pragma unroll
        for (int k = 0; k < 16; k++) pp[k] = vals[k];
    }
}

// ---------------- pooled mean -> h = mean @ Wh + bh ----------------
__global__ void __launch_bounds__(128) k_fc(const float* __restrict__ Wh, const float* __restrict__ bh) {
    __shared__ float p[256];
    int b = blockIdx.x, tid = threadIdx.x;
    for (int oc = tid; oc < 256; oc += 128) {
        float sv = 0.0f;
        const float* pp = g_part + (size_t)b*49*256 + oc;
        for (int t = 0; t < 49; t++) sv += pp[t*256];
        p[oc] = sv / 784.0f;
    }
    __syncthreads();
    #pragma unroll
    for (int q = 0; q < 4; q++) {
        int c = tid + q*128;
        float acc = bh[c];
        #pragma unroll 4
        for (int k = 0; k < 256; k++) acc = fmaf(p[k], Wh[k*512 + c], acc);
        g_h[b*512 + c] = acc;
    }
}

// ---------------- mu (normalized) and kappa ----------------
__global__ void __launch_bounds__(64) k_mukappa(const float* __restrict__ Wmu, const float* __restrict__ bmu,
                                                const float* __restrict__ Wk,  const float* __restrict__ bk,
                                                float* out_mu, float* out_k) {
    __shared__ float h[512];
    int b = blockIdx.x, tid = threadIdx.x;
    for (int i = tid; i < 512; i += 64) h[i] = g_h[b*512 + i];
    __syncthreads();
    if (tid < 32) {
        float acc = bmu[tid];
        #pragma unroll 4
        for (int k = 0; k < 512; k++) acc = fmaf(h[k], Wmu[k*32 + tid], acc);
        float ss = acc * acc;
        #pragma unroll
        for (int o = 16; o; o >>= 1) ss += __shfl_xor_sync(0xffffffffu, ss, o);
        float m = acc / sqrtf(fmaxf(ss, 1e-24f));
        g_mu[b*32 + tid] = m;
        if (out_mu) out_mu[b*32 + tid] = m;
    } else if (tid == 32) {
        float acc = bk[0];
        for (int k = 0; k < 512; k++) acc = fmaf(h[k], Wk[k], acc);
        float sp = fmaxf(acc, 0.0f) + log1pf(expf(-fabsf(acc)));   // logaddexp(x,0)
        float kap = sp + 1.0f;
        g_kappa[b] = kap;
        if (out_k) out_k[b] = kap;
    }
}

// ---------------- Threefry2x32 (exact JAX) ----------------
static __device__ __forceinline__ void tf2(unsigned k0, unsigned k1, unsigned &x0, unsigned &x1) {
    unsigned ks2 = k0 ^ k1 ^ 0x1BD11BDAu;
    x0 += k0; x1 += k1;
#define TFR(r) { x0 += x1; x1 = __funnelshift_l(x1, x1, r); x1 ^= x0; }
    TFR(13) TFR(15) TFR(26) TFR(6)   x0 += k1;  x1 += ks2 + 1u;
    TFR(17) TFR(29) TFR(16) TFR(24)  x0 += ks2; x1 += k0 + 2u;
    TFR(13) TFR(15) TFR(26) TFR(6)   x0 += k0;  x1 += k1 + 3u;
    TFR(17) TFR(29) TFR(16) TFR(24)  x0 += k1;  x1 += ks2 + 4u;
    TFR(13) TFR(15) TFR(26) TFR(6)   x0 += ks2; x1 += k0 + 5u;
#undef TFR
}
static __device__ __forceinline__ float u01(unsigned bits) {
    return __uint_as_float((bits >> 9) | 0x3f800000u) - 1.0f;
}
static __device__ float erfinv_f(float x) {   // XLA ErfInv32 polynomial
    float w = -log1pf(-x*x);
    float p;
    if (w < 5.0f) {
        w -= 2.5f;
        p = 2.81022636e-08f;
        p = fmaf(p, w, 3.43273939e-07f);
        p = fmaf(p, w, -3.5233877e-06f);
        p = fmaf(p, w, -4.39150654e-06f);
        p = fmaf(p, w, 0.00021858087f);
        p = fmaf(p, w, -0.00125372503f);
        p = fmaf(p, w, -0.00417768164f);
        p = fmaf(p, w, 0.246640727f);
        p = fmaf(p, w, 1.50140941f);
    } else {
        w = sqrtf(w) - 3.0f;
        p = -0.000200214257f;
        p = fmaf(p, w, 0.000100950558f);
        p = fmaf(p, w, 0.00134934322f);
        p = fmaf(p, w, -0.00367342844f);
        p = fmaf(p, w, 0.00573950773f);
        p = fmaf(p, w, -0.0076224613f);
        p = fmaf(p, w, 0.00943887047f);
        p = fmaf(p, w, 1.00167406f);
        p = fmaf(p, w, 2.83297682f);
    }
    return p * x;
}

// ---------------- vMF sampling (Wood), bit-exact JAX RNG ----------------
// JAX >= 0.4.30: jax_threefry_partitionable defaults to True.
//   split(key,2) (foldlike): key_i = full out-pair of block(key, x0=0, x1=i)
//   random_bits(key,32,shape): elem i = out0 ^ out1 of block(key, x0=0, x1=i)
//   fold_in(key,d): unchanged = out-pair of block(key, x0=0, x1=d)
__global__ void __launch_bounds__(32) k_sample() {
    int b = blockIdx.x;
    int lane = threadIdx.x;
    __shared__ float s_w[10];
    __shared__ int   s_a[10];

    // key(42) = (0,42); foldlike split -> k_w = block(0), k_v = block(1)
    unsigned a0,a1,c0,c1;
    { unsigned x0=0u, x1=0u; tf2(0u,42u,x0,x1); a0=x0; a1=x1; }   // k_w
    { unsigned x0=0u, x1=1u; tf2(0u,42u,x0,x1); c0=x0; c1=x1; }   // k_v

    float kap = g_kappa[b];
    if (lane < 10) {
        unsigned f0,f1,h0,h1;
        { unsigned x0=0u, x1=(unsigned)(2*lane);   tf2(a0,a1,x0,x1); f0=x0; f1=x1; }  // fold_in(k_w, 2i)
        { unsigned x0=0u, x1=(unsigned)(2*lane+1); tf2(a0,a1,x0,x1); h0=x0; h1=x1; }  // fold_in(k_w, 2i+1)
        unsigned bw, br;
        { unsigned x0=0u, x1=(unsigned)b; tf2(f0,f1,x0,x1); bw = x0 ^ x1; }   // uniform bits (partitionable)
        { unsigned x0=0u, x1=(unsigned)b; tf2(h0,h1,x0,x1); br = x0 ^ x1; }
        float wc = 2.0f*u01(bw) - 1.0f;
        float om = fmaxf(1.0f - wc*wc, 1e-40f);
        float lp = kap*wc + 14.5f*logf(om);          // 0.5*(alpha-2), alpha=31
        float lr = logf(u01(br) + 1e-40f);
        s_w[lane] = wc;
        s_a[lane] = (lr + kap <= lp) ? 1 : 0;
    }
    __syncthreads();
    float w = 0.0f;
    #pragma unroll
    for (int i = 9; i >= 0; i--) if (s_a[i]) w = s_w[i];   // first accepted i wins
    w = fminf(fmaxf(w, -1.0f), 1.0f);

    // tangent normals: normal(k_v, (64,31)) element e = b*31+lane
    float vj = 0.0f;
    if (lane < 31) {
        int e = b*31 + lane;
        unsigned bits;
        { unsigned x0=0u, x1=(unsigned)e; tf2(c0,c1,x0,x1); bits = x0 ^ x1; }
        float u = u01(bits);
        const float LO = -0.99999994f;               // nextafter(-1,0); (hi-lo) rounds to 2.0f
        float un = fmaxf(LO, fmaf(u, 2.0f, LO));
        vj = 1.4142135623730951f * erfinv_f(un);
    }
    float ss = vj*vj;
    #pragma unroll
    for (int o = 16; o; o >>= 1) ss += __shfl_xor_sync(0xffffffffu, ss, o);
    vj /= sqrtf(fmaxf(ss, 1e-24f));

    float st = sqrtf(fmaxf(1.0f - w*w, 1e-40f));
    float zt = (lane < 31) ? st*vj : w;

    float mub = g_mu[b*32 + lane];
    float uj = ((lane == 31) ? 1.0f : 0.0f) - mub;   // e_d - mu
    float us = uj*uj;
    #pragma unroll
    for (int o = 16; o; o >>= 1) us += __shfl_xor_sync(0xffffffffu, us, o);
    uj /= sqrtf(fmaxf(us, 1e-24f));
    float dp = zt*uj;
    #pragma unroll
    for (int o = 16; o; o >>= 1) dp += __shfl_xor_sync(0xffffffffu, dp, o);
    g_z[b*32 + lane] = zt - 2.0f*dp*uj;
}

// ---------------- MLP head (fused, one block per batch row) ----------------
__global__ void __launch_bounds__(512) k_mlp(const float* __restrict__ M1, const float* __restrict__ bM1,
                                             const float* __restrict__ M2, const float* __restrict__ bM2,
                                             const float* __restrict__ M3, const float* __restrict__ bM3,
                                             const float* __restrict__ M4, const float* __restrict__ bM4,
                                             float* __restrict__ out) {
    __shared__ float z[32];
    __shared__ float y1[512];
    __shared__ float y2[512];
    __shared__ float y3[32];
    int b = blockIdx.x, tid = threadIdx.x;
    if (tid < 32) z[tid] = g_z[b*32 + tid];
    __syncthreads();
    {
        float acc = bM1[tid];
        #pragma unroll
        for (int k = 0; k < 32; k++) acc = fmaf(z[k], M1[k*512 + tid], acc);
        y1[tid] = fmaxf(acc, 0.0f);
    }
    __syncthreads();
    {
        float acc = bM2[tid];
        #pragma unroll 4
        for (int k = 0; k < 512; k++) acc = fmaf(y1[k], M2[k*512 + tid], acc);
        y2[tid] = fmaxf(acc, 0.0f);
    }
    __syncthreads();
    if (tid < 32) {
        float acc = bM3[tid];
        #pragma unroll 4
        for (int k = 0; k < 512; k++) acc = fmaf(y2[k], M3[k*32 + tid], acc);
        y3[tid] = fmaxf(acc, 0.0f);
    }
    __syncthreads();
    if (tid < 7) {
        float acc = bM4[tid];
        #pragma unroll
        for (int k = 0; k < 32; k++) acc = fmaf(y3[k], M4[k*7 + tid], acc);
        out[b*7 + tid] = acc;
    }
}

// ---------------- launch ----------------
extern "C" void kernel_launch(void* const* d_in, const int* in_sizes, int n_in,
                              void* d_out, int out_size) {
    const float* x   = (const float*)d_in[0];
    const float* W1  = (const float*)d_in[1];
    const float* b1  = (const float*)d_in[2];
    const float* W2  = (const float*)d_in[3];
    const float* b2  = (const float*)d_in[4];
    const float* Wh  = (const float*)d_in[5];
    const float* bh  = (const float*)d_in[6];
    const float* Wmu = (const float*)d_in[7];
    const float* bmu = (const float*)d_in[8];
    const float* Wk  = (const float*)d_in[9];
    const float* bk  = (const float*)d_in[10];
    const float* M1  = (const float*)d_in[11];
    const float* bM1 = (const float*)d_in[12];
    const float* M2  = (const float*)d_in[13];
    const float* bM2 = (const float*)d_in[14];
    const float* M3  = (const float*)d_in[15];
    const float* bM3 = (const float*)d_in[16];
    const float* M4  = (const float*)d_in[17];
    const float* bM4 = (const float*)d_in[18];

    float* out  = (float*)d_out;
    float* omu  = (out_size >= 2560) ? out + 448  : nullptr;   // tuple order: out, mu, kappa
    float* okap = (out_size >= 2560) ? out + 2496 : nullptr;

    cudaFuncSetAttribute(k_conv1, cudaFuncAttributeMaxDynamicSharedMemorySize, CONV1_SMEM);
    cudaFuncSetAttribute(k_conv2, cudaFuncAttributeMaxDynamicSharedMemorySize, CONV2_SMEM);

    k_prep<<<128, 256>>>(W1, W2);
    k_conv1<<<dim3(49, 64), 256, CONV1_SMEM>>>(x, b1);
    k_conv2<<<dim3(49, 64), 256, CONV2_SMEM>>>(b2);
    k_fc<<<64, 128>>>(Wh, bh);
    k_mukappa<<<64, 64>>>(Wmu, bmu, Wk, bk, omu, okap);
    k_sample<<<64, 32>>>();
    k_mlp<<<64, 512>>>(M1, bM1, M2, bM2, M3, bM3, M4, bM4, out);
}

// round 3
// speedup vs baseline: 1.5572x; 1.5572x over previous
#include <cuda_runtime.h>

// ---------------- scratch (static device globals; no allocation) ----------------
__device__ float g_buf1[64*64*56*56];     // conv1 output (relu'd)  ~51MB
__device__ float g_wt1[294*64];           // conv1 weights transposed [r][oc]
__device__ float g_wt2[576*256];          // conv2 weights transposed [r][oc]
__device__ float g_part[64*14*256];       // conv2 pooled partials [n][slot][oc]
__device__ float g_h[64*512];
__device__ float g_mu[64*32];
__device__ float g_kappa[64];
__device__ float g_z[64*32];

// ---------------- packed f32x2 helpers ----------------
static __device__ __forceinline__ unsigned long long pk2(float a, float b){
    unsigned long long r; asm("mov.b64 %0,{%1,%2};" : "=l"(r) : "f"(a), "f"(b)); return r;
}
static __device__ __forceinline__ float2 upk2(unsigned long long v){
    float2 f; asm("mov.b64 {%0,%1},%2;" : "=f"(f.x), "=f"(f.y) : "l"(v)); return f;
}
static __device__ __forceinline__ void ffma2(unsigned long long &d, unsigned long long a, unsigned long long b){
    asm("fma.rn.f32x2 %0,%1,%2,%0;" : "+l"(d) : "l"(a), "l"(b));
}

// ---------------- weight transpose prep ----------------
__global__ void k_prep(const float* __restrict__ W1, const float* __restrict__ W2) {
    int stride = gridDim.x * blockDim.x;
    int i0 = blockIdx.x * blockDim.x + threadIdx.x;
    for (int i = i0; i < 294*64; i += stride) {
        int oc = i / 294, r = i - oc*294;
        g_wt1[r*64 + oc] = W1[i];
    }
    for (int i = i0; i < 576*256; i += stride) {
        int oc = i / 576, r = i - oc*576;
        g_wt2[r*256 + oc] = W2[i];
    }
}

// ---------------- conv1: [64,6,224,224] -> relu -> [64,64,56,56] ----------------
// grid (49 tiles, 64 n), 128 threads. Thread = 8 oc x 4 spatial.
// x smem: 6 planes x 35 rows x 36 cols (padded), 16B-aligned float4 loads.
#define C1_XS (6*35*36)          // 7560
#define CONV1_SMEM ((C1_XS + 294*64) * 4)
__global__ void __launch_bounds__(128) k_conv1(const float* __restrict__ x, const float* __restrict__ b1) {
    extern __shared__ float sm[];
    float* xs = sm;              // 7560
    float* ws = sm + C1_XS;      // 294*64
    int tile = blockIdx.x, n = blockIdx.y;
    int ty = tile / 7, tx = tile - ty*7;
    int tid = threadIdx.x;
    int ocg = tid >> 4;          // 0..7  (8 oc each)
    int sg  = tid & 15;          // 0..15 (4 spatial each)
    int sy  = sg >> 1, sxg = sg & 1;

    for (int i = tid; i < 294*64; i += 128) ws[i] = g_wt1[i];

    int y0 = ty*32 - 3, x0 = tx*32 - 3;
    const float* xb = x + (size_t)n*6*224*224;
    for (int i = tid; i < C1_XS; i += 128) {
        int ic = i / 1260; int rem = i - ic*1260;
        int ry = rem / 36, cx = rem - ry*36;
        int gy = y0 + ry, gx = x0 + cx;
        float v = 0.0f;
        if (cx < 35 && (unsigned)gy < 224u && (unsigned)gx < 224u)
            v = xb[(ic*224 + gy)*224 + gx];
        xs[i] = v;
    }
    __syncthreads();

    int oc0 = ocg*8;
    unsigned long long acc[4][4];
    #pragma unroll
    for (int j = 0; j < 4; j++)
        #pragma unroll
        for (int q = 0; q < 4; q++)
            acc[j][q] = pk2(b1[oc0+2*q], b1[oc0+2*q+1]);

    const float* wbase = ws + oc0;
    #pragma unroll 1
    for (int ic = 0; ic < 6; ic++) {
        const float* xpl = xs + ic*1260 + sxg*16;
        #pragma unroll 1
        for (int kh = 0; kh < 7; kh++) {
            const float* xr = xpl + (sy*4 + kh)*36;
            float xc[20];
            #pragma unroll
            for (int q = 0; q < 5; q++) {
                float4 v = *(const float4*)(xr + q*4);
                xc[4*q] = v.x; xc[4*q+1] = v.y; xc[4*q+2] = v.z; xc[4*q+3] = v.w;
            }
            const float* wr = wbase + (ic*49 + kh*7)*64;
            #pragma unroll
            for (int kw = 0; kw < 7; kw++) {
                ulonglong2 wA = *(const ulonglong2*)(wr);
                ulonglong2 wB = *(const ulonglong2*)(wr + 4);
                #pragma unroll
                for (int j = 0; j < 4; j++) {
                    float xv = xc[j*4 + kw];
                    unsigned long long xx = pk2(xv, xv);
                    ffma2(acc[j][0], xx, wA.x); ffma2(acc[j][1], xx, wA.y);
                    ffma2(acc[j][2], xx, wB.x); ffma2(acc[j][3], xx, wB.y);
                }
                wr += 64;
            }
        }
    }

    int oy = ty*8 + sy;
    #pragma unroll
    for (int j = 0; j < 4; j++) {
        int ox = tx*8 + sxg*4 + j;
        float* ob = g_buf1 + ((size_t)(n*64 + oc0)*56 + oy)*56 + ox;
        #pragma unroll
        for (int q = 0; q < 4; q++) {
            float2 f = upk2(acc[j][q]);
            ob[(size_t)(2*q)*3136]   = fmaxf(f.x, 0.0f);
            ob[(size_t)(2*q+1)*3136] = fmaxf(f.y, 0.0f);
        }
    }
}

// ---------------- conv2 + relu + masked pool partials ----------------
// grid (7 bands, 64 n, 2 oc-half), 512 threads. Thread = 16 oc x 2 spatial.
// Streams x + weights in 8 ic-chunks of 8.
#define C2_XS (8*612)            // 8 planes x 9 rows x 68 cols = 4896
#define C2_WS (72*128)           // 9216
#define CONV2_SMEM ((C2_XS + C2_WS) * 4)
__global__ void __launch_bounds__(512) k_conv2(const float* __restrict__ b2) {
    extern __shared__ float sm[];
    float* xs = sm;              // 4896
    float* ws = sm + C2_XS;      // 9216
    int band = blockIdx.x, n = blockIdx.y, och = blockIdx.z;
    int tid = threadIdx.x;
    int ocg = tid >> 6;          // 0..7 (16 oc each)
    int sg  = tid & 63;          // 0..63 (2 spatial each)
    int ry  = sg >> 4, cxg = sg & 15;
    int oc0 = och*128 + ocg*16;

    unsigned long long acc[2][8];
    #pragma unroll
    for (int j = 0; j < 2; j++)
        #pragma unroll
        for (int q = 0; q < 8; q++)
            acc[j][q] = pk2(b2[oc0+2*q], b2[oc0+2*q+1]);

    for (int ch = 0; ch < 8; ch++) {
        __syncthreads();
        // weights: 72 rows x 128 oc slice
        for (int i = tid; i < C2_WS; i += 512) {
            int rr = i >> 7, c = i & 127;
            ws[i] = g_wt2[(ch*72 + rr)*256 + och*128 + c];
        }
        // x: 8 planes x 9 rows x 68 cols (zero-padded)
        const float* xbase = g_buf1 + ((size_t)n*64 + ch*8)*3136;
        for (int i = tid; i < C2_XS; i += 512) {
            int icc = i / 612; int rem = i - icc*612;
            int rr = rem / 68, cc = rem - rr*68;
            int iy = band*8 - 1 + rr;
            int ix = cc - 1;
            float v = 0.0f;
            if ((unsigned)iy < 56u && (unsigned)ix < 56u)
                v = xbase[icc*3136 + iy*56 + ix];
            xs[i] = v;
        }
        __syncthreads();

        #pragma unroll 1
        for (int icc = 0; icc < 8; icc++) {
            #pragma unroll
            for (int kh = 0; kh < 3; kh++) {
                const float* xr = xs + icc*612 + (ry*2 + kh)*68 + cxg*4;
                float4 xa = *(const float4*)xr;
                float4 xb4 = *(const float4*)(xr + 4);
                float xc[8] = {xa.x, xa.y, xa.z, xa.w, xb4.x, xb4.y, xb4.z, xb4.w};
                const float* wr = ws + (icc*9 + kh*3)*128 + ocg*16;
                #pragma unroll
                for (int kw = 0; kw < 3; kw++) {
                    ulonglong2 wA = *(const ulonglong2*)(wr);
                    ulonglong2 wB = *(const ulonglong2*)(wr + 4);
                    ulonglong2 wC = *(const ulonglong2*)(wr + 8);
                    ulonglong2 wD = *(const ulonglong2*)(wr + 12);
                    #pragma unroll
                    for (int j = 0; j < 2; j++) {
                        float xv = xc[j*2 + kw];
                        unsigned long long xx = pk2(xv, xv);
                        ffma2(acc[j][0], xx, wA.x); ffma2(acc[j][1], xx, wA.y);
                        ffma2(acc[j][2], xx, wB.x); ffma2(acc[j][3], xx, wB.y);
                        ffma2(acc[j][4], xx, wC.x); ffma2(acc[j][5], xx, wC.y);
                        ffma2(acc[j][6], xx, wD.x); ffma2(acc[j][7], xx, wD.y);
                    }
                    wr += 128;
                }
            }
        }
    }

    // relu + mask (ox<28) + per-thread sum over its 2 positions, then warp-sum
    float sums[16];
    #pragma unroll
    for (int q = 0; q < 8; q++) {
        float2 f0 = upk2(acc[0][q]);
        float2 f1 = upk2(acc[1][q]);
        int ox0 = cxg*2, ox1 = cxg*2 + 1;
        float m0 = (ox0 < 28) ? 1.0f : 0.0f;
        float m1 = (ox1 < 28) ? 1.0f : 0.0f;
        sums[2*q]   = fmaxf(f0.x, 0.0f)*m0 + fmaxf(f1.x, 0.0f)*m1;
        sums[2*q+1] = fmaxf(f0.y, 0.0f)*m0 + fmaxf(f1.y, 0.0f)*m1;
    }
    #pragma unroll
    for (int m = 0; m < 16; m++) {
        float v = sums[m];
        #pragma unroll
        for (int o = 16; o; o >>= 1) v += __shfl_xor_sync(0xffffffffu, v, o);
        sums[m] = v;
    }
    if ((tid & 31) == 0) {
        int slot = band*2 + (sg >> 5);
        float* pp = g_part + ((size_t)n*14 + slot)*256 + oc0;
        #pragma unroll
        for (int m = 0; m < 16; m++) pp[m] = sums[m];
    }
}

// ---------------- pooled mean -> h = mean @ Wh + bh ----------------
// grid (64 n, 4 quarter), 128 threads
__global__ void __launch_bounds__(128) k_fc(const float* __restrict__ Wh, const float* __restrict__ bh) {
    __shared__ float p[256];
    int b = blockIdx.x, cq = blockIdx.y, tid = threadIdx.x;
    for (int oc = tid; oc < 256; oc += 128) {
        float sv = 0.0f;
        const float* pp = g_part + (size_t)b*14*256 + oc;
        #pragma unroll
        for (int t = 0; t < 14; t++) sv += pp[t*256];
        p[oc] = sv * (1.0f/784.0f);
    }
    __syncthreads();
    int c = cq*128 + tid;
    float a0 = 0.f, a1 = 0.f, a2 = 0.f, a3 = 0.f;
    #pragma unroll 2
    for (int k = 0; k < 256; k += 4) {
        a0 = fmaf(p[k],   Wh[(k)*512 + c],   a0);
        a1 = fmaf(p[k+1], Wh[(k+1)*512 + c], a1);
        a2 = fmaf(p[k+2], Wh[(k+2)*512 + c], a2);
        a3 = fmaf(p[k+3], Wh[(k+3)*512 + c], a3);
    }
    g_h[b*512 + c] = bh[c] + ((a0 + a1) + (a2 + a3));
}

// ---------------- mu (normalized) and kappa ----------------
__global__ void __launch_bounds__(64) k_mukappa(const float* __restrict__ Wmu, const float* __restrict__ bmu,
                                                const float* __restrict__ Wk,  const float* __restrict__ bk,
                                                float* out_mu, float* out_k) {
    __shared__ float h[512];
    int b = blockIdx.x, tid = threadIdx.x;
    for (int i = tid; i < 512; i += 64) h[i] = g_h[b*512 + i];
    __syncthreads();
    if (tid < 32) {
        int o = tid;
        float a0 = 0.f, a1 = 0.f, a2 = 0.f, a3 = 0.f;
        #pragma unroll 2
        for (int k = 0; k < 512; k += 4) {
            a0 = fmaf(h[k],   Wmu[(k)*32 + o],   a0);
            a1 = fmaf(h[k+1], Wmu[(k+1)*32 + o], a1);
            a2 = fmaf(h[k+2], Wmu[(k+2)*32 + o], a2);
            a3 = fmaf(h[k+3], Wmu[(k+3)*32 + o], a3);
        }
        float acc = bmu[o] + ((a0 + a1) + (a2 + a3));
        float ss = acc * acc;
        #pragma unroll
        for (int of = 16; of; of >>= 1) ss += __shfl_xor_sync(0xffffffffu, ss, of);
        float m = acc / sqrtf(fmaxf(ss, 1e-24f));
        g_mu[b*32 + o] = m;
        if (out_mu) out_mu[b*32 + o] = m;
    } else {
        int l = tid - 32;
        float a = 0.f;
        #pragma unroll
        for (int t = 0; t < 16; t++) {
            int k = l*16 + t;
            a = fmaf(h[k], Wk[k], a);
        }
        #pragma unroll
        for (int of = 16; of; of >>= 1) a += __shfl_xor_sync(0xffffffffu, a, of);
        if (l == 0) {
            float acc = a + bk[0];
            float sp = fmaxf(acc, 0.0f) + log1pf(expf(-fabsf(acc)));
            float kap = sp + 1.0f;
            g_kappa[b] = kap;
            if (out_k) out_k[b] = kap;
        }
    }
}

// ---------------- Threefry2x32 (exact JAX, partitionable) ----------------
static __device__ __forceinline__ void tf2(unsigned k0, unsigned k1, unsigned &x0, unsigned &x1) {
    unsigned ks2 = k0 ^ k1 ^ 0x1BD11BDAu;
    x0 += k0; x1 += k1;
#define TFR(r) { x0 += x1; x1 = __funnelshift_l(x1, x1, r); x1 ^= x0; }
    TFR(13) TFR(15) TFR(26) TFR(6)   x0 += k1;  x1 += ks2 + 1u;
    TFR(17) TFR(29) TFR(16) TFR(24)  x0 += ks2; x1 += k0 + 2u;
    TFR(13) TFR(15) TFR(26) TFR(6)   x0 += k0;  x1 += k1 + 3u;
    TFR(17) TFR(29) TFR(16) TFR(24)  x0 += k1;  x1 += ks2 + 4u;
    TFR(13) TFR(15) TFR(26) TFR(6)   x0 += ks2; x1 += k0 + 5u;
#undef TFR
}
static __device__ __forceinline__ float u01(unsigned bits) {
    return __uint_as_float((bits >> 9) | 0x3f800000u) - 1.0f;
}
static __device__ float erfinv_f(float x) {   // XLA ErfInv32 polynomial
    float w = -log1pf(-x*x);
    float p;
    if (w < 5.0f) {
        w -= 2.5f;
        p = 2.81022636e-08f;
        p = fmaf(p, w, 3.43273939e-07f);
        p = fmaf(p, w, -3.5233877e-06f);
        p = fmaf(p, w, -4.39150654e-06f);
        p = fmaf(p, w, 0.00021858087f);
        p = fmaf(p, w, -0.00125372503f);
        p = fmaf(p, w, -0.00417768164f);
        p = fmaf(p, w, 0.246640727f);
        p = fmaf(p, w, 1.50140941f);
    } else {
        w = sqrtf(w) - 3.0f;
        p = -0.000200214257f;
        p = fmaf(p, w, 0.000100950558f);
        p = fmaf(p, w, 0.00134934322f);
        p = fmaf(p, w, -0.00367342844f);
        p = fmaf(p, w, 0.00573950773f);
        p = fmaf(p, w, -0.0076224613f);
        p = fmaf(p, w, 0.00943887047f);
        p = fmaf(p, w, 1.00167406f);
        p = fmaf(p, w, 2.83297682f);
    }
    return p * x;
}

// ---------------- vMF sampling (Wood), bit-exact JAX RNG ----------------
__global__ void __launch_bounds__(32) k_sample() {
    int b = blockIdx.x;
    int lane = threadIdx.x;
    __shared__ float s_w[10];
    __shared__ int   s_a[10];

    unsigned a0,a1,c0,c1;
    { unsigned x0=0u, x1=0u; tf2(0u,42u,x0,x1); a0=x0; a1=x1; }   // k_w
    { unsigned x0=0u, x1=1u; tf2(0u,42u,x0,x1); c0=x0; c1=x1; }   // k_v

    float kap = g_kappa[b];
    if (lane < 10) {
        unsigned f0,f1,h0,h1;
        { unsigned x0=0u, x1=(unsigned)(2*lane);   tf2(a0,a1,x0,x1); f0=x0; f1=x1; }
        { unsigned x0=0u, x1=(unsigned)(2*lane+1); tf2(a0,a1,x0,x1); h0=x0; h1=x1; }
        unsigned bw, br;
        { unsigned x0=0u, x1=(unsigned)b; tf2(f0,f1,x0,x1); bw = x0 ^ x1; }
        { unsigned x0=0u, x1=(unsigned)b; tf2(h0,h1,x0,x1); br = x0 ^ x1; }
        float wc = 2.0f*u01(bw) - 1.0f;
        float om = fmaxf(1.0f - wc*wc, 1e-40f);
        float lp = kap*wc + 14.5f*logf(om);
        float lr = logf(u01(br) + 1e-40f);
        s_w[lane] = wc;
        s_a[lane] = (lr + kap <= lp) ? 1 : 0;
    }
    __syncthreads();
    float w = 0.0f;
    #pragma unroll
    for (int i = 9; i >= 0; i--) if (s_a[i]) w = s_w[i];
    w = fminf(fmaxf(w, -1.0f), 1.0f);

    float vj = 0.0f;
    if (lane < 31) {
        int e = b*31 + lane;
        unsigned bits;
        { unsigned x0=0u, x1=(unsigned)e; tf2(c0,c1,x0,x1); bits = x0 ^ x1; }
        float u = u01(bits);
        const float LO = -0.99999994f;
        float un = fmaxf(LO, fmaf(u, 2.0f, LO));
        vj = 1.4142135623730951f * erfinv_f(un);
    }
    float ss = vj*vj;
    #pragma unroll
    for (int o = 16; o; o >>= 1) ss += __shfl_xor_sync(0xffffffffu, ss, o);
    vj /= sqrtf(fmaxf(ss, 1e-24f));

    float st = sqrtf(fmaxf(1.0f - w*w, 1e-40f));
    float zt = (lane < 31) ? st*vj : w;

    float mub = g_mu[b*32 + lane];
    float uj = ((lane == 31) ? 1.0f : 0.0f) - mub;
    float us = uj*uj;
    #pragma unroll
    for (int o = 16; o; o >>= 1) us += __shfl_xor_sync(0xffffffffu, us, o);
    uj /= sqrtf(fmaxf(us, 1e-24f));
    float dp = zt*uj;
    #pragma unroll
    for (int o = 16; o; o >>= 1) dp += __shfl_xor_sync(0xffffffffu, dp, o);
    g_z[b*32 + lane] = zt - 2.0f*dp*uj;
}

// ---------------- MLP head (fused, one block per batch row) ----------------
__global__ void __launch_bounds__(512) k_mlp(const float* __restrict__ M1, const float* __restrict__ bM1,
                                             const float* __restrict__ M2, const float* __restrict__ bM2,
                                             const float* __restrict__ M3, const float* __restrict__ bM3,
                                             const float* __restrict__ M4, const float* __restrict__ bM4,
                                             float* __restrict__ out) {
    __shared__ float z[32];
    __shared__ float y1[512];
    __shared__ float y2[512];
    __shared__ float red[32][8];
    __shared__ float y3[32];
    int b = blockIdx.x, tid = threadIdx.x;
    if (tid < 32) z[tid] = g_z[b*32 + tid];
    __syncthreads();
    {
        float acc = bM1[tid];
        #pragma unroll
        for (int k = 0; k < 32; k++) acc = fmaf(z[k], M1[k*512 + tid], acc);
        y1[tid] = fmaxf(acc, 0.0f);
    }
    __syncthreads();
    {
        float a0 = 0.f, a1 = 0.f, a2 = 0.f, a3 = 0.f;
        #pragma unroll 2
        for (int k = 0; k < 512; k += 4) {
            a0 = fmaf(y1[k],   M2[(k)*512 + tid],   a0);
            a1 = fmaf(y1[k+1], M2[(k+1)*512 + tid], a1);
            a2 = fmaf(y1[k+2], M2[(k+2)*512 + tid], a2);
            a3 = fmaf(y1[k+3], M2[(k+3)*512 + tid], a3);
        }
        y2[tid] = fmaxf(bM2[tid] + ((a0 + a1) + (a2 + a3)), 0.0f);
    }
    __syncthreads();
    if (tid < 256) {
        int o = tid >> 3, p = tid & 7;   // 32 outputs x 8 partials of 64
        float a = 0.f;
        #pragma unroll 4
        for (int t = 0; t < 64; t++) {
            int k = p*64 + t;
            a = fmaf(y2[k], M3[k*32 + o], a);
        }
        red[o][p] = a;
    }
    __syncthreads();
    if (tid < 32) {
        float a = bM3[tid];
        #pragma unroll
        for (int p = 0; p < 8; p++) a += red[tid][p];
        y3[tid] = fmaxf(a, 0.0f);
    }
    __syncthreads();
    if (tid < 7) {
        float acc = bM4[tid];
        #pragma unroll
        for (int k = 0; k < 32; k++) acc = fmaf(y3[k], M4[k*7 + tid], acc);
        out[b*7 + tid] = acc;
    }
}

// ---------------- launch ----------------
extern "C" void kernel_launch(void* const* d_in, const int* in_sizes, int n_in,
                              void* d_out, int out_size) {
    const float* x   = (const float*)d_in[0];
    const float* W1  = (const float*)d_in[1];
    const float* b1  = (const float*)d_in[2];
    const float* W2  = (const float*)d_in[3];
    const float* b2  = (const float*)d_in[4];
    const float* Wh  = (const float*)d_in[5];
    const float* bh  = (const float*)d_in[6];
    const float* Wmu = (const float*)d_in[7];
    const float* bmu = (const float*)d_in[8];
    const float* Wk  = (const float*)d_in[9];
    const float* bk  = (const float*)d_in[10];
    const float* M1  = (const float*)d_in[11];
    const float* bM1 = (const float*)d_in[12];
    const float* M2  = (const float*)d_in[13];
    const float* bM2 = (const float*)d_in[14];
    const float* M3  = (const float*)d_in[15];
    const float* bM3 = (const float*)d_in[16];
    const float* M4  = (const float*)d_in[17];
    const float* bM4 = (const float*)d_in[18];

    float* out  = (float*)d_out;
    float* omu  = (out_size >= 2560) ? out + 448  : nullptr;   // tuple order: out, mu, kappa
    float* okap = (out_size >= 2560) ? out + 2496 : nullptr;

    cudaFuncSetAttribute(k_conv1, cudaFuncAttributeMaxDynamicSharedMemorySize, CONV1_SMEM);
    cudaFuncSetAttribute(k_conv2, cudaFuncAttributeMaxDynamicSharedMemorySize, CONV2_SMEM);

    k_prep<<<128, 256>>>(W1, W2);
    k_conv1<<<dim3(49, 64), 128, CONV1_SMEM>>>(x, b1);
    k_conv2<<<dim3(7, 64, 2), 512, CONV2_SMEM>>>(b2);
    k_fc<<<dim3(64, 4), 128>>>(Wh, bh);
    k_mukappa<<<64, 64>>>(Wmu, bmu, Wk, bk, omu, okap);
    k_sample<<<64, 32>>>();
    k_mlp<<<64, 512>>>(M1, bM1, M2, bM2, M3, bM3, M4, bM4, out);
}

// round 10
// speedup vs baseline: 1.7957x; 1.1531x over previous
#include <cuda_runtime.h>
#include <cuda_bf16.h>

// ---------------- scratch (static device globals; no allocation) ----------------
__device__ __nv_bfloat16 g_c1h[64*56*56*64];   // conv1 out hi, channels-last [n][y][x][oc]
__device__ __nv_bfloat16 g_c1l[64*56*56*64];   // conv1 out lo
__device__ __nv_bfloat16 g_wb1h[64*320];       // conv1 W [oc][k(320 pad)] hi
__device__ __nv_bfloat16 g_wb1l[64*320];
__device__ __nv_bfloat16 g_wb2h[9*256*64];     // conv2 W [shift][oc][ic] hi
__device__ __nv_bfloat16 g_wb2l[9*256*64];
__device__ float g_part[64*7*256];             // pooled partials [n][rowgroup][oc]
__device__ float g_h[64*512];
__device__ float g_mu[64*32];
__device__ float g_kappa[64];
__device__ float g_z[64*32];

// ---------------- helpers ----------------
static __device__ __forceinline__ void split_bf16(float v, __nv_bfloat16 &hi, __nv_bfloat16 &lo){
    hi = __float2bfloat16(v);
    lo = __float2bfloat16(v - __bfloat162float(hi));
}
static __device__ __forceinline__ unsigned pack2(__nv_bfloat16 a, __nv_bfloat16 b){
    return (unsigned)__bfloat16_as_ushort(a) | ((unsigned)__bfloat16_as_ushort(b) << 16);
}
// swizzled byte offset for u32 element (row, kp) in a [row][32 kp-u32] tile (128B rows)
static __device__ __forceinline__ unsigned swa(int row, int kp){
    return (unsigned)(row*128 + ((((kp>>2) ^ (row & 7)) << 4) | ((kp & 3) << 2)));
}
static __device__ __forceinline__ void mma_bf16(float* d, const unsigned* a, const unsigned* b){
    asm volatile("mma.sync.aligned.m16n8k16.row.col.f32.bf16.bf16.f32 "
        "{%0,%1,%2,%3}, {%4,%5,%6,%7}, {%8,%9}, {%0,%1,%2,%3};"
        : "+f"(d[0]), "+f"(d[1]), "+f"(d[2]), "+f"(d[3])
        : "r"(a[0]), "r"(a[1]), "r"(a[2]), "r"(a[3]), "r"(b[0]), "r"(b[1]));
}

// ---------------- prep: weight transforms to bf16 hi/lo ----------------
__global__ void k_prep(const float* __restrict__ W1, const float* __restrict__ W2) {
    int stride = gridDim.x * blockDim.x;
    int i0 = blockIdx.x * blockDim.x + threadIdx.x;
    for (int i = i0; i < 64*320; i += stride) {
        int oc = i / 320, k = i - oc*320;
        float v = (k < 294) ? W1[oc*294 + k] : 0.0f;
        __nv_bfloat16 hi, lo; split_bf16(v, hi, lo);
        g_wb1h[i] = hi; g_wb1l[i] = lo;
    }
    for (int i = i0; i < 9*256*64; i += stride) {
        int ic = i & 63, oc = (i >> 6) & 255, s = i >> 14;
        int kh = s / 3, kw = s - kh*3;
        float v = W2[oc*576 + ic*9 + kh*3 + kw];
        __nv_bfloat16 hi, lo; split_bf16(v, hi, lo);
        g_wb2h[i] = hi; g_wb2l[i] = lo;
    }
}

// ---------------- conv1: HMMA implicit GEMM ----------------
// grid (28 row-pairs, 64 n), 256 thr (8 warps: 4M x 2N). M=128(112 used), K=320(5x64), N=64.
#define C1_B1S  0        // 64 f32
#define C1_LUT  256      // 320 u32
#define C1_AH   2048     // 128x32 u32 = 16KB
#define C1_AL   18432
#define C1_BH   34816    // 64x32 u32 = 8KB
#define C1_BL   43008
#define C1_SMEM 51200
__global__ void __launch_bounds__(256)
k_conv1(const float* __restrict__ x, const float* __restrict__ b1) {
    extern __shared__ char smc[];
    float* b1s = (float*)(smc + C1_B1S);
    unsigned* lut = (unsigned*)(smc + C1_LUT);
    int pr = blockIdx.x, n = blockIdx.y;
    int tid = threadIdx.x, wid = tid >> 5, lane = tid & 31;
    int g = lane >> 2, t = lane & 3;
    int wm = wid >> 1, wn = wid & 1;
    int rowblk = wm*32, colblk = wn*32;

    if (tid < 64) b1s[tid] = b1[tid];
    for (int k = tid; k < 320; k += 256) {
        if (k < 294) {
            int ic = k / 49, r = k - ic*49, kh = r / 7, kw = r - kh*7;
            lut[k] = (unsigned)(ic*50176 + kh*224 + kw) | ((unsigned)kh << 20) | ((unsigned)kw << 23);
        } else lut[k] = 0xFFFFFFFFu;
    }

    float acc[2][4][4];
    #pragma unroll
    for (int mi = 0; mi < 2; mi++)
        #pragma unroll
        for (int nj = 0; nj < 4; nj++)
            #pragma unroll
            for (int q = 0; q < 4; q++) acc[mi][nj][q] = 0.0f;

    const float* xn = x + (size_t)n * 301056;

    for (int c = 0; c < 5; c++) {
        __syncthreads();
        // stage A: 128 rows x 32 kp (im2col gather, hi/lo split, pack pairs)
        for (int e = tid; e < 4096; e += 256) {
            int row = e >> 5, kp = e & 31;
            int k0 = c*64 + kp*2;
            float v0 = 0.0f, v1 = 0.0f;
            if (row < 112) {
                int hi56 = (row >= 56);
                int oy = pr*2 + hi56;
                int ox = row - (hi56 ? 56 : 0);
                int base = (4*oy - 3)*224 + (4*ox - 3);
                unsigned L0 = lut[k0];
                if (L0 != 0xFFFFFFFFu) {
                    int kh = (L0 >> 20) & 7, kw = (L0 >> 23) & 7;
                    if ((oy > 0 || kh >= 3) && (ox > 0 || kw >= 3)) v0 = xn[(L0 & 0xFFFFFu) + base];
                }
                unsigned L1 = lut[k0 + 1];
                if (L1 != 0xFFFFFFFFu) {
                    int kh = (L1 >> 20) & 7, kw = (L1 >> 23) & 7;
                    if ((oy > 0 || kh >= 3) && (ox > 0 || kw >= 3)) v1 = xn[(L1 & 0xFFFFFu) + base];
                }
            }
            __nv_bfloat16 h0, l0, h1, l1;
            split_bf16(v0, h0, l0); split_bf16(v1, h1, l1);
            unsigned sw = swa(row, kp);
            *(unsigned*)(smc + C1_AH + sw) = pack2(h0, h1);
            *(unsigned*)(smc + C1_AL + sw) = pack2(l0, l1);
        }
        // stage B: 64 oc x 32 kp
        for (int e = tid; e < 2048; e += 256) {
            int oc = e >> 5, kp = e & 31;
            int so = oc*320 + c*64 + kp*2;
            unsigned vh = *(const unsigned*)&g_wb1h[so];
            unsigned vl = *(const unsigned*)&g_wb1l[so];
            unsigned sw = swa(oc, kp);
            *(unsigned*)(smc + C1_BH + sw) = vh;
            *(unsigned*)(smc + C1_BL + sw) = vl;
        }
        __syncthreads();

        #pragma unroll
        for (int ks = 0; ks < 4; ks++) {
            int kpb = ks*8;
            unsigned ah[2][4], al[2][4];
            #pragma unroll
            for (int mi = 0; mi < 2; mi++) {
                int row = rowblk + mi*16 + g;
                ah[mi][0] = *(const unsigned*)(smc + C1_AH + swa(row,     kpb + t));
                ah[mi][1] = *(const unsigned*)(smc + C1_AH + swa(row + 8, kpb + t));
                ah[mi][2] = *(const unsigned*)(smc + C1_AH + swa(row,     kpb + t + 4));
                ah[mi][3] = *(const unsigned*)(smc + C1_AH + swa(row + 8, kpb + t + 4));
                al[mi][0] = *(const unsigned*)(smc + C1_AL + swa(row,     kpb + t));
                al[mi][1] = *(const unsigned*)(smc + C1_AL + swa(row + 8, kpb + t));
                al[mi][2] = *(const unsigned*)(smc + C1_AL + swa(row,     kpb + t + 4));
                al[mi][3] = *(const unsigned*)(smc + C1_AL + swa(row + 8, kpb + t + 4));
            }
            #pragma unroll
            for (int nj = 0; nj < 4; nj++) {
                int oc = colblk + nj*8 + g;
                unsigned bh[2], bl[2];
                bh[0] = *(const unsigned*)(smc + C1_BH + swa(oc, kpb + t));
                bh[1] = *(const unsigned*)(smc + C1_BH + swa(oc, kpb + t + 4));
                bl[0] = *(const unsigned*)(smc + C1_BL + swa(oc, kpb + t));
                bl[1] = *(const unsigned*)(smc + C1_BL + swa(oc, kpb + t + 4));
                #pragma unroll
                for (int mi = 0; mi < 2; mi++) {
                    mma_bf16(acc[mi][nj], ah[mi], bh);
                    mma_bf16(acc[mi][nj], ah[mi], bl);
                    mma_bf16(acc[mi][nj], al[mi], bh);
                }
            }
        }
    }

    // epilogue: bias + relu + split -> channels-last bf16 hi/lo
    #pragma unroll
    for (int mi = 0; mi < 2; mi++) {
        #pragma unroll
        for (int nj = 0; nj < 4; nj++) {
            int cc = colblk + nj*8 + 2*t;
            float bb0 = b1s[cc], bb1 = b1s[cc + 1];
            #pragma unroll
            for (int rh = 0; rh < 2; rh++) {
                int s = rowblk + mi*16 + g + rh*8;
                if (s < 112) {
                    float v0 = fmaxf(acc[mi][nj][rh*2]     + bb0, 0.0f);
                    float v1 = fmaxf(acc[mi][nj][rh*2 + 1] + bb1, 0.0f);
                    int hi56 = (s >= 56);
                    int oy = pr*2 + hi56, ox = s - (hi56 ? 56 : 0);
                    size_t ob = ((size_t)(n*56 + oy)*56 + ox)*64 + cc;
                    __nv_bfloat16 h0, l0, h1, l1;
                    split_bf16(v0, h0, l0); split_bf16(v1, h1, l1);
                    *(unsigned*)(g_c1h + ob) = pack2(h0, h1);
                    *(unsigned*)(g_c1l + ob) = pack2(l0, l1);
                }
            }
        }
    }
}

// ---------------- conv2: HMMA, 9 shifted GEMMs + fused pool ----------------
// grid (7 rowgroups, 64 n), 256 thr (8 warps: 4M x 2N). M=128(112 used: 4 rows x 28),
// K=64 per shift x 9 shifts, N=256 in two sequential halves of 128.
#define C2_B2S  0        // 256 f32
#define C2_RED  1024     // 4x128 f32
#define C2_AH   4096     // 128x32 u32 = 16KB
#define C2_AL   20480
#define C2_BH   36864    // 128x32 u32 = 16KB
#define C2_BL   53248
#define C2_SMEM 69632
__global__ void __launch_bounds__(256)
k_conv2(const float* __restrict__ b2) {
    extern __shared__ char smc[];
    float* b2s = (float*)(smc + C2_B2S);
    float* red = (float*)(smc + C2_RED);
    int rg = blockIdx.x, n = blockIdx.y;
    int tid = threadIdx.x, wid = tid >> 5, lane = tid & 31;
    int g = lane >> 2, t = lane & 3;
    int wm = wid >> 1, wn = wid & 1;
    int rowblk = wm*32, colblk = wn*64;

    b2s[tid] = b2[tid];

    for (int half = 0; half < 2; half++) {
        float acc[2][8][4];
        #pragma unroll
        for (int mi = 0; mi < 2; mi++)
            #pragma unroll
            for (int nj = 0; nj < 8; nj++)
                #pragma unroll
                for (int q = 0; q < 4; q++) acc[mi][nj][q] = 0.0f;

        for (int s = 0; s < 9; s++) {
            int kh = s / 3, kw = s - kh*3;
            __syncthreads();
            // stage A: 128 rows x 32 kp (shifted window of conv1 channels-last out)
            for (int e = tid; e < 4096; e += 256) {
                int srow = e >> 5, kp = e & 31;
                unsigned vh = 0u, vl = 0u;
                if (srow < 112) {
                    int oy = rg*4 + srow / 28, ox = srow % 28;
                    int iy = 2*oy - 1 + kh, ix = 2*ox - 1 + kw;
                    if ((unsigned)iy < 56u && (unsigned)ix < 56u) {
                        size_t si = ((size_t)(n*56 + iy)*56 + ix)*64 + kp*2;
                        vh = *(const unsigned*)(g_c1h + si);
                        vl = *(const unsigned*)(g_c1l + si);
                    }
                }
                unsigned sw = swa(srow, kp);
                *(unsigned*)(smc + C2_AH + sw) = vh;
                *(unsigned*)(smc + C2_AL + sw) = vl;
            }
            // stage B: 128 oc (this half) x 32 kp
            for (int e = tid; e < 4096; e += 256) {
                int oc = e >> 5, kp = e & 31;
                size_t so = ((size_t)(s*256 + half*128 + oc))*64 + kp*2;
                unsigned vh = *(const unsigned*)&g_wb2h[so];
                unsigned vl = *(const unsigned*)&g_wb2l[so];
                unsigned sw = swa(oc, kp);
                *(unsigned*)(smc + C2_BH + sw) = vh;
                *(unsigned*)(smc + C2_BL + sw) = vl;
            }
            __syncthreads();

            #pragma unroll
            for (int ks = 0; ks < 4; ks++) {
                int kpb = ks*8;
                unsigned ah[2][4], al[2][4];
                #pragma unroll
                for (int mi = 0; mi < 2; mi++) {
                    int row = rowblk + mi*16 + g;
                    ah[mi][0] = *(const unsigned*)(smc + C2_AH + swa(row,     kpb + t));
                    ah[mi][1] = *(const unsigned*)(smc + C2_AH + swa(row + 8, kpb + t));
                    ah[mi][2] = *(const unsigned*)(smc + C2_AH + swa(row,     kpb + t + 4));
                    ah[mi][3] = *(const unsigned*)(smc + C2_AH + swa(row + 8, kpb + t + 4));
                    al[mi][0] = *(const unsigned*)(smc + C2_AL + swa(row,     kpb + t));
                    al[mi][1] = *(const unsigned*)(smc + C2_AL + swa(row + 8, kpb + t));
                    al[mi][2] = *(const unsigned*)(smc + C2_AL + swa(row,     kpb + t + 4));
                    al[mi][3] = *(const unsigned*)(smc + C2_AL + swa(row + 8, kpb + t + 4));
                }
                #pragma unroll
                for (int nj = 0; nj < 8; nj++) {
                    int oc = colblk + nj*8 + g;
                    unsigned bh[2], bl[2];
                    bh[0] = *(const unsigned*)(smc + C2_BH + swa(oc, kpb + t));
                    bh[1] = *(const unsigned*)(smc + C2_BH + swa(oc, kpb + t + 4));
                    bl[0] = *(const unsigned*)(smc + C2_BL + swa(oc, kpb + t));
                    bl[1] = *(const unsigned*)(smc + C2_BL + swa(oc, kpb + t + 4));
                    #pragma unroll
                    for (int mi = 0; mi < 2; mi++) {
                        mma_bf16(acc[mi][nj], ah[mi], bh);
                        mma_bf16(acc[mi][nj], ah[mi], bl);
                        mma_bf16(acc[mi][nj], al[mi], bh);
                    }
                }
            }
        }

        // epilogue: bias + relu + masked pool partials for this half
        __syncthreads();
        #pragma unroll
        for (int nj = 0; nj < 8; nj++) {
            int cl = colblk + nj*8 + 2*t;     // local col in this half [0,128)
            float bb0 = b2s[half*128 + cl], bb1 = b2s[half*128 + cl + 1];
            float p0 = 0.0f, p1 = 0.0f;
            #pragma unroll
            for (int mi = 0; mi < 2; mi++) {
                int s0 = rowblk + mi*16 + g;
                float m0 = (s0 < 112) ? 1.0f : 0.0f;
                float m1 = (s0 + 8 < 112) ? 1.0f : 0.0f;
                p0 += fmaxf(acc[mi][nj][0] + bb0, 0.0f)*m0 + fmaxf(acc[mi][nj][2] + bb0, 0.0f)*m1;
                p1 += fmaxf(acc[mi][nj][1] + bb1, 0.0f)*m0 + fmaxf(acc[mi][nj][3] + bb1, 0.0f)*m1;
            }
            p0 += __shfl_xor_sync(0xffffffffu, p0, 4);
            p0 += __shfl_xor_sync(0xffffffffu, p0, 8);
            p0 += __shfl_xor_sync(0xffffffffu, p0, 16);
            p1 += __shfl_xor_sync(0xffffffffu, p1, 4);
            p1 += __shfl_xor_sync(0xffffffffu, p1, 8);
            p1 += __shfl_xor_sync(0xffffffffu, p1, 16);
            if (g == 0) {
                red[wm*128 + cl]     = p0;
                red[wm*128 + cl + 1] = p1;
            }
        }
        __syncthreads();
        if (tid < 128) {
            float tsum = red[tid] + red[128 + tid] + red[256 + tid] + red[384 + tid];
            g_part[((size_t)n*7 + rg)*256 + half*128 + tid] = tsum;
        }
    }
}

// ---------------- pooled mean -> h = mean @ Wh + bh ----------------
__global__ void __launch_bounds__(256) k_fc(const float* __restrict__ Wh, const float* __restrict__ bh) {
    __shared__ float p[256];
    __shared__ float r2[256];
    int b = blockIdx.x, cq = blockIdx.y, tid = threadIdx.x;
    {
        float sv = 0.0f;
        const float* pp = g_part + (size_t)b*7*256 + tid;
        #pragma unroll
        for (int tt = 0; tt < 7; tt++) sv += pp[tt*256];
        p[tid] = sv * (1.0f/784.0f);
    }
    __syncthreads();
    int c = cq*128 + (tid & 127);
    int k0 = (tid >> 7)*128;
    float a0 = 0.f, a1 = 0.f, a2 = 0.f, a3 = 0.f;
    #pragma unroll 2
    for (int k = k0; k < k0 + 128; k += 4) {
        a0 = fmaf(p[k],   Wh[(k)*512 + c],   a0);
        a1 = fmaf(p[k+1], Wh[(k+1)*512 + c], a1);
        a2 = fmaf(p[k+2], Wh[(k+2)*512 + c], a2);
        a3 = fmaf(p[k+3], Wh[(k+3)*512 + c], a3);
    }
    r2[tid] = (a0 + a1) + (a2 + a3);
    __syncthreads();
    if (tid < 128) g_h[b*512 + cq*128 + tid] = bh[cq*128 + tid] + r2[tid] + r2[tid + 128];
}

// ---------------- mu (normalized) and kappa ----------------
__global__ void __launch_bounds__(64) k_mukappa(const float* __restrict__ Wmu, const float* __restrict__ bmu,
                                                const float* __restrict__ Wk,  const float* __restrict__ bk,
                                                float* out_mu, float* out_k) {
    __shared__ float h[512];
    int b = blockIdx.x, tid = threadIdx.x;
    for (int i = tid; i < 512; i += 64) h[i] = g_h[b*512 + i];
    __syncthreads();
    if (tid < 32) {
        int o = tid;
        float a0 = 0.f, a1 = 0.f, a2 = 0.f, a3 = 0.f;
        #pragma unroll 2
        for (int k = 0; k < 512; k += 4) {
            a0 = fmaf(h[k],   Wmu[(k)*32 + o],   a0);
            a1 = fmaf(h[k+1], Wmu[(k+1)*32 + o], a1);
            a2 = fmaf(h[k+2], Wmu[(k+2)*32 + o], a2);
            a3 = fmaf(h[k+3], Wmu[(k+3)*32 + o], a3);
        }
        float acc = bmu[o] + ((a0 + a1) + (a2 + a3));
        float ss = acc * acc;
        #pragma unroll
        for (int of = 16; of; of >>= 1) ss += __shfl_xor_sync(0xffffffffu, ss, of);
        float m = acc / sqrtf(fmaxf(ss, 1e-24f));
        g_mu[b*32 + o] = m;
        if (out_mu) out_mu[b*32 + o] = m;
    } else {
        int l = tid - 32;
        float a = 0.f;
        #pragma unroll
        for (int tt = 0; tt < 16; tt++) {
            int k = l*16 + tt;
            a = fmaf(h[k], Wk[k], a);
        }
        #pragma unroll
        for (int of = 16; of; of >>= 1) a += __shfl_xor_sync(0xffffffffu, a, of);
        if (l == 0) {
            float acc = a + bk[0];
            float sp = fmaxf(acc, 0.0f) + log1pf(expf(-fabsf(acc)));
            float kap = sp + 1.0f;
            g_kappa[b] = kap;
            if (out_k) out_k[b] = kap;
        }
    }
}

// ---------------- Threefry2x32 (exact JAX, partitionable) ----------------
static __device__ __forceinline__ void tf2(unsigned k0, unsigned k1, unsigned &x0, unsigned &x1) {
    unsigned ks2 = k0 ^ k1 ^ 0x1BD11BDAu;
    x0 += k0; x1 += k1;
#define TFR(r) { x0 += x1; x1 = __funnelshift_l(x1, x1, r); x1 ^= x0; }
    TFR(13) TFR(15) TFR(26) TFR(6)   x0 += k1;  x1 += ks2 + 1u;
    TFR(17) TFR(29) TFR(16) TFR(24)  x0 += ks2; x1 += k0 + 2u;
    TFR(13) TFR(15) TFR(26) TFR(6)   x0 += k0;  x1 += k1 + 3u;
    TFR(17) TFR(29) TFR(16) TFR(24)  x0 += k1;  x1 += ks2 + 4u;
    TFR(13) TFR(15) TFR(26) TFR(6)   x0 += ks2; x1 += k0 + 5u;
#undef TFR
}
static __device__ __forceinline__ float u01(unsigned bits) {
    return __uint_as_float((bits >> 9) | 0x3f800000u) - 1.0f;
}
static __device__ float erfinv_f(float x) {   // XLA ErfInv32 polynomial
    float w = -log1pf(-x*x);
    float p;
    if (w < 5.0f) {
        w -= 2.5f;
        p = 2.81022636e-08f;
        p = fmaf(p, w, 3.43273939e-07f);
        p = fmaf(p, w, -3.5233877e-06f);
        p = fmaf(p, w, -4.39150654e-06f);
        p = fmaf(p, w, 0.00021858087f);
        p = fmaf(p, w, -0.00125372503f);
        p = fmaf(p, w, -0.00417768164f);
        p = fmaf(p, w, 0.246640727f);
        p = fmaf(p, w, 1.50140941f);
    } else {
        w = sqrtf(w) - 3.0f;
        p = -0.000200214257f;
        p = fmaf(p, w, 0.000100950558f);
        p = fmaf(p, w, 0.00134934322f);
        p = fmaf(p, w, -0.00367342844f);
        p = fmaf(p, w, 0.00573950773f);
        p = fmaf(p, w, -0.0076224613f);
        p = fmaf(p, w, 0.00943887047f);
        p = fmaf(p, w, 1.00167406f);
        p = fmaf(p, w, 2.83297682f);
    }
    return p * x;
}

// ---------------- vMF sampling (Wood), bit-exact JAX RNG ----------------
__global__ void __launch_bounds__(32) k_sample() {
    int b = blockIdx.x;
    int lane = threadIdx.x;
    __shared__ float s_w[10];
    __shared__ int   s_a[10];

    unsigned a0,a1,c0,c1;
    { unsigned x0=0u, x1=0u; tf2(0u,42u,x0,x1); a0=x0; a1=x1; }   // k_w
    { unsigned x0=0u, x1=1u; tf2(0u,42u,x0,x1); c0=x0; c1=x1; }   // k_v

    float kap = g_kappa[b];
    if (lane < 10) {
        unsigned f0,f1,h0,h1;
        { unsigned x0=0u, x1=(unsigned)(2*lane);   tf2(a0,a1,x0,x1); f0=x0; f1=x1; }
        { unsigned x0=0u, x1=(unsigned)(2*lane+1); tf2(a0,a1,x0,x1); h0=x0; h1=x1; }
        unsigned bw, br;
        { unsigned x0=0u, x1=(unsigned)b; tf2(f0,f1,x0,x1); bw = x0 ^ x1; }
        { unsigned x0=0u, x1=(unsigned)b; tf2(h0,h1,x0,x1); br = x0 ^ x1; }
        float wc = 2.0f*u01(bw) - 1.0f;
        float om = fmaxf(1.0f - wc*wc, 1e-40f);
        float lp = kap*wc + 14.5f*logf(om);
        float lr = logf(u01(br) + 1e-40f);
        s_w[lane] = wc;
        s_a[lane] = (lr + kap <= lp) ? 1 : 0;
    }
    __syncthreads();
    float w = 0.0f;
    #pragma unroll
    for (int i = 9; i >= 0; i--) if (s_a[i]) w = s_w[i];
    w = fminf(fmaxf(w, -1.0f), 1.0f);

    float vj = 0.0f;
    if (lane < 31) {
        int e = b*31 + lane;
        unsigned bits;
        { unsigned x0=0u, x1=(unsigned)e; tf2(c0,c1,x0,x1); bits = x0 ^ x1; }
        float u = u01(bits);
        const float LO = -0.99999994f;
        float un = fmaxf(LO, fmaf(u, 2.0f, LO));
        vj = 1.4142135623730951f * erfinv_f(un);
    }
    float ss = vj*vj;
    #pragma unroll
    for (int o = 16; o; o >>= 1) ss += __shfl_xor_sync(0xffffffffu, ss, o);
    vj /= sqrtf(fmaxf(ss, 1e-24f));

    float st = sqrtf(fmaxf(1.0f - w*w, 1e-40f));
    float zt = (lane < 31) ? st*vj : w;

    float mub = g_mu[b*32 + lane];
    float uj = ((lane == 31) ? 1.0f : 0.0f) - mub;
    float us = uj*uj;
    #pragma unroll
    for (int o = 16; o; o >>= 1) us += __shfl_xor_sync(0xffffffffu, us, o);
    uj /= sqrtf(fmaxf(us, 1e-24f));
    float dp = zt*uj;
    #pragma unroll
    for (int o = 16; o; o >>= 1) dp += __shfl_xor_sync(0xffffffffu, dp, o);
    g_z[b*32 + lane] = zt - 2.0f*dp*uj;
}

// ---------------- MLP head (fused, one block per batch row) ----------------
__global__ void __launch_bounds__(512) k_mlp(const float* __restrict__ M1, const float* __restrict__ bM1,
                                             const float* __restrict__ M2, const float* __restrict__ bM2,
                                             const float* __restrict__ M3, const float* __restrict__ bM3,
                                             const float* __restrict__ M4, const float* __restrict__ bM4,
                                             float* __restrict__ out) {
    __shared__ float z[32];
    __shared__ float y1[512];
    __shared__ float y2[512];
    __shared__ float red[32][8];
    __shared__ float y3[32];
    int b = blockIdx.x, tid = threadIdx.x;
    if (tid < 32) z[tid] = g_z[b*32 + tid];
    __syncthreads();
    {
        float acc = bM1[tid];
        #pragma unroll
        for (int k = 0; k < 32; k++) acc = fmaf(z[k], M1[k*512 + tid], acc);
        y1[tid] = fmaxf(acc, 0.0f);
    }
    __syncthreads();
    {
        float a0 = 0.f, a1 = 0.f, a2 = 0.f, a3 = 0.f;
        #pragma unroll 2
        for (int k = 0; k < 512; k += 4) {
            a0 = fmaf(y1[k],   M2[(k)*512 + tid],   a0);
            a1 = fmaf(y1[k+1], M2[(k+1)*512 + tid], a1);
            a2 = fmaf(y1[k+2], M2[(k+2)*512 + tid], a2);
            a3 = fmaf(y1[k+3], M2[(k+3)*512 + tid], a3);
        }
        y2[tid] = fmaxf(bM2[tid] + ((a0 + a1) + (a2 + a3)), 0.0f);
    }
    __syncthreads();
    if (tid < 256) {
        int o = tid >> 3, p = tid & 7;
        float a = 0.f;
        #pragma unroll 4
        for (int tt = 0; tt < 64; tt++) {
            int k = p*64 + tt;
            a = fmaf(y2[k], M3[k*32 + o], a);
        }
        red[o][p] = a;
    }
    __syncthreads();
    if (tid < 32) {
        float a = bM3[tid];
        #pragma unroll
        for (int p = 0; p < 8; p++) a += red[tid][p];
        y3[tid] = fmaxf(a, 0.0f);
    }
    __syncthreads();
    if (tid < 7) {
        float acc = bM4[tid];
        #pragma unroll
        for (int k = 0; k < 32; k++) acc = fmaf(y3[k], M4[k*7 + tid], acc);
        out[b*7 + tid] = acc;
    }
}

// ---------------- launch ----------------
extern "C" void kernel_launch(void* const* d_in, const int* in_sizes, int n_in,
                              void* d_out, int out_size) {
    const float* x   = (const float*)d_in[0];
    const float* W1  = (const float*)d_in[1];
    const float* b1  = (const float*)d_in[2];
    const float* W2  = (const float*)d_in[3];
    const float* b2  = (const float*)d_in[4];
    const float* Wh  = (const float*)d_in[5];
    const float* bh  = (const float*)d_in[6];
    const float* Wmu = (const float*)d_in[7];
    const float* bmu = (const float*)d_in[8];
    const float* Wk  = (const float*)d_in[9];
    const float* bk  = (const float*)d_in[10];
    const float* M1  = (const float*)d_in[11];
    const float* bM1 = (const float*)d_in[12];
    const float* M2  = (const float*)d_in[13];
    const float* bM2 = (const float*)d_in[14];
    const float* M3  = (const float*)d_in[15];
    const float* bM3 = (const float*)d_in[16];
    const float* M4  = (const float*)d_in[17];
    const float* bM4 = (const float*)d_in[18];

    float* out  = (float*)d_out;
    float* omu  = (out_size >= 2560) ? out + 448  : nullptr;   // tuple order: out, mu, kappa
    float* okap = (out_size >= 2560) ? out + 2496 : nullptr;

    cudaFuncSetAttribute(k_conv1, cudaFuncAttributeMaxDynamicSharedMemorySize, C1_SMEM);
    cudaFuncSetAttribute(k_conv2, cudaFuncAttributeMaxDynamicSharedMemorySize, C2_SMEM);

    k_prep<<<128, 256>>>(W1, W2);
    k_conv1<<<dim3(28, 64), 256, C1_SMEM>>>(x, b1);
    k_conv2<<<dim3(7, 64), 256, C2_SMEM>>>(b2);
    k_fc<<<dim3(64, 4), 256>>>(Wh, bh);
    k_mukappa<<<64, 64>>>(Wmu, bmu, Wk, bk, omu, okap);
    k_sample<<<64, 32>>>();
    k_mlp<<<64, 512>>>(M1, bM1, M2, bM2, M3, bM3, M4, bM4, out);
}

// round 11
// speedup vs baseline: 2.0765x; 1.1564x over previous
#include <cuda_runtime.h>
#include <cuda_bf16.h>

// ---------------- scratch (static device globals; no allocation) ----------------
__device__ __nv_bfloat16 g_xh[64*6*224*224];   // x hi bf16 (NCHW, same indexing as x)
__device__ __nv_bfloat16 g_xl[64*6*224*224];   // x lo
__device__ __nv_bfloat16 g_c1h[64*56*56*64];   // conv1 out hi, channels-last [n][y][x][oc]
__device__ __nv_bfloat16 g_c1l[64*56*56*64];   // conv1 out lo
__device__ __nv_bfloat16 g_wn1h[64*336];       // conv1 W [oc][k'] hi, k'=ic*56+kh*8+kw (kw7 pad)
__device__ __nv_bfloat16 g_wn1l[64*336];
__device__ __nv_bfloat16 g_wb2h[9*256*64];     // conv2 W [shift][oc][ic] hi
__device__ __nv_bfloat16 g_wb2l[9*256*64];
__device__ float g_part[64*7*256];             // pooled partials [n][rowgroup][oc]

// ---------------- helpers ----------------
static __device__ __forceinline__ void split_bf16(float v, __nv_bfloat16 &hi, __nv_bfloat16 &lo){
    hi = __float2bfloat16(v);
    lo = __float2bfloat16(v - __bfloat162float(hi));
}
static __device__ __forceinline__ unsigned pack2(__nv_bfloat16 a, __nv_bfloat16 b){
    return (unsigned)__bfloat16_as_ushort(a) | ((unsigned)__bfloat16_as_ushort(b) << 16);
}
// packed f32 pair -> bf16x2: result lo = bf16(lo_from), hi = bf16(hi_from)
static __device__ __forceinline__ unsigned cvt2(float lo_from, float hi_from){
    unsigned r; asm("cvt.rn.bf16x2.f32 %0, %1, %2;" : "=r"(r) : "f"(hi_from), "f"(lo_from)); return r;
}
// swizzled byte offset, 256B row stride, kp in u32 units [0,64)
static __device__ __forceinline__ unsigned swa64(int row, int kp){
    return (unsigned)(row*256 + ((((kp>>2) ^ (row & 7)) << 4) | ((kp & 3) << 2)));
}
// old 128B-row swizzle (conv2 unchanged)
static __device__ __forceinline__ unsigned swa(int row, int kp){
    return (unsigned)(row*128 + ((((kp>>2) ^ (row & 7)) << 4) | ((kp & 3) << 2)));
}
static __device__ __forceinline__ void mma_bf16(float* d, const unsigned* a, const unsigned* b){
    asm volatile("mma.sync.aligned.m16n8k16.row.col.f32.bf16.bf16.f32 "
        "{%0,%1,%2,%3}, {%4,%5,%6,%7}, {%8,%9}, {%0,%1,%2,%3};"
        : "+f"(d[0]), "+f"(d[1]), "+f"(d[2]), "+f"(d[3])
        : "r"(a[0]), "r"(a[1]), "r"(a[2]), "r"(a[3]), "r"(b[0]), "r"(b[1]));
}

// ---------------- prep: weights -> bf16 hi/lo ----------------
__global__ void k_prew(const float* __restrict__ W1, const float* __restrict__ W2) {
    int stride = gridDim.x * blockDim.x;
    int i0 = blockIdx.x * blockDim.x + threadIdx.x;
    for (int i = i0; i < 64*336; i += stride) {
        int oc = i / 336, kq = i - oc*336;
        int ic = kq / 56, r = kq - ic*56, kh = r >> 3, kw = r & 7;
        float v = (kw < 7) ? W1[oc*294 + ic*49 + kh*7 + kw] : 0.0f;
        __nv_bfloat16 hi, lo; split_bf16(v, hi, lo);
        g_wn1h[i] = hi; g_wn1l[i] = lo;
    }
    for (int i = i0; i < 9*256*64; i += stride) {
        int ic = i & 63, oc = (i >> 6) & 255, s = i >> 14;
        int kh = s / 3, kw = s - kh*3;
        float v = W2[oc*576 + ic*9 + kh*3 + kw];
        __nv_bfloat16 hi, lo; split_bf16(v, hi, lo);
        g_wb2h[i] = hi; g_wb2l[i] = lo;
    }
}

// ---------------- prex: x -> bf16 hi/lo (16 floats/thread) ----------------
__global__ void __launch_bounds__(256) k_prex(const float* __restrict__ x) {
    size_t fidx = ((size_t)blockIdx.x*256 + threadIdx.x) * 16;
    const float4* xv = (const float4*)(x + fidx);
    unsigned hh[8], ll[8];
    #pragma unroll
    for (int q = 0; q < 4; q++) {
        float4 v = xv[q];
        unsigned h01 = cvt2(v.x, v.y);
        unsigned h23 = cvt2(v.z, v.w);
        float r0 = __uint_as_float(h01 << 16);
        float r1 = __uint_as_float(h01 & 0xFFFF0000u);
        float r2 = __uint_as_float(h23 << 16);
        float r3 = __uint_as_float(h23 & 0xFFFF0000u);
        hh[2*q] = h01; hh[2*q+1] = h23;
        ll[2*q]   = cvt2(v.x - r0, v.y - r1);
        ll[2*q+1] = cvt2(v.z - r2, v.w - r3);
    }
    uint4* oh = (uint4*)((unsigned*)g_xh + (fidx >> 1));
    uint4* ol = (uint4*)((unsigned*)g_xl + (fidx >> 1));
    oh[0] = make_uint4(hh[0],hh[1],hh[2],hh[3]);
    oh[1] = make_uint4(hh[4],hh[5],hh[6],hh[7]);
    ol[0] = make_uint4(ll[0],ll[1],ll[2],ll[3]);
    ol[1] = make_uint4(ll[4],ll[5],ll[6],ll[7]);
}

// ---------------- conv1: HMMA implicit GEMM, run-based staging ----------------
// grid (28 row-pairs, 64 n), 256 thr (8 warps: 4M x 2N). M=128(112 used), K'=336 (3 chunks of 112), N=64.
#define C1_B1S  0        // 64 f32
#define C1_AH   1024     // 128x64 u32 = 32KB
#define C1_AL   33792
#define C1_BH   66560    // 64x64 u32 = 16KB
#define C1_BL   82944
#define C1_SMEM 99328
__global__ void __launch_bounds__(256)
k_conv1(const float* __restrict__ b1) {
    extern __shared__ char smc[];
    float* b1s = (float*)(smc + C1_B1S);
    int pr = blockIdx.x, n = blockIdx.y;
    int tid = threadIdx.x, wid = tid >> 5, lane = tid & 31;
    int g = lane >> 2, t = lane & 3;
    int wm = wid >> 1, wn = wid & 1;
    int rowblk = wm*32, colblk = wn*32;

    if (tid < 64) b1s[tid] = b1[tid];

    float acc[2][4][4];
    #pragma unroll
    for (int mi = 0; mi < 2; mi++)
        #pragma unroll
        for (int nj = 0; nj < 4; nj++)
            #pragma unroll
            for (int q = 0; q < 4; q++) acc[mi][nj][q] = 0.0f;

    for (int c = 0; c < 3; c++) {
        __syncthreads();
        // ---- stage A: items = (row, icL, kh); each item = 8 bf16 (kw 0..6 + pad) ----
        #pragma unroll 1
        for (int j = 0; j < 7; j++) {
            int it = tid + 256*j;            // [0, 1792)
            int row = it & 127;
            int icL = (it >> 7) & 1;
            int kh  = it >> 8;               // 0..6
            unsigned r0=0,r1=0,r2=0,r3=0, s0=0,s1=0,s2=0,s3=0;
            if (row < 112) {
                int hi56 = (row >= 56);
                int oy = pr*2 + hi56;
                int ox = row - (hi56 ? 56 : 0);
                int iy = 4*oy - 3 + kh;
                if (iy >= 0) {
                    int ic = c*2 + icL;
                    size_t base = (size_t)n*301056 + (size_t)(ic*224 + iy)*224;
                    if (ox > 0) {
                        const uint2* ph = (const uint2*)(g_xh + base + 4*ox - 4);
                        const uint2* pl = (const uint2*)(g_xl + base + 4*ox - 4);
                        uint2 a = ph[0], bq = ph[1];
                        uint2 e = pl[0], f = pl[1];
                        r0 = __funnelshift_r(a.x, a.y, 16);
                        r1 = __funnelshift_r(a.y, bq.x, 16);
                        r2 = __funnelshift_r(bq.x, bq.y, 16);
                        r3 = bq.y >> 16;
                        s0 = __funnelshift_r(e.x, e.y, 16);
                        s1 = __funnelshift_r(e.y, f.x, 16);
                        s2 = __funnelshift_r(f.x, f.y, 16);
                        s3 = f.y >> 16;
                    } else {
                        uint2 a = *(const uint2*)(g_xh + base);   // ix 0..3 -> kw 3..6
                        uint2 e = *(const uint2*)(g_xl + base);
                        r1 = (a.x & 0xFFFFu) << 16;
                        r2 = __funnelshift_r(a.x, a.y, 16);
                        r3 = a.y >> 16;
                        s1 = (e.x & 0xFFFFu) << 16;
                        s2 = __funnelshift_r(e.x, e.y, 16);
                        s3 = e.y >> 16;
                    }
                }
            }
            int kp0 = icL*28 + kh*4;
            unsigned dofs = (unsigned)(row*256 + (((kp0>>2) ^ (row & 7)) << 4));
            *(uint4*)(smc + C1_AH + dofs) = make_uint4(r0,r1,r2,r3);
            *(uint4*)(smc + C1_AL + dofs) = make_uint4(s0,s1,s2,s3);
        }
        // ---- stage B: 64 oc x 14 uint4 per array ----
        #pragma unroll 1
        for (int e = tid; e < 1792; e += 256) {
            int arr = (e >= 896);
            int e2 = arr ? e - 896 : e;
            int oc = e2 / 14, q = e2 - oc*14;
            const unsigned* src = (arr ? (const unsigned*)g_wn1l : (const unsigned*)g_wn1h)
                                  + oc*168 + c*56 + q*4;
            uint4 v = *(const uint4*)src;
            char* dst = smc + (arr ? C1_BL : C1_BH) + oc*256 + ((q ^ (oc & 7)) << 4);
            *(uint4*)dst = v;
        }
        __syncthreads();

        #pragma unroll
        for (int ks = 0; ks < 7; ks++) {
            int kpb = ks*8;
            unsigned ah[2][4], al[2][4];
            #pragma unroll
            for (int mi = 0; mi < 2; mi++) {
                int row = rowblk + mi*16 + g;
                ah[mi][0] = *(const unsigned*)(smc + C1_AH + swa64(row,     kpb + t));
                ah[mi][1] = *(const unsigned*)(smc + C1_AH + swa64(row + 8, kpb + t));
                ah[mi][2] = *(const unsigned*)(smc + C1_AH + swa64(row,     kpb + t + 4));
                ah[mi][3] = *(const unsigned*)(smc + C1_AH + swa64(row + 8, kpb + t + 4));
                al[mi][0] = *(const unsigned*)(smc + C1_AL + swa64(row,     kpb + t));
                al[mi][1] = *(const unsigned*)(smc + C1_AL + swa64(row + 8, kpb + t));
                al[mi][2] = *(const unsigned*)(smc + C1_AL + swa64(row,     kpb + t + 4));
                al[mi][3] = *(const unsigned*)(smc + C1_AL + swa64(row + 8, kpb + t + 4));
            }
            #pragma unroll
            for (int nj = 0; nj < 4; nj++) {
                int oc = colblk + nj*8 + g;
                unsigned bh[2], bl[2];
                bh[0] = *(const unsigned*)(smc + C1_BH + swa64(oc, kpb + t));
                bh[1] = *(const unsigned*)(smc + C1_BH + swa64(oc, kpb + t + 4));
                bl[0] = *(const unsigned*)(smc + C1_BL + swa64(oc, kpb + t));
                bl[1] = *(const unsigned*)(smc + C1_BL + swa64(oc, kpb + t + 4));
                #pragma unroll
                for (int mi = 0; mi < 2; mi++) {
                    mma_bf16(acc[mi][nj], ah[mi], bh);
                    mma_bf16(acc[mi][nj], ah[mi], bl);
                    mma_bf16(acc[mi][nj], al[mi], bh);
                }
            }
        }
    }

    // epilogue: bias + relu + split -> channels-last bf16 hi/lo
    #pragma unroll
    for (int mi = 0; mi < 2; mi++) {
        #pragma unroll
        for (int nj = 0; nj < 4; nj++) {
            int cc = colblk + nj*8 + 2*t;
            float bb0 = b1s[cc], bb1 = b1s[cc + 1];
            #pragma unroll
            for (int rh = 0; rh < 2; rh++) {
                int s = rowblk + mi*16 + g + rh*8;
                if (s < 112) {
                    float v0 = fmaxf(acc[mi][nj][rh*2]     + bb0, 0.0f);
                    float v1 = fmaxf(acc[mi][nj][rh*2 + 1] + bb1, 0.0f);
                    int hi56 = (s >= 56);
                    int oy = pr*2 + hi56, ox = s - (hi56 ? 56 : 0);
                    size_t ob = ((size_t)(n*56 + oy)*56 + ox)*64 + cc;
                    __nv_bfloat16 h0, l0, h1, l1;
                    split_bf16(v0, h0, l0); split_bf16(v1, h1, l1);
                    *(unsigned*)(g_c1h + ob) = pack2(h0, h1);
                    *(unsigned*)(g_c1l + ob) = pack2(l0, l1);
                }
            }
        }
    }
}

// ---------------- conv2: HMMA, 9 shifted GEMMs + fused pool (unchanged) ----------------
#define C2_B2S  0
#define C2_RED  1024
#define C2_AH   4096
#define C2_AL   20480
#define C2_BH   36864
#define C2_BL   53248
#define C2_SMEM 69632
__global__ void __launch_bounds__(256)
k_conv2(const float* __restrict__ b2) {
    extern __shared__ char smc[];
    float* b2s = (float*)(smc + C2_B2S);
    float* red = (float*)(smc + C2_RED);
    int rg = blockIdx.x, n = blockIdx.y;
    int tid = threadIdx.x, wid = tid >> 5, lane = tid & 31;
    int g = lane >> 2, t = lane & 3;
    int wm = wid >> 1, wn = wid & 1;
    int rowblk = wm*32, colblk = wn*64;

    b2s[tid] = b2[tid];

    for (int half = 0; half < 2; half++) {
        float acc[2][8][4];
        #pragma unroll
        for (int mi = 0; mi < 2; mi++)
            #pragma unroll
            for (int nj = 0; nj < 8; nj++)
                #pragma unroll
                for (int q = 0; q < 4; q++) acc[mi][nj][q] = 0.0f;

        for (int s = 0; s < 9; s++) {
            int kh = s / 3, kw = s - kh*3;
            __syncthreads();
            for (int e = tid; e < 4096; e += 256) {
                int srow = e >> 5, kp = e & 31;
                unsigned vh = 0u, vl = 0u;
                if (srow < 112) {
                    int oy = rg*4 + srow / 28, ox = srow % 28;
                    int iy = 2*oy - 1 + kh, ix = 2*ox - 1 + kw;
                    if ((unsigned)iy < 56u && (unsigned)ix < 56u) {
                        size_t si = ((size_t)(n*56 + iy)*56 + ix)*64 + kp*2;
                        vh = *(const unsigned*)(g_c1h + si);
                        vl = *(const unsigned*)(g_c1l + si);
                    }
                }
                unsigned sw = swa(srow, kp);
                *(unsigned*)(smc + C2_AH + sw) = vh;
                *(unsigned*)(smc + C2_AL + sw) = vl;
            }
            for (int e = tid; e < 4096; e += 256) {
                int oc = e >> 5, kp = e & 31;
                size_t so = ((size_t)(s*256 + half*128 + oc))*64 + kp*2;
                unsigned vh = *(const unsigned*)&g_wb2h[so];
                unsigned vl = *(const unsigned*)&g_wb2l[so];
                unsigned sw = swa(oc, kp);
                *(unsigned*)(smc + C2_BH + sw) = vh;
                *(unsigned*)(smc + C2_BL + sw) = vl;
            }
            __syncthreads();

            #pragma unroll
            for (int ks = 0; ks < 4; ks++) {
                int kpb = ks*8;
                unsigned ah[2][4], al[2][4];
                #pragma unroll
                for (int mi = 0; mi < 2; mi++) {
                    int row = rowblk + mi*16 + g;
                    ah[mi][0] = *(const unsigned*)(smc + C2_AH + swa(row,     kpb + t));
                    ah[mi][1] = *(const unsigned*)(smc + C2_AH + swa(row + 8, kpb + t));
                    ah[mi][2] = *(const unsigned*)(smc + C2_AH + swa(row,     kpb + t + 4));
                    ah[mi][3] = *(const unsigned*)(smc + C2_AH + swa(row + 8, kpb + t + 4));
                    al[mi][0] = *(const unsigned*)(smc + C2_AL + swa(row,     kpb + t));
                    al[mi][1] = *(const unsigned*)(smc + C2_AL + swa(row + 8, kpb + t));
                    al[mi][2] = *(const unsigned*)(smc + C2_AL + swa(row,     kpb + t + 4));
                    al[mi][3] = *(const unsigned*)(smc + C2_AL + swa(row + 8, kpb + t + 4));
                }
                #pragma unroll
                for (int nj = 0; nj < 8; nj++) {
                    int oc = colblk + nj*8 + g;
                    unsigned bh[2], bl[2];
                    bh[0] = *(const unsigned*)(smc + C2_BH + swa(oc, kpb + t));
                    bh[1] = *(const unsigned*)(smc + C2_BH + swa(oc, kpb + t + 4));
                    bl[0] = *(const unsigned*)(smc + C2_BL + swa(oc, kpb + t));
                    bl[1] = *(const unsigned*)(smc + C2_BL + swa(oc, kpb + t + 4));
                    #pragma unroll
                    for (int mi = 0; mi < 2; mi++) {
                        mma_bf16(acc[mi][nj], ah[mi], bh);
                        mma_bf16(acc[mi][nj], ah[mi], bl);
                        mma_bf16(acc[mi][nj], al[mi], bh);
                    }
                }
            }
        }

        __syncthreads();
        #pragma unroll
        for (int nj = 0; nj < 8; nj++) {
            int cl = colblk + nj*8 + 2*t;
            float bb0 = b2s[half*128 + cl], bb1 = b2s[half*128 + cl + 1];
            float p0 = 0.0f, p1 = 0.0f;
            #pragma unroll
            for (int mi = 0; mi < 2; mi++) {
                int s0 = rowblk + mi*16 + g;
                float m0 = (s0 < 112) ? 1.0f : 0.0f;
                float m1 = (s0 + 8 < 112) ? 1.0f : 0.0f;
                p0 += fmaxf(acc[mi][nj][0] + bb0, 0.0f)*m0 + fmaxf(acc[mi][nj][2] + bb0, 0.0f)*m1;
                p1 += fmaxf(acc[mi][nj][1] + bb1, 0.0f)*m0 + fmaxf(acc[mi][nj][3] + bb1, 0.0f)*m1;
            }
            p0 += __shfl_xor_sync(0xffffffffu, p0, 4);
            p0 += __shfl_xor_sync(0xffffffffu, p0, 8);
            p0 += __shfl_xor_sync(0xffffffffu, p0, 16);
            p1 += __shfl_xor_sync(0xffffffffu, p1, 4);
            p1 += __shfl_xor_sync(0xffffffffu, p1, 8);
            p1 += __shfl_xor_sync(0xffffffffu, p1, 16);
            if (g == 0) {
                red[wm*128 + cl]     = p0;
                red[wm*128 + cl + 1] = p1;
            }
        }
        __syncthreads();
        if (tid < 128) {
            float tsum = red[tid] + red[128 + tid] + red[256 + tid] + red[384 + tid];
            g_part[((size_t)n*7 + rg)*256 + half*128 + tid] = tsum;
        }
    }
}

// ---------------- Threefry2x32 (exact JAX, partitionable) ----------------
static __device__ __forceinline__ void tf2(unsigned k0, unsigned k1, unsigned &x0, unsigned &x1) {
    unsigned ks2 = k0 ^ k1 ^ 0x1BD11BDAu;
    x0 += k0; x1 += k1;
#define TFR(r) { x0 += x1; x1 = __funnelshift_l(x1, x1, r); x1 ^= x0; }
    TFR(13) TFR(15) TFR(26) TFR(6)   x0 += k1;  x1 += ks2 + 1u;
    TFR(17) TFR(29) TFR(16) TFR(24)  x0 += ks2; x1 += k0 + 2u;
    TFR(13) TFR(15) TFR(26) TFR(6)   x0 += k0;  x1 += k1 + 3u;
    TFR(17) TFR(29) TFR(16) TFR(24)  x0 += k1;  x1 += ks2 + 4u;
    TFR(13) TFR(15) TFR(26) TFR(6)   x0 += ks2; x1 += k0 + 5u;
#undef TFR
}
static __device__ __forceinline__ float u01(unsigned bits) {
    return __uint_as_float((bits >> 9) | 0x3f800000u) - 1.0f;
}
static __device__ float erfinv_f(float x) {
    float w = -log1pf(-x*x);
    float p;
    if (w < 5.0f) {
        w -= 2.5f;
        p = 2.81022636e-08f;
        p = fmaf(p, w, 3.43273939e-07f);
        p = fmaf(p, w, -3.5233877e-06f);
        p = fmaf(p, w, -4.39150654e-06f);
        p = fmaf(p, w, 0.00021858087f);
        p = fmaf(p, w, -0.00125372503f);
        p = fmaf(p, w, -0.00417768164f);
        p = fmaf(p, w, 0.246640727f);
        p = fmaf(p, w, 1.50140941f);
    } else {
        w = sqrtf(w) - 3.0f;
        p = -0.000200214257f;
        p = fmaf(p, w, 0.000100950558f);
        p = fmaf(p, w, 0.00134934322f);
        p = fmaf(p, w, -0.00367342844f);
        p = fmaf(p, w, 0.00573950773f);
        p = fmaf(p, w, -0.0076224613f);
        p = fmaf(p, w, 0.00943887047f);
        p = fmaf(p, w, 1.00167406f);
        p = fmaf(p, w, 2.83297682f);
    }
    return p * x;
}

// ---------------- fused tail: fc + mu/kappa + vMF sample + MLP ----------------
// grid 64 (one per batch row), 512 threads
__global__ void __launch_bounds__(512)
k_tail(const float* __restrict__ Wh,  const float* __restrict__ bh,
       const float* __restrict__ Wmu, const float* __restrict__ bmu,
       const float* __restrict__ Wk,  const float* __restrict__ bk,
       const float* __restrict__ M1,  const float* __restrict__ bM1,
       const float* __restrict__ M2,  const float* __restrict__ bM2,
       const float* __restrict__ M3,  const float* __restrict__ bM3,
       const float* __restrict__ M4,  const float* __restrict__ bM4,
       float* __restrict__ out, float* __restrict__ omu, float* __restrict__ okap) {
    __shared__ float p[256];
    __shared__ float h[512];
    __shared__ float redmu[16][32];
    __shared__ float mus[32];
    __shared__ float kapsh;
    __shared__ float s_w[10];
    __shared__ int   s_a[10];
    __shared__ float zs[32];
    __shared__ float y1[512];
    __shared__ float y2[512];
    __shared__ float red3[32][8];
    __shared__ float y3[32];
    int b = blockIdx.x, tid = threadIdx.x;

    if (tid < 256) {
        float sv = 0.0f;
        const float* pp = g_part + (size_t)b*7*256 + tid;
        #pragma unroll
        for (int tt = 0; tt < 7; tt++) sv += pp[tt*256];
        p[tid] = sv * (1.0f/784.0f);
    }
    __syncthreads();
    // fc: 512 outputs, one per thread
    {
        float a0 = 0.f, a1 = 0.f, a2 = 0.f, a3 = 0.f;
        #pragma unroll 4
        for (int k = 0; k < 256; k += 4) {
            a0 = fmaf(p[k],   Wh[(k)*512 + tid],   a0);
            a1 = fmaf(p[k+1], Wh[(k+1)*512 + tid], a1);
            a2 = fmaf(p[k+2], Wh[(k+2)*512 + tid], a2);
            a3 = fmaf(p[k+3], Wh[(k+3)*512 + tid], a3);
        }
        h[tid] = bh[tid] + ((a0 + a1) + (a2 + a3));
    }
    __syncthreads();
    // mu partials: 16 segments x 32 outputs
    {
        int o = tid & 31, seg = tid >> 5;
        float a = 0.f;
        #pragma unroll 4
        for (int tt = 0; tt < 32; tt++) {
            int k = seg*32 + tt;
            a = fmaf(h[k], Wmu[k*32 + o], a);
        }
        redmu[seg][o] = a;
    }
    __syncthreads();
    if (tid < 32) {
        float acc = bmu[tid];
        #pragma unroll
        for (int s2 = 0; s2 < 16; s2++) acc += redmu[s2][tid];
        float ss = acc * acc;
        #pragma unroll
        for (int of = 16; of; of >>= 1) ss += __shfl_xor_sync(0xffffffffu, ss, of);
        float m = acc / sqrtf(fmaxf(ss, 1e-24f));
        mus[tid] = m;
        if (omu) omu[b*32 + tid] = m;
    } else if (tid < 64) {
        int l = tid - 32;
        float a = 0.f;
        #pragma unroll
        for (int tt = 0; tt < 16; tt++) {
            int k = l*16 + tt;
            a = fmaf(h[k], Wk[k], a);
        }
        #pragma unroll
        for (int of = 16; of; of >>= 1) a += __shfl_xor_sync(0xffffffffu, a, of);
        if (l == 0) {
            float acc = a + bk[0];
            float sp = fmaxf(acc, 0.0f) + log1pf(expf(-fabsf(acc)));
            float kap = sp + 1.0f;
            kapsh = kap;
            if (okap) okap[b] = kap;
        }
    }
    __syncthreads();
    // vMF sample (warp 0)
    if (tid < 32) {
        int lane = tid;
        unsigned a0,a1,c0,c1;
        { unsigned x0=0u, x1=0u; tf2(0u,42u,x0,x1); a0=x0; a1=x1; }   // k_w
        { unsigned x0=0u, x1=1u; tf2(0u,42u,x0,x1); c0=x0; c1=x1; }   // k_v
        float kap = kapsh;
        if (lane < 10) {
            unsigned f0,f1,h0,h1;
            { unsigned x0=0u, x1=(unsigned)(2*lane);   tf2(a0,a1,x0,x1); f0=x0; f1=x1; }
            { unsigned x0=0u, x1=(unsigned)(2*lane+1); tf2(a0,a1,x0,x1); h0=x0; h1=x1; }
            unsigned bw, br;
            { unsigned x0=0u, x1=(unsigned)b; tf2(f0,f1,x0,x1); bw = x0 ^ x1; }
            { unsigned x0=0u, x1=(unsigned)b; tf2(h0,h1,x0,x1); br = x0 ^ x1; }
            float wc = 2.0f*u01(bw) - 1.0f;
            float om = fmaxf(1.0f - wc*wc, 1e-40f);
            float lp = kap*wc + 14.5f*logf(om);
            float lr = logf(u01(br) + 1e-40f);
            s_w[lane] = wc;
            s_a[lane] = (lr + kap <= lp) ? 1 : 0;
        }
        __syncwarp();
        float w = 0.0f;
        #pragma unroll
        for (int i = 9; i >= 0; i--) if (s_a[i]) w = s_w[i];
        w = fminf(fmaxf(w, -1.0f), 1.0f);

        float vj = 0.0f;
        if (lane < 31) {
            int e = b*31 + lane;
            unsigned bits;
            { unsigned x0=0u, x1=(unsigned)e; tf2(c0,c1,x0,x1); bits = x0 ^ x1; }
            float u = u01(bits);
            const float LO = -0.99999994f;
            float un = fmaxf(LO, fmaf(u, 2.0f, LO));
            vj = 1.4142135623730951f * erfinv_f(un);
        }
        float ss = vj*vj;
        #pragma unroll
        for (int o = 16; o; o >>= 1) ss += __shfl_xor_sync(0xffffffffu, ss, o);
        vj /= sqrtf(fmaxf(ss, 1e-24f));

        float st = sqrtf(fmaxf(1.0f - w*w, 1e-40f));
        float zt = (lane < 31) ? st*vj : w;

        float mub = mus[lane];
        float uj = ((lane == 31) ? 1.0f : 0.0f) - mub;
        float us = uj*uj;
        #pragma unroll
        for (int o = 16; o; o >>= 1) us += __shfl_xor_sync(0xffffffffu, us, o);
        uj /= sqrtf(fmaxf(us, 1e-24f));
        float dp = zt*uj;
        #pragma unroll
        for (int o = 16; o; o >>= 1) dp += __shfl_xor_sync(0xffffffffu, dp, o);
        zs[lane] = zt - 2.0f*dp*uj;
    }
    __syncthreads();
    // MLP
    {
        float acc = bM1[tid];
        #pragma unroll
        for (int k = 0; k < 32; k++) acc = fmaf(zs[k], M1[k*512 + tid], acc);
        y1[tid] = fmaxf(acc, 0.0f);
    }
    __syncthreads();
    {
        float a0 = 0.f, a1 = 0.f, a2 = 0.f, a3 = 0.f;
        #pragma unroll 4
        for (int k = 0; k < 512; k += 4) {
            a0 = fmaf(y1[k],   M2[(k)*512 + tid],   a0);
            a1 = fmaf(y1[k+1], M2[(k+1)*512 + tid], a1);
            a2 = fmaf(y1[k+2], M2[(k+2)*512 + tid], a2);
            a3 = fmaf(y1[k+3], M2[(k+3)*512 + tid], a3);
        }
        y2[tid] = fmaxf(bM2[tid] + ((a0 + a1) + (a2 + a3)), 0.0f);
    }
    __syncthreads();
    if (tid < 256) {
        int o = tid >> 3, pp = tid & 7;
        float a = 0.f;
        #pragma unroll 4
        for (int tt = 0; tt < 64; tt++) {
            int k = pp*64 + tt;
            a = fmaf(y2[k], M3[k*32 + o], a);
        }
        red3[o][pp] = a;
    }
    __syncthreads();
    if (tid < 32) {
        float a = bM3[tid];
        #pragma unroll
        for (int pp = 0; pp < 8; pp++) a += red3[tid][pp];
        y3[tid] = fmaxf(a, 0.0f);
    }
    __syncthreads();
    if (tid < 7) {
        float acc = bM4[tid];
        #pragma unroll
        for (int k = 0; k < 32; k++) acc = fmaf(y3[k], M4[k*7 + tid], acc);
        out[b*7 + tid] = acc;
    }
}

// ---------------- launch ----------------
extern "C" void kernel_launch(void* const* d_in, const int* in_sizes, int n_in,
                              void* d_out, int out_size) {
    const float* x   = (const float*)d_in[0];
    const float* W1  = (const float*)d_in[1];
    const float* b1  = (const float*)d_in[2];
    const float* W2  = (const float*)d_in[3];
    const float* b2  = (const float*)d_in[4];
    const float* Wh  = (const float*)d_in[5];
    const float* bh  = (const float*)d_in[6];
    const float* Wmu = (const float*)d_in[7];
    const float* bmu = (const float*)d_in[8];
    const float* Wk  = (const float*)d_in[9];
    const float* bk  = (const float*)d_in[10];
    const float* M1  = (const float*)d_in[11];
    const float* bM1 = (const float*)d_in[12];
    const float* M2  = (const float*)d_in[13];
    const float* bM2 = (const float*)d_in[14];
    const float* M3  = (const float*)d_in[15];
    const float* bM3 = (const float*)d_in[16];
    const float* M4  = (const float*)d_in[17];
    const float* bM4 = (const float*)d_in[18];

    float* out  = (float*)d_out;
    float* omu  = (out_size >= 2560) ? out + 448  : nullptr;   // tuple order: out, mu, kappa
    float* okap = (out_size >= 2560) ? out + 2496 : nullptr;

    cudaFuncSetAttribute(k_conv1, cudaFuncAttributeMaxDynamicSharedMemorySize, C1_SMEM);
    cudaFuncSetAttribute(k_conv2, cudaFuncAttributeMaxDynamicSharedMemorySize, C2_SMEM);

    k_prew<<<128, 256>>>(W1, W2);
    k_prex<<<4704, 256>>>(x);
    k_conv1<<<dim3(28, 64), 256, C1_SMEM>>>(b1);
    k_conv2<<<dim3(7, 64), 256, C2_SMEM>>>(b2);
    k_tail<<<64, 512>>>(Wh, bh, Wmu, bmu, Wk, bk, M1, bM1, M2, bM2, M3, bM3, M4, bM4,
                        out, omu, okap);
}

// round 12
// speedup vs baseline: 3.0562x; 1.4718x over previous
#include <cuda_runtime.h>
#include <cuda_bf16.h>

// ---------------- scratch (static device globals; no allocation) ----------------
__device__ __nv_bfloat16 g_xh[64*6*224*224];   // x hi bf16 (NCHW, same indexing as x)
__device__ __nv_bfloat16 g_xl[64*6*224*224];   // x lo
__device__ __nv_bfloat16 g_c1h[64*56*56*64];   // conv1 out hi, channels-last [n][y][x][oc]
__device__ __nv_bfloat16 g_c1l[64*56*56*64];   // conv1 out lo
__device__ __nv_bfloat16 g_wn1h[64*336];       // conv1 W [oc][k'] hi, k'=ic*56+kh*8+kw (kw7 pad)
__device__ __nv_bfloat16 g_wn1l[64*336];
__device__ __nv_bfloat16 g_wb2h[9*256*64];     // conv2 W [shift][oc][ic] hi
__device__ __nv_bfloat16 g_wb2l[9*256*64];
__device__ float g_part[64*7*256];             // pooled partials [n][rowgroup][oc]

// ---------------- helpers ----------------
static __device__ __forceinline__ void split_bf16(float v, __nv_bfloat16 &hi, __nv_bfloat16 &lo){
    hi = __float2bfloat16(v);
    lo = __float2bfloat16(v - __bfloat162float(hi));
}
static __device__ __forceinline__ unsigned pack2(__nv_bfloat16 a, __nv_bfloat16 b){
    return (unsigned)__bfloat16_as_ushort(a) | ((unsigned)__bfloat16_as_ushort(b) << 16);
}
// packed f32 pair -> bf16x2: result lo = bf16(lo_from), hi = bf16(hi_from)
static __device__ __forceinline__ unsigned cvt2(float lo_from, float hi_from){
    unsigned r; asm("cvt.rn.bf16x2.f32 %0, %1, %2;" : "=r"(r) : "f"(hi_from), "f"(lo_from)); return r;
}
// swizzled byte offset, 256B row stride, kp in u32 units [0,64)
static __device__ __forceinline__ unsigned swa64(int row, int kp){
    return (unsigned)(row*256 + ((((kp>>2) ^ (row & 7)) << 4) | ((kp & 3) << 2)));
}
// 128B-row swizzle (conv2)
static __device__ __forceinline__ unsigned swa(int row, int kp){
    return (unsigned)(row*128 + ((((kp>>2) ^ (row & 7)) << 4) | ((kp & 3) << 2)));
}
static __device__ __forceinline__ void mma_bf16(float* d, const unsigned* a, const unsigned* b){
    asm volatile("mma.sync.aligned.m16n8k16.row.col.f32.bf16.bf16.f32 "
        "{%0,%1,%2,%3}, {%4,%5,%6,%7}, {%8,%9}, {%0,%1,%2,%3};"
        : "+f"(d[0]), "+f"(d[1]), "+f"(d[2]), "+f"(d[3])
        : "r"(a[0]), "r"(a[1]), "r"(a[2]), "r"(a[3]), "r"(b[0]), "r"(b[1]));
}

// ---------------- prep: weights -> bf16 hi/lo ----------------
__global__ void k_prew(const float* __restrict__ W1, const float* __restrict__ W2) {
    int stride = gridDim.x * blockDim.x;
    int i0 = blockIdx.x * blockDim.x + threadIdx.x;
    for (int i = i0; i < 64*336; i += stride) {
        int oc = i / 336, kq = i - oc*336;
        int ic = kq / 56, r = kq - ic*56, kh = r >> 3, kw = r & 7;
        float v = (kw < 7) ? W1[oc*294 + ic*49 + kh*7 + kw] : 0.0f;
        __nv_bfloat16 hi, lo; split_bf16(v, hi, lo);
        g_wn1h[i] = hi; g_wn1l[i] = lo;
    }
    for (int i = i0; i < 9*256*64; i += stride) {
        int ic = i & 63, oc = (i >> 6) & 255, s = i >> 14;
        int kh = s / 3, kw = s - kh*3;
        float v = W2[oc*576 + ic*9 + kh*3 + kw];
        __nv_bfloat16 hi, lo; split_bf16(v, hi, lo);
        g_wb2h[i] = hi; g_wb2l[i] = lo;
    }
}

// ---------------- prex: x -> bf16 hi/lo (16 floats/thread) ----------------
__global__ void __launch_bounds__(256) k_prex(const float* __restrict__ x) {
    size_t fidx = ((size_t)blockIdx.x*256 + threadIdx.x) * 16;
    const float4* xv = (const float4*)(x + fidx);
    unsigned hh[8], ll[8];
    #pragma unroll
    for (int q = 0; q < 4; q++) {
        float4 v = xv[q];
        unsigned h01 = cvt2(v.x, v.y);
        unsigned h23 = cvt2(v.z, v.w);
        float r0 = __uint_as_float(h01 << 16);
        float r1 = __uint_as_float(h01 & 0xFFFF0000u);
        float r2 = __uint_as_float(h23 << 16);
        float r3 = __uint_as_float(h23 & 0xFFFF0000u);
        hh[2*q] = h01; hh[2*q+1] = h23;
        ll[2*q]   = cvt2(v.x - r0, v.y - r1);
        ll[2*q+1] = cvt2(v.z - r2, v.w - r3);
    }
    uint4* oh = (uint4*)((unsigned*)g_xh + (fidx >> 1));
    uint4* ol = (uint4*)((unsigned*)g_xl + (fidx >> 1));
    oh[0] = make_uint4(hh[0],hh[1],hh[2],hh[3]);
    oh[1] = make_uint4(hh[4],hh[5],hh[6],hh[7]);
    ol[0] = make_uint4(ll[0],ll[1],ll[2],ll[3]);
    ol[1] = make_uint4(ll[4],ll[5],ll[6],ll[7]);
}

// ---------------- conv1: HMMA implicit GEMM, run-based staging ----------------
// grid (28 row-pairs, 64 n), 256 thr (8 warps: 4M x 2N). M=128(112 used), K'=336 (3 chunks of 112), N=64.
#define C1_B1S  0        // 64 f32
#define C1_AH   1024     // 128x64 u32 = 32KB
#define C1_AL   33792
#define C1_BH   66560    // 64x64 u32 = 16KB
#define C1_BL   82944
#define C1_SMEM 99328
__global__ void __launch_bounds__(256, 2)
k_conv1(const float* __restrict__ b1) {
    extern __shared__ char smc[];
    float* b1s = (float*)(smc + C1_B1S);
    int pr = blockIdx.x, n = blockIdx.y;
    int tid = threadIdx.x, wid = tid >> 5, lane = tid & 31;
    int g = lane >> 2, t = lane & 3;
    int wm = wid >> 1, wn = wid & 1;
    int rowblk = wm*32, colblk = wn*32;

    if (tid < 64) b1s[tid] = b1[tid];

    float acc[2][4][4];
    #pragma unroll
    for (int mi = 0; mi < 2; mi++)
        #pragma unroll
        for (int nj = 0; nj < 4; nj++)
            #pragma unroll
            for (int q = 0; q < 4; q++) acc[mi][nj][q] = 0.0f;

    for (int c = 0; c < 3; c++) {
        __syncthreads();
        // ---- stage A: items = (row, icL, kh); each item = 8 bf16 (kw 0..6 + pad) ----
        #pragma unroll 1
        for (int j = 0; j < 7; j++) {
            int it = tid + 256*j;            // [0, 1792)
            int row = it & 127;
            int icL = (it >> 7) & 1;
            int kh  = it >> 8;               // 0..6
            unsigned r0=0,r1=0,r2=0,r3=0, s0=0,s1=0,s2=0,s3=0;
            if (row < 112) {
                int hi56 = (row >= 56);
                int oy = pr*2 + hi56;
                int ox = row - (hi56 ? 56 : 0);
                int iy = 4*oy - 3 + kh;
                if (iy >= 0) {
                    int ic = c*2 + icL;
                    size_t base = (size_t)n*301056 + (size_t)(ic*224 + iy)*224;
                    if (ox > 0) {
                        const uint2* ph = (const uint2*)(g_xh + base + 4*ox - 4);
                        const uint2* pl = (const uint2*)(g_xl + base + 4*ox - 4);
                        uint2 a = ph[0], bq = ph[1];
                        uint2 e = pl[0], f = pl[1];
                        r0 = __funnelshift_r(a.x, a.y, 16);
                        r1 = __funnelshift_r(a.y, bq.x, 16);
                        r2 = __funnelshift_r(bq.x, bq.y, 16);
                        r3 = bq.y >> 16;
                        s0 = __funnelshift_r(e.x, e.y, 16);
                        s1 = __funnelshift_r(e.y, f.x, 16);
                        s2 = __funnelshift_r(f.x, f.y, 16);
                        s3 = f.y >> 16;
                    } else {
                        uint2 a = *(const uint2*)(g_xh + base);   // ix 0..3 -> kw 3..6
                        uint2 e = *(const uint2*)(g_xl + base);
                        r1 = (a.x & 0xFFFFu) << 16;
                        r2 = __funnelshift_r(a.x, a.y, 16);
                        r3 = a.y >> 16;
                        s1 = (e.x & 0xFFFFu) << 16;
                        s2 = __funnelshift_r(e.x, e.y, 16);
                        s3 = e.y >> 16;
                    }
                }
            }
            int kp0 = icL*28 + kh*4;
            unsigned dofs = (unsigned)(row*256 + (((kp0>>2) ^ (row & 7)) << 4));
            *(uint4*)(smc + C1_AH + dofs) = make_uint4(r0,r1,r2,r3);
            *(uint4*)(smc + C1_AL + dofs) = make_uint4(s0,s1,s2,s3);
        }
        // ---- stage B: 64 oc x 14 uint4 per array ----
        #pragma unroll 1
        for (int e = tid; e < 1792; e += 256) {
            int arr = (e >= 896);
            int e2 = arr ? e - 896 : e;
            int oc = e2 / 14, q = e2 - oc*14;
            const unsigned* src = (arr ? (const unsigned*)g_wn1l : (const unsigned*)g_wn1h)
                                  + oc*168 + c*56 + q*4;
            uint4 v = *(const uint4*)src;
            char* dst = smc + (arr ? C1_BL : C1_BH) + oc*256 + ((q ^ (oc & 7)) << 4);
            *(uint4*)dst = v;
        }
        __syncthreads();

        #pragma unroll
        for (int ks = 0; ks < 7; ks++) {
            int kpb = ks*8;
            unsigned ah[2][4], al[2][4];
            #pragma unroll
            for (int mi = 0; mi < 2; mi++) {
                int row = rowblk + mi*16 + g;
                ah[mi][0] = *(const unsigned*)(smc + C1_AH + swa64(row,     kpb + t));
                ah[mi][1] = *(const unsigned*)(smc + C1_AH + swa64(row + 8, kpb + t));
                ah[mi][2] = *(const unsigned*)(smc + C1_AH + swa64(row,     kpb + t + 4));
                ah[mi][3] = *(const unsigned*)(smc + C1_AH + swa64(row + 8, kpb + t + 4));
                al[mi][0] = *(const unsigned*)(smc + C1_AL + swa64(row,     kpb + t));
                al[mi][1] = *(const unsigned*)(smc + C1_AL + swa64(row + 8, kpb + t));
                al[mi][2] = *(const unsigned*)(smc + C1_AL + swa64(row,     kpb + t + 4));
                al[mi][3] = *(const unsigned*)(smc + C1_AL + swa64(row + 8, kpb + t + 4));
            }
            #pragma unroll
            for (int nj = 0; nj < 4; nj++) {
                int oc = colblk + nj*8 + g;
                unsigned bh[2], bl[2];
                bh[0] = *(const unsigned*)(smc + C1_BH + swa64(oc, kpb + t));
                bh[1] = *(const unsigned*)(smc + C1_BH + swa64(oc, kpb + t + 4));
                bl[0] = *(const unsigned*)(smc + C1_BL + swa64(oc, kpb + t));
                bl[1] = *(const unsigned*)(smc + C1_BL + swa64(oc, kpb + t + 4));
                #pragma unroll
                for (int mi = 0; mi < 2; mi++) {
                    mma_bf16(acc[mi][nj], ah[mi], bh);
                    mma_bf16(acc[mi][nj], ah[mi], bl);
                    mma_bf16(acc[mi][nj], al[mi], bh);
                }
            }
        }
    }

    // epilogue: bias + relu + split -> channels-last bf16 hi/lo
    #pragma unroll
    for (int mi = 0; mi < 2; mi++) {
        #pragma unroll
        for (int nj = 0; nj < 4; nj++) {
            int cc = colblk + nj*8 + 2*t;
            float bb0 = b1s[cc], bb1 = b1s[cc + 1];
            #pragma unroll
            for (int rh = 0; rh < 2; rh++) {
                int s = rowblk + mi*16 + g + rh*8;
                if (s < 112) {
                    float v0 = fmaxf(acc[mi][nj][rh*2]     + bb0, 0.0f);
                    float v1 = fmaxf(acc[mi][nj][rh*2 + 1] + bb1, 0.0f);
                    int hi56 = (s >= 56);
                    int oy = pr*2 + hi56, ox = s - (hi56 ? 56 : 0);
                    size_t ob = ((size_t)(n*56 + oy)*56 + ox)*64 + cc;
                    __nv_bfloat16 h0, l0, h1, l1;
                    split_bf16(v0, h0, l0); split_bf16(v1, h1, l1);
                    *(unsigned*)(g_c1h + ob) = pack2(h0, h1);
                    *(unsigned*)(g_c1l + ob) = pack2(l0, l1);
                }
            }
        }
    }
}

// ---------------- conv2: HMMA, 9 shifted GEMMs + fused pool ----------------
// grid (7 rowgroups, 64 n, 2 oc-halves), 256 thr (8 warps: 4M x 2N).
// M=128(112 used: 4 rows x 28), K=64 per shift x 9 shifts, N=128 (this block's half).
#define C2_B2S  0
#define C2_RED  1024
#define C2_AH   4096
#define C2_AL   20480
#define C2_BH   36864
#define C2_BL   53248
#define C2_SMEM 69632
__global__ void __launch_bounds__(256, 2)
k_conv2(const float* __restrict__ b2) {
    extern __shared__ char smc[];
    float* b2s = (float*)(smc + C2_B2S);
    float* red = (float*)(smc + C2_RED);
    int rg = blockIdx.x, n = blockIdx.y, half = blockIdx.z;
    int tid = threadIdx.x, wid = tid >> 5, lane = tid & 31;
    int g = lane >> 2, t = lane & 3;
    int wm = wid >> 1, wn = wid & 1;
    int rowblk = wm*32, colblk = wn*64;

    if (tid < 128) b2s[tid] = b2[half*128 + tid];

    float acc[2][8][4];
    #pragma unroll
    for (int mi = 0; mi < 2; mi++)
        #pragma unroll
        for (int nj = 0; nj < 8; nj++)
            #pragma unroll
            for (int q = 0; q < 4; q++) acc[mi][nj][q] = 0.0f;

    for (int s = 0; s < 9; s++) {
        int kh = s / 3, kw = s - kh*3;
        __syncthreads();
        // stage A: uint4 items (row, q); 128 rows x 8 q x 2 arrays = 2048 items
        #pragma unroll 1
        for (int e = tid; e < 2048; e += 256) {
            int arr = e >> 10;
            int idx = e & 1023;
            int row = idx >> 3, q = idx & 7;
            uint4 v = make_uint4(0u,0u,0u,0u);
            if (row < 112) {
                int oy = rg*4 + row / 28, ox = row % 28;
                int iy = 2*oy - 1 + kh, ix = 2*ox - 1 + kw;
                if ((unsigned)iy < 56u && (unsigned)ix < 56u) {
                    const __nv_bfloat16* src = (arr ? g_c1l : g_c1h)
                        + ((size_t)(n*56 + iy)*56 + ix)*64 + q*8;
                    v = *(const uint4*)src;
                }
            }
            char* dst = smc + (arr ? C2_AL : C2_AH) + row*128 + ((q ^ (row & 7)) << 4);
            *(uint4*)dst = v;
        }
        // stage B: uint4 items (oc, q); 128 oc x 8 q x 2 arrays
        #pragma unroll 1
        for (int e = tid; e < 2048; e += 256) {
            int arr = e >> 10;
            int idx = e & 1023;
            int oc = idx >> 3, q = idx & 7;
            const __nv_bfloat16* src = (arr ? g_wb2l : g_wb2h)
                + ((size_t)(s*256 + half*128 + oc))*64 + q*8;
            uint4 v = *(const uint4*)src;
            char* dst = smc + (arr ? C2_BL : C2_BH) + oc*128 + ((q ^ (oc & 7)) << 4);
            *(uint4*)dst = v;
        }
        __syncthreads();

        #pragma unroll
        for (int ks = 0; ks < 4; ks++) {
            int kpb = ks*8;
            unsigned ah[2][4], al[2][4];
            #pragma unroll
            for (int mi = 0; mi < 2; mi++) {
                int row = rowblk + mi*16 + g;
                ah[mi][0] = *(const unsigned*)(smc + C2_AH + swa(row,     kpb + t));
                ah[mi][1] = *(const unsigned*)(smc + C2_AH + swa(row + 8, kpb + t));
                ah[mi][2] = *(const unsigned*)(smc + C2_AH + swa(row,     kpb + t + 4));
                ah[mi][3] = *(const unsigned*)(smc + C2_AH + swa(row + 8, kpb + t + 4));
                al[mi][0] = *(const unsigned*)(smc + C2_AL + swa(row,     kpb + t));
                al[mi][1] = *(const unsigned*)(smc + C2_AL + swa(row + 8, kpb + t));
                al[mi][2] = *(const unsigned*)(smc + C2_AL + swa(row,     kpb + t + 4));
                al[mi][3] = *(const unsigned*)(smc + C2_AL + swa(row + 8, kpb + t + 4));
            }
            #pragma unroll
            for (int nj = 0; nj < 8; nj++) {
                int oc = colblk + nj*8 + g;
                unsigned bh[2], bl[2];
                bh[0] = *(const unsigned*)(smc + C2_BH + swa(oc, kpb + t));
                bh[1] = *(const unsigned*)(smc + C2_BH + swa(oc, kpb + t + 4));
                bl[0] = *(const unsigned*)(smc + C2_BL + swa(oc, kpb + t));
                bl[1] = *(const unsigned*)(smc + C2_BL + swa(oc, kpb + t + 4));
                #pragma unroll
                for (int mi = 0; mi < 2; mi++) {
                    mma_bf16(acc[mi][nj], ah[mi], bh);
                    mma_bf16(acc[mi][nj], ah[mi], bl);
                    mma_bf16(acc[mi][nj], al[mi], bh);
                }
            }
        }
    }

    // epilogue: bias + relu + masked pool partials for this half
    __syncthreads();
    #pragma unroll
    for (int nj = 0; nj < 8; nj++) {
        int cl = colblk + nj*8 + 2*t;     // local col in this half [0,128)
        float bb0 = b2s[cl], bb1 = b2s[cl + 1];
        float p0 = 0.0f, p1 = 0.0f;
        #pragma unroll
        for (int mi = 0; mi < 2; mi++) {
            int s0 = rowblk + mi*16 + g;
            float m0 = (s0 < 112) ? 1.0f : 0.0f;
            float m1 = (s0 + 8 < 112) ? 1.0f : 0.0f;
            p0 += fmaxf(acc[mi][nj][0] + bb0, 0.0f)*m0 + fmaxf(acc[mi][nj][2] + bb0, 0.0f)*m1;
            p1 += fmaxf(acc[mi][nj][1] + bb1, 0.0f)*m0 + fmaxf(acc[mi][nj][3] + bb1, 0.0f)*m1;
        }
        p0 += __shfl_xor_sync(0xffffffffu, p0, 4);
        p0 += __shfl_xor_sync(0xffffffffu, p0, 8);
        p0 += __shfl_xor_sync(0xffffffffu, p0, 16);
        p1 += __shfl_xor_sync(0xffffffffu, p1, 4);
        p1 += __shfl_xor_sync(0xffffffffu, p1, 8);
        p1 += __shfl_xor_sync(0xffffffffu, p1, 16);
        if (g == 0) {
            red[wm*128 + cl]     = p0;
            red[wm*128 + cl + 1] = p1;
        }
    }
    __syncthreads();
    if (tid < 128) {
        float tsum = red[tid] + red[128 + tid] + red[256 + tid] + red[384 + tid];
        g_part[((size_t)n*7 + rg)*256 + half*128 + tid] = tsum;
    }
}

// ---------------- Threefry2x32 (exact JAX, partitionable) ----------------
static __device__ __forceinline__ void tf2(unsigned k0, unsigned k1, unsigned &x0, unsigned &x1) {
    unsigned ks2 = k0 ^ k1 ^ 0x1BD11BDAu;
    x0 += k0; x1 += k1;
#define TFR(r) { x0 += x1; x1 = __funnelshift_l(x1, x1, r); x1 ^= x0; }
    TFR(13) TFR(15) TFR(26) TFR(6)   x0 += k1;  x1 += ks2 + 1u;
    TFR(17) TFR(29) TFR(16) TFR(24)  x0 += ks2; x1 += k0 + 2u;
    TFR(13) TFR(15) TFR(26) TFR(6)   x0 += k0;  x1 += k1 + 3u;
    TFR(17) TFR(29) TFR(16) TFR(24)  x0 += k1;  x1 += ks2 + 4u;
    TFR(13) TFR(15) TFR(26) TFR(6)   x0 += ks2; x1 += k0 + 5u;
#undef TFR
}
static __device__ __forceinline__ float u01(unsigned bits) {
    return __uint_as_float((bits >> 9) | 0x3f800000u) - 1.0f;
}
static __device__ float erfinv_f(float x) {
    float w = -log1pf(-x*x);
    float p;
    if (w < 5.0f) {
        w -= 2.5f;
        p = 2.81022636e-08f;
        p = fmaf(p, w, 3.43273939e-07f);
        p = fmaf(p, w, -3.5233877e-06f);
        p = fmaf(p, w, -4.39150654e-06f);
        p = fmaf(p, w, 0.00021858087f);
        p = fmaf(p, w, -0.00125372503f);
        p = fmaf(p, w, -0.00417768164f);
        p = fmaf(p, w, 0.246640727f);
        p = fmaf(p, w, 1.50140941f);
    } else {
        w = sqrtf(w) - 3.0f;
        p = -0.000200214257f;
        p = fmaf(p, w, 0.000100950558f);
        p = fmaf(p, w, 0.00134934322f);
        p = fmaf(p, w, -0.00367342844f);
        p = fmaf(p, w, 0.00573950773f);
        p = fmaf(p, w, -0.0076224613f);
        p = fmaf(p, w, 0.00943887047f);
        p = fmaf(p, w, 1.00167406f);
        p = fmaf(p, w, 2.83297682f);
    }
    return p * x;
}

// ---------------- fused tail: fc + mu/kappa + vMF sample + MLP ----------------
// grid 64 (one per batch row), 512 threads
__global__ void __launch_bounds__(512)
k_tail(const float* __restrict__ Wh,  const float* __restrict__ bh,
       const float* __restrict__ Wmu, const float* __restrict__ bmu,
       const float* __restrict__ Wk,  const float* __restrict__ bk,
       const float* __restrict__ M1,  const float* __restrict__ bM1,
       const float* __restrict__ M2,  const float* __restrict__ bM2,
       const float* __restrict__ M3,  const float* __restrict__ bM3,
       const float* __restrict__ M4,  const float* __restrict__ bM4,
       float* __restrict__ out, float* __restrict__ omu, float* __restrict__ okap) {
    __shared__ float p[256];
    __shared__ float h[512];
    __shared__ float redmu[16][32];
    __shared__ float mus[32];
    __shared__ float kapsh;
    __shared__ float s_w[10];
    __shared__ int   s_a[10];
    __shared__ float zs[32];
    __shared__ float y1[512];
    __shared__ float y2[512];
    __shared__ float red3[32][8];
    __shared__ float y3[32];
    int b = blockIdx.x, tid = threadIdx.x;

    if (tid < 256) {
        float sv = 0.0f;
        const float* pp = g_part + (size_t)b*7*256 + tid;
        #pragma unroll
        for (int tt = 0; tt < 7; tt++) sv += pp[tt*256];
        p[tid] = sv * (1.0f/784.0f);
    }
    __syncthreads();
    {
        float a0 = 0.f, a1 = 0.f, a2 = 0.f, a3 = 0.f;
        #pragma unroll 4
        for (int k = 0; k < 256; k += 4) {
            a0 = fmaf(p[k],   Wh[(k)*512 + tid],   a0);
            a1 = fmaf(p[k+1], Wh[(k+1)*512 + tid], a1);
            a2 = fmaf(p[k+2], Wh[(k+2)*512 + tid], a2);
            a3 = fmaf(p[k+3], Wh[(k+3)*512 + tid], a3);
        }
        h[tid] = bh[tid] + ((a0 + a1) + (a2 + a3));
    }
    __syncthreads();
    {
        int o = tid & 31, seg = tid >> 5;
        float a = 0.f;
        #pragma unroll 4
        for (int tt = 0; tt < 32; tt++) {
            int k = seg*32 + tt;
            a = fmaf(h[k], Wmu[k*32 + o], a);
        }
        redmu[seg][o] = a;
    }
    __syncthreads();
    if (tid < 32) {
        float acc = bmu[tid];
        #pragma unroll
        for (int s2 = 0; s2 < 16; s2++) acc += redmu[s2][tid];
        float ss = acc * acc;
        #pragma unroll
        for (int of = 16; of; of >>= 1) ss += __shfl_xor_sync(0xffffffffu, ss, of);
        float m = acc / sqrtf(fmaxf(ss, 1e-24f));
        mus[tid] = m;
        if (omu) omu[b*32 + tid] = m;
    } else if (tid < 64) {
        int l = tid - 32;
        float a = 0.f;
        #pragma unroll
        for (int tt = 0; tt < 16; tt++) {
            int k = l*16 + tt;
            a = fmaf(h[k], Wk[k], a);
        }
        #pragma unroll
        for (int of = 16; of; of >>= 1) a += __shfl_xor_sync(0xffffffffu, a, of);
        if (l == 0) {
            float acc = a + bk[0];
            float sp = fmaxf(acc, 0.0f) + log1pf(expf(-fabsf(acc)));
            float kap = sp + 1.0f;
            kapsh = kap;
            if (okap) okap[b] = kap;
        }
    }
    __syncthreads();
    if (tid < 32) {
        int lane = tid;
        unsigned a0,a1,c0,c1;
        { unsigned x0=0u, x1=0u; tf2(0u,42u,x0,x1); a0=x0; a1=x1; }   // k_w
        { unsigned x0=0u, x1=1u; tf2(0u,42u,x0,x1); c0=x0; c1=x1; }   // k_v
        float kap = kapsh;
        if (lane < 10) {
            unsigned f0,f1,h0,h1;
            { unsigned x0=0u, x1=(unsigned)(2*lane);   tf2(a0,a1,x0,x1); f0=x0; f1=x1; }
            { unsigned x0=0u, x1=(unsigned)(2*lane+1); tf2(a0,a1,x0,x1); h0=x0; h1=x1; }
            unsigned bw, br;
            { unsigned x0=0u, x1=(unsigned)b; tf2(f0,f1,x0,x1); bw = x0 ^ x1; }
            { unsigned x0=0u, x1=(unsigned)b; tf2(h0,h1,x0,x1); br = x0 ^ x1; }
            float wc = 2.0f*u01(bw) - 1.0f;
            float om = fmaxf(1.0f - wc*wc, 1e-40f);
            float lp = kap*wc + 14.5f*logf(om);
            float lr = logf(u01(br) + 1e-40f);
            s_w[lane] = wc;
            s_a[lane] = (lr + kap <= lp) ? 1 : 0;
        }
        __syncwarp();
        float w = 0.0f;
        #pragma unroll
        for (int i = 9; i >= 0; i--) if (s_a[i]) w = s_w[i];
        w = fminf(fmaxf(w, -1.0f), 1.0f);

        float vj = 0.0f;
        if (lane < 31) {
            int e = b*31 + lane;
            unsigned bits;
            { unsigned x0=0u, x1=(unsigned)e; tf2(c0,c1,x0,x1); bits = x0 ^ x1; }
            float u = u01(bits);
            const float LO = -0.99999994f;
            float un = fmaxf(LO, fmaf(u, 2.0f, LO));
            vj = 1.4142135623730951f * erfinv_f(un);
        }
        float ss = vj*vj;
        #pragma unroll
        for (int o = 16; o; o >>= 1) ss += __shfl_xor_sync(0xffffffffu, ss, o);
        vj /= sqrtf(fmaxf(ss, 1e-24f));

        float st = sqrtf(fmaxf(1.0f - w*w, 1e-40f));
        float zt = (lane < 31) ? st*vj : w;

        float mub = mus[lane];
        float uj = ((lane == 31) ? 1.0f : 0.0f) - mub;
        float us = uj*uj;
        #pragma unroll
        for (int o = 16; o; o >>= 1) us += __shfl_xor_sync(0xffffffffu, us, o);
        uj /= sqrtf(fmaxf(us, 1e-24f));
        float dp = zt*uj;
        #pragma unroll
        for (int o = 16; o; o >>= 1) dp += __shfl_xor_sync(0xffffffffu, dp, o);
        zs[lane] = zt - 2.0f*dp*uj;
    }
    __syncthreads();
    {
        float acc = bM1[tid];
        #pragma unroll
        for (int k = 0; k < 32; k++) acc = fmaf(zs[k], M1[k*512 + tid], acc);
        y1[tid] = fmaxf(acc, 0.0f);
    }
    __syncthreads();
    {
        float a0 = 0.f, a1 = 0.f, a2 = 0.f, a3 = 0.f;
        #pragma unroll 4
        for (int k = 0; k < 512; k += 4) {
            a0 = fmaf(y1[k],   M2[(k)*512 + tid],   a0);
            a1 = fmaf(y1[k+1], M2[(k+1)*512 + tid], a1);
            a2 = fmaf(y1[k+2], M2[(k+2)*512 + tid], a2);
            a3 = fmaf(y1[k+3], M2[(k+3)*512 + tid], a3);
        }
        y2[tid] = fmaxf(bM2[tid] + ((a0 + a1) + (a2 + a3)), 0.0f);
    }
    __syncthreads();
    if (tid < 256) {
        int o = tid >> 3, pp = tid & 7;
        float a = 0.f;
        #pragma unroll 4
        for (int tt = 0; tt < 64; tt++) {
            int k = pp*64 + tt;
            a = fmaf(y2[k], M3[k*32 + o], a);
        }
        red3[o][pp] = a;
    }
    __syncthreads();
    if (tid < 32) {
        float a = bM3[tid];
        #pragma unroll
        for (int pp = 0; pp < 8; pp++) a += red3[tid][pp];
        y3[tid] = fmaxf(a, 0.0f);
    }
    __syncthreads();
    if (tid < 7) {
        float acc = bM4[tid];
        #pragma unroll
        for (int k = 0; k < 32; k++) acc = fmaf(y3[k], M4[k*7 + tid], acc);
        out[b*7 + tid] = acc;
    }
}

// ---------------- launch ----------------
extern "C" void kernel_launch(void* const* d_in, const int* in_sizes, int n_in,
                              void* d_out, int out_size) {
    const float* x   = (const float*)d_in[0];
    const float* W1  = (const float*)d_in[1];
    const float* b1  = (const float*)d_in[2];
    const float* W2  = (const float*)d_in[3];
    const float* b2  = (const float*)d_in[4];
    const float* Wh  = (const float*)d_in[5];
    const float* bh  = (const float*)d_in[6];
    const float* Wmu = (const float*)d_in[7];
    const float* bmu = (const float*)d_in[8];
    const float* Wk  = (const float*)d_in[9];
    const float* bk  = (const float*)d_in[10];
    const float* M1  = (const float*)d_in[11];
    const float* bM1 = (const float*)d_in[12];
    const float* M2  = (const float*)d_in[13];
    const float* bM2 = (const float*)d_in[14];
    const float* M3  = (const float*)d_in[15];
    const float* bM3 = (const float*)d_in[16];
    const float* M4  = (const float*)d_in[17];
    const float* bM4 = (const float*)d_in[18];

    float* out  = (float*)d_out;
    float* omu  = (out_size >= 2560) ? out + 448  : nullptr;   // tuple order: out, mu, kappa
    float* okap = (out_size >= 2560) ? out + 2496 : nullptr;

    cudaFuncSetAttribute(k_conv1, cudaFuncAttributeMaxDynamicSharedMemorySize, C1_SMEM);
    cudaFuncSetAttribute(k_conv2, cudaFuncAttributeMaxDynamicSharedMemorySize, C2_SMEM);

    k_prew<<<128, 256>>>(W1, W2);
    k_prex<<<4704, 256>>>(x);
    k_conv1<<<dim3(28, 64), 256, C1_SMEM>>>(b1);
    k_conv2<<<dim3(7, 64, 2), 256, C2_SMEM>>>(b2);
    k_tail<<<64, 512>>>(Wh, bh, Wmu, bmu, Wk, bk, M1, bM1, M2, bM2, M3, bM3, M4, bM4,
                        out, omu, okap);
}

// round 13
// speedup vs baseline: 3.0678x; 1.0038x over previous
#include <cuda_runtime.h>
#include <cuda_bf16.h>

// ---------------- scratch (static device globals; no allocation) ----------------
__device__ __nv_bfloat16 g_xh[64*6*224*224];   // x hi bf16 (NCHW, same indexing as x)
__device__ __nv_bfloat16 g_xl[64*6*224*224];   // x lo
__device__ __nv_bfloat16 g_c1h[64*56*56*64];   // conv1 out hi, channels-last [n][y][x][oc]
__device__ __nv_bfloat16 g_c1l[64*56*56*64];   // conv1 out lo
__device__ __nv_bfloat16 g_wn1h[64*336];       // conv1 W [oc][k'] hi, k'=ic*56+kh*8+kw (kw7 pad)
__device__ __nv_bfloat16 g_wn1l[64*336];
__device__ __nv_bfloat16 g_wb2h[9*256*64];     // conv2 W [shift][oc][ic] hi
__device__ __nv_bfloat16 g_wb2l[9*256*64];
__device__ float g_part[64*7*256];             // pooled partials [n][rowgroup][oc]

// ---------------- helpers ----------------
static __device__ __forceinline__ void split_bf16(float v, __nv_bfloat16 &hi, __nv_bfloat16 &lo){
    hi = __float2bfloat16(v);
    lo = __float2bfloat16(v - __bfloat162float(hi));
}
static __device__ __forceinline__ unsigned pack2(__nv_bfloat16 a, __nv_bfloat16 b){
    return (unsigned)__bfloat16_as_ushort(a) | ((unsigned)__bfloat16_as_ushort(b) << 16);
}
// packed f32 pair -> bf16x2: result lo = bf16(lo_from), hi = bf16(hi_from)
static __device__ __forceinline__ unsigned cvt2(float lo_from, float hi_from){
    unsigned r; asm("cvt.rn.bf16x2.f32 %0, %1, %2;" : "=r"(r) : "f"(hi_from), "f"(lo_from)); return r;
}
static __device__ __forceinline__ unsigned smem_u32(const void* p){
    unsigned a; asm("{ .reg .u64 t; cvta.to.shared.u64 t, %1; cvt.u32.u64 %0, t; }" : "=r"(a) : "l"(p));
    return a;
}
static __device__ __forceinline__ void ldsm4(unsigned* r, unsigned addr){
    asm volatile("ldmatrix.sync.aligned.m8n8.x4.shared.b16 {%0,%1,%2,%3}, [%4];"
        : "=r"(r[0]), "=r"(r[1]), "=r"(r[2]), "=r"(r[3]) : "r"(addr));
}
static __device__ __forceinline__ void mma_bf16(float* d, const unsigned* a, const unsigned* b){
    asm volatile("mma.sync.aligned.m16n8k16.row.col.f32.bf16.bf16.f32 "
        "{%0,%1,%2,%3}, {%4,%5,%6,%7}, {%8,%9}, {%0,%1,%2,%3};"
        : "+f"(d[0]), "+f"(d[1]), "+f"(d[2]), "+f"(d[3])
        : "r"(a[0]), "r"(a[1]), "r"(a[2]), "r"(a[3]), "r"(b[0]), "r"(b[1]));
}

// ---------------- prep: weights -> bf16 hi/lo ----------------
__global__ void k_prew(const float* __restrict__ W1, const float* __restrict__ W2) {
    int stride = gridDim.x * blockDim.x;
    int i0 = blockIdx.x * blockDim.x + threadIdx.x;
    for (int i = i0; i < 64*336; i += stride) {
        int oc = i / 336, kq = i - oc*336;
        int ic = kq / 56, r = kq - ic*56, kh = r >> 3, kw = r & 7;
        float v = (kw < 7) ? W1[oc*294 + ic*49 + kh*7 + kw] : 0.0f;
        __nv_bfloat16 hi, lo; split_bf16(v, hi, lo);
        g_wn1h[i] = hi; g_wn1l[i] = lo;
    }
    for (int i = i0; i < 9*256*64; i += stride) {
        int ic = i & 63, oc = (i >> 6) & 255, s = i >> 14;
        int kh = s / 3, kw = s - kh*3;
        float v = W2[oc*576 + ic*9 + kh*3 + kw];
        __nv_bfloat16 hi, lo; split_bf16(v, hi, lo);
        g_wb2h[i] = hi; g_wb2l[i] = lo;
    }
}

// ---------------- prex: x -> bf16 hi/lo (16 floats/thread) ----------------
__global__ void __launch_bounds__(256) k_prex(const float* __restrict__ x) {
    size_t fidx = ((size_t)blockIdx.x*256 + threadIdx.x) * 16;
    const float4* xv = (const float4*)(x + fidx);
    unsigned hh[8], ll[8];
    #pragma unroll
    for (int q = 0; q < 4; q++) {
        float4 v = xv[q];
        unsigned h01 = cvt2(v.x, v.y);
        unsigned h23 = cvt2(v.z, v.w);
        float r0 = __uint_as_float(h01 << 16);
        float r1 = __uint_as_float(h01 & 0xFFFF0000u);
        float r2 = __uint_as_float(h23 << 16);
        float r3 = __uint_as_float(h23 & 0xFFFF0000u);
        hh[2*q] = h01; hh[2*q+1] = h23;
        ll[2*q]   = cvt2(v.x - r0, v.y - r1);
        ll[2*q+1] = cvt2(v.z - r2, v.w - r3);
    }
    uint4* oh = (uint4*)((unsigned*)g_xh + (fidx >> 1));
    uint4* ol = (uint4*)((unsigned*)g_xl + (fidx >> 1));
    oh[0] = make_uint4(hh[0],hh[1],hh[2],hh[3]);
    oh[1] = make_uint4(hh[4],hh[5],hh[6],hh[7]);
    ol[0] = make_uint4(ll[0],ll[1],ll[2],ll[3]);
    ol[1] = make_uint4(ll[4],ll[5],ll[6],ll[7]);
}

// ---------------- conv1: HMMA implicit GEMM, ldmatrix frags ----------------
// grid (28 row-pairs, 64 n), 256 thr (8 warps: 4M x 2N). M=128(112 used), K'=336 (3 chunks of 112), N=64.
#define C1_B1S  0        // 64 f32
#define C1_AH   1024     // 128x64 u32 = 32KB (256B rows)
#define C1_AL   33792
#define C1_BH   66560    // 64x64 u32 = 16KB
#define C1_BL   82944
#define C1_SMEM 99328
__global__ void __launch_bounds__(256, 2)
k_conv1(const float* __restrict__ b1) {
    extern __shared__ char smc[];
    float* b1s = (float*)(smc + C1_B1S);
    int pr = blockIdx.x, n = blockIdx.y;
    int tid = threadIdx.x, wid = tid >> 5, lane = tid & 31;
    int g = lane >> 2, t = lane & 3;
    int wm = wid >> 1, wn = wid & 1;
    int rowblk = wm*32, colblk = wn*32;

    if (tid < 64) b1s[tid] = b1[tid];

    // ldmatrix per-lane address precompute
    unsigned sb = smem_u32(smc);
    int rA = rowblk + (lane & 15);
    int r7A = rA & 7;
    unsigned aAH = sb + C1_AH + rA*256;            // + mi*4096 + ((cc^r7A)<<4)
    unsigned aAL = sb + C1_AL + rA*256;
    int ccA = lane >> 4;                            // + 2ks
    int ocB = colblk + (lane & 7) + 8*(lane >> 4);  // + 16p
    int r7B = lane & 7;
    unsigned aBH = sb + C1_BH + ocB*256;            // + p*4096 + ((cc^r7B)<<4)
    unsigned aBL = sb + C1_BL + ocB*256;
    int ccB = (lane >> 3) & 1;                      // + 2ks

    float acc[2][4][4];
    #pragma unroll
    for (int mi = 0; mi < 2; mi++)
        #pragma unroll
        for (int nj = 0; nj < 4; nj++)
            #pragma unroll
            for (int q = 0; q < 4; q++) acc[mi][nj][q] = 0.0f;

    for (int c = 0; c < 3; c++) {
        __syncthreads();
        // ---- stage A: items = (row, icL, kh); each item = 8 bf16 (kw 0..6 + pad) ----
        #pragma unroll 1
        for (int j = 0; j < 7; j++) {
            int it = tid + 256*j;            // [0, 1792)
            int row = it & 127;
            int icL = (it >> 7) & 1;
            int kh  = it >> 8;               // 0..6
            unsigned r0=0,r1=0,r2=0,r3=0, s0=0,s1=0,s2=0,s3=0;
            if (row < 112) {
                int hi56 = (row >= 56);
                int oy = pr*2 + hi56;
                int ox = row - (hi56 ? 56 : 0);
                int iy = 4*oy - 3 + kh;
                if (iy >= 0) {
                    int ic = c*2 + icL;
                    size_t base = (size_t)n*301056 + (size_t)(ic*224 + iy)*224;
                    if (ox > 0) {
                        const uint2* ph = (const uint2*)(g_xh + base + 4*ox - 4);
                        const uint2* pl = (const uint2*)(g_xl + base + 4*ox - 4);
                        uint2 a = ph[0], bq = ph[1];
                        uint2 e = pl[0], f = pl[1];
                        r0 = __funnelshift_r(a.x, a.y, 16);
                        r1 = __funnelshift_r(a.y, bq.x, 16);
                        r2 = __funnelshift_r(bq.x, bq.y, 16);
                        r3 = bq.y >> 16;
                        s0 = __funnelshift_r(e.x, e.y, 16);
                        s1 = __funnelshift_r(e.y, f.x, 16);
                        s2 = __funnelshift_r(f.x, f.y, 16);
                        s3 = f.y >> 16;
                    } else {
                        uint2 a = *(const uint2*)(g_xh + base);   // ix 0..3 -> kw 3..6
                        uint2 e = *(const uint2*)(g_xl + base);
                        r1 = (a.x & 0xFFFFu) << 16;
                        r2 = __funnelshift_r(a.x, a.y, 16);
                        r3 = a.y >> 16;
                        s1 = (e.x & 0xFFFFu) << 16;
                        s2 = __funnelshift_r(e.x, e.y, 16);
                        s3 = e.y >> 16;
                    }
                }
            }
            int kp0 = icL*28 + kh*4;
            unsigned dofs = (unsigned)(row*256 + (((kp0>>2) ^ (row & 7)) << 4));
            *(uint4*)(smc + C1_AH + dofs) = make_uint4(r0,r1,r2,r3);
            *(uint4*)(smc + C1_AL + dofs) = make_uint4(s0,s1,s2,s3);
        }
        // ---- stage B: 64 oc x 14 uint4 per array ----
        #pragma unroll 1
        for (int e = tid; e < 1792; e += 256) {
            int arr = (e >= 896);
            int e2 = arr ? e - 896 : e;
            int oc = e2 / 14, q = e2 - oc*14;
            const unsigned* src = (arr ? (const unsigned*)g_wn1l : (const unsigned*)g_wn1h)
                                  + oc*168 + c*56 + q*4;
            uint4 v = *(const uint4*)src;
            char* dst = smc + (arr ? C1_BL : C1_BH) + oc*256 + ((q ^ (oc & 7)) << 4);
            *(uint4*)dst = v;
        }
        __syncthreads();

        #pragma unroll
        for (int ks = 0; ks < 7; ks++) {
            unsigned offA = (unsigned)(((2*ks + ccA) ^ r7A) << 4);
            unsigned offB = (unsigned)(((2*ks + ccB) ^ r7B) << 4);
            unsigned ah0[4], ah1[4], al0[4], al1[4], bt[4];
            ldsm4(ah0, aAH + offA);
            ldsm4(ah1, aAH + 4096 + offA);
            #pragma unroll
            for (int p = 0; p < 2; p++) {        // ah . bh
                ldsm4(bt, aBH + p*4096 + offB);
                mma_bf16(acc[0][2*p],   ah0, bt);
                mma_bf16(acc[1][2*p],   ah1, bt);
                mma_bf16(acc[0][2*p+1], ah0, bt+2);
                mma_bf16(acc[1][2*p+1], ah1, bt+2);
            }
            #pragma unroll
            for (int p = 0; p < 2; p++) {        // ah . bl
                ldsm4(bt, aBL + p*4096 + offB);
                mma_bf16(acc[0][2*p],   ah0, bt);
                mma_bf16(acc[1][2*p],   ah1, bt);
                mma_bf16(acc[0][2*p+1], ah0, bt+2);
                mma_bf16(acc[1][2*p+1], ah1, bt+2);
            }
            ldsm4(al0, aAL + offA);
            ldsm4(al1, aAL + 4096 + offA);
            #pragma unroll
            for (int p = 0; p < 2; p++) {        // al . bh
                ldsm4(bt, aBH + p*4096 + offB);
                mma_bf16(acc[0][2*p],   al0, bt);
                mma_bf16(acc[1][2*p],   al1, bt);
                mma_bf16(acc[0][2*p+1], al0, bt+2);
                mma_bf16(acc[1][2*p+1], al1, bt+2);
            }
        }
    }

    // epilogue: bias + relu + split -> channels-last bf16 hi/lo
    #pragma unroll
    for (int mi = 0; mi < 2; mi++) {
        #pragma unroll
        for (int nj = 0; nj < 4; nj++) {
            int cc = colblk + nj*8 + 2*t;
            float bb0 = b1s[cc], bb1 = b1s[cc + 1];
            #pragma unroll
            for (int rh = 0; rh < 2; rh++) {
                int s = rowblk + mi*16 + g + rh*8;
                if (s < 112) {
                    float v0 = fmaxf(acc[mi][nj][rh*2]     + bb0, 0.0f);
                    float v1 = fmaxf(acc[mi][nj][rh*2 + 1] + bb1, 0.0f);
                    int hi56 = (s >= 56);
                    int oy = pr*2 + hi56, ox = s - (hi56 ? 56 : 0);
                    size_t ob = ((size_t)(n*56 + oy)*56 + ox)*64 + cc;
                    __nv_bfloat16 h0, l0, h1, l1;
                    split_bf16(v0, h0, l0); split_bf16(v1, h1, l1);
                    *(unsigned*)(g_c1h + ob) = pack2(h0, h1);
                    *(unsigned*)(g_c1l + ob) = pack2(l0, l1);
                }
            }
        }
    }
}

// ---------------- conv2: HMMA, 9 shifted GEMMs + fused pool, ldmatrix frags ----------------
// grid (7 rowgroups, 64 n, 2 oc-halves), 256 thr (8 warps: 4M x 2N).
// M=128(112 used: 4 rows x 28), K=64 per shift x 9 shifts, N=128 (this block's half).
#define C2_B2S  0
#define C2_RED  1024
#define C2_AH   4096
#define C2_AL   20480
#define C2_BH   36864
#define C2_BL   53248
#define C2_SMEM 69632
__global__ void __launch_bounds__(256, 2)
k_conv2(const float* __restrict__ b2) {
    extern __shared__ char smc[];
    float* b2s = (float*)(smc + C2_B2S);
    float* red = (float*)(smc + C2_RED);
    int rg = blockIdx.x, n = blockIdx.y, half = blockIdx.z;
    int tid = threadIdx.x, wid = tid >> 5, lane = tid & 31;
    int g = lane >> 2, t = lane & 3;
    int wm = wid >> 1, wn = wid & 1;
    int rowblk = wm*32, colblk = wn*64;

    if (tid < 128) b2s[tid] = b2[half*128 + tid];

    // ldmatrix per-lane address precompute (128B rows)
    unsigned sb = smem_u32(smc);
    int rA = rowblk + (lane & 15);
    int r7A = rA & 7;
    unsigned aAH = sb + C2_AH + rA*128;            // + mi*2048 + ((cc^r7A)<<4)
    unsigned aAL = sb + C2_AL + rA*128;
    int ccA = lane >> 4;
    int ocB = colblk + (lane & 7) + 8*(lane >> 4); // + 16p
    int r7B = lane & 7;
    unsigned aBH = sb + C2_BH + ocB*128;
    unsigned aBL = sb + C2_BL + ocB*128;
    int ccB = (lane >> 3) & 1;

    float acc[2][8][4];
    #pragma unroll
    for (int mi = 0; mi < 2; mi++)
        #pragma unroll
        for (int nj = 0; nj < 8; nj++)
            #pragma unroll
            for (int q = 0; q < 4; q++) acc[mi][nj][q] = 0.0f;

    for (int s = 0; s < 9; s++) {
        int kh = s / 3, kw = s - kh*3;
        __syncthreads();
        // stage A: uint4 items (row, q); 128 rows x 8 q x 2 arrays = 2048 items
        #pragma unroll 1
        for (int e = tid; e < 2048; e += 256) {
            int arr = e >> 10;
            int idx = e & 1023;
            int row = idx >> 3, q = idx & 7;
            uint4 v = make_uint4(0u,0u,0u,0u);
            if (row < 112) {
                int oy = rg*4 + row / 28, ox = row % 28;
                int iy = 2*oy - 1 + kh, ix = 2*ox - 1 + kw;
                if ((unsigned)iy < 56u && (unsigned)ix < 56u) {
                    const __nv_bfloat16* src = (arr ? g_c1l : g_c1h)
                        + ((size_t)(n*56 + iy)*56 + ix)*64 + q*8;
                    v = *(const uint4*)src;
                }
            }
            char* dst = smc + (arr ? C2_AL : C2_AH) + row*128 + ((q ^ (row & 7)) << 4);
            *(uint4*)dst = v;
        }
        // stage B: uint4 items (oc, q); 128 oc x 8 q x 2 arrays
        #pragma unroll 1
        for (int e = tid; e < 2048; e += 256) {
            int arr = e >> 10;
            int idx = e & 1023;
            int oc = idx >> 3, q = idx & 7;
            const __nv_bfloat16* src = (arr ? g_wb2l : g_wb2h)
                + ((size_t)(s*256 + half*128 + oc))*64 + q*8;
            uint4 v = *(const uint4*)src;
            char* dst = smc + (arr ? C2_BL : C2_BH) + oc*128 + ((q ^ (oc & 7)) << 4);
            *(uint4*)dst = v;
        }
        __syncthreads();

        #pragma unroll
        for (int ks = 0; ks < 4; ks++) {
            unsigned offA = (unsigned)(((2*ks + ccA) ^ r7A) << 4);
            unsigned offB = (unsigned)(((2*ks + ccB) ^ r7B) << 4);
            unsigned ah0[4], ah1[4], al0[4], al1[4], bt[4];
            ldsm4(ah0, aAH + offA);
            ldsm4(ah1, aAH + 2048 + offA);
            #pragma unroll
            for (int p = 0; p < 4; p++) {        // ah . bh
                ldsm4(bt, aBH + p*2048 + offB);
                mma_bf16(acc[0][2*p],   ah0, bt);
                mma_bf16(acc[1][2*p],   ah1, bt);
                mma_bf16(acc[0][2*p+1], ah0, bt+2);
                mma_bf16(acc[1][2*p+1], ah1, bt+2);
            }
            #pragma unroll
            for (int p = 0; p < 4; p++) {        // ah . bl
                ldsm4(bt, aBL + p*2048 + offB);
                mma_bf16(acc[0][2*p],   ah0, bt);
                mma_bf16(acc[1][2*p],   ah1, bt);
                mma_bf16(acc[0][2*p+1], ah0, bt+2);
                mma_bf16(acc[1][2*p+1], ah1, bt+2);
            }
            ldsm4(al0, aAL + offA);
            ldsm4(al1, aAL + 2048 + offA);
            #pragma unroll
            for (int p = 0; p < 4; p++) {        // al . bh
                ldsm4(bt, aBH + p*2048 + offB);
                mma_bf16(acc[0][2*p],   al0, bt);
                mma_bf16(acc[1][2*p],   al1, bt);
                mma_bf16(acc[0][2*p+1], al0, bt+2);
                mma_bf16(acc[1][2*p+1], al1, bt+2);
            }
        }
    }

    // epilogue: bias + relu + masked pool partials for this half
    __syncthreads();
    #pragma unroll
    for (int nj = 0; nj < 8; nj++) {
        int cl = colblk + nj*8 + 2*t;     // local col in this half [0,128)
        float bb0 = b2s[cl], bb1 = b2s[cl + 1];
        float p0 = 0.0f, p1 = 0.0f;
        #pragma unroll
        for (int mi = 0; mi < 2; mi++) {
            int s0 = rowblk + mi*16 + g;
            float m0 = (s0 < 112) ? 1.0f : 0.0f;
            float m1 = (s0 + 8 < 112) ? 1.0f : 0.0f;
            p0 += fmaxf(acc[mi][nj][0] + bb0, 0.0f)*m0 + fmaxf(acc[mi][nj][2] + bb0, 0.0f)*m1;
            p1 += fmaxf(acc[mi][nj][1] + bb1, 0.0f)*m0 + fmaxf(acc[mi][nj][3] + bb1, 0.0f)*m1;
        }
        p0 += __shfl_xor_sync(0xffffffffu, p0, 4);
        p0 += __shfl_xor_sync(0xffffffffu, p0, 8);
        p0 += __shfl_xor_sync(0xffffffffu, p0, 16);
        p1 += __shfl_xor_sync(0xffffffffu, p1, 4);
        p1 += __shfl_xor_sync(0xffffffffu, p1, 8);
        p1 += __shfl_xor_sync(0xffffffffu, p1, 16);
        if (g == 0) {
            red[wm*128 + cl]     = p0;
            red[wm*128 + cl + 1] = p1;
        }
    }
    __syncthreads();
    if (tid < 128) {
        float tsum = red[tid] + red[128 + tid] + red[256 + tid] + red[384 + tid];
        g_part[((size_t)n*7 + rg)*256 + half*128 + tid] = tsum;
    }
}

// ---------------- Threefry2x32 (exact JAX, partitionable) ----------------
static __device__ __forceinline__ void tf2(unsigned k0, unsigned k1, unsigned &x0, unsigned &x1) {
    unsigned ks2 = k0 ^ k1 ^ 0x1BD11BDAu;
    x0 += k0; x1 += k1;
#define TFR(r) { x0 += x1; x1 = __funnelshift_l(x1, x1, r); x1 ^= x0; }
    TFR(13) TFR(15) TFR(26) TFR(6)   x0 += k1;  x1 += ks2 + 1u;
    TFR(17) TFR(29) TFR(16) TFR(24)  x0 += ks2; x1 += k0 + 2u;
    TFR(13) TFR(15) TFR(26) TFR(6)   x0 += k0;  x1 += k1 + 3u;
    TFR(17) TFR(29) TFR(16) TFR(24)  x0 += k1;  x1 += ks2 + 4u;
    TFR(13) TFR(15) TFR(26) TFR(6)   x0 += ks2; x1 += k0 + 5u;
#undef TFR
}
static __device__ __forceinline__ float u01(unsigned bits) {
    return __uint_as_float((bits >> 9) | 0x3f800000u) - 1.0f;
}
static __device__ float erfinv_f(float x) {
    float w = -log1pf(-x*x);
    float p;
    if (w < 5.0f) {
        w -= 2.5f;
        p = 2.81022636e-08f;
        p = fmaf(p, w, 3.43273939e-07f);
        p = fmaf(p, w, -3.5233877e-06f);
        p = fmaf(p, w, -4.39150654e-06f);
        p = fmaf(p, w, 0.00021858087f);
        p = fmaf(p, w, -0.00125372503f);
        p = fmaf(p, w, -0.00417768164f);
        p = fmaf(p, w, 0.246640727f);
        p = fmaf(p, w, 1.50140941f);
    } else {
        w = sqrtf(w) - 3.0f;
        p = -0.000200214257f;
        p = fmaf(p, w, 0.000100950558f);
        p = fmaf(p, w, 0.00134934322f);
        p = fmaf(p, w, -0.00367342844f);
        p = fmaf(p, w, 0.00573950773f);
        p = fmaf(p, w, -0.0076224613f);
        p = fmaf(p, w, 0.00943887047f);
        p = fmaf(p, w, 1.00167406f);
        p = fmaf(p, w, 2.83297682f);
    }
    return p * x;
}

// ---------------- fused tail: fc + mu/kappa + vMF sample + MLP ----------------
// grid 64 (one per batch row), 512 threads
__global__ void __launch_bounds__(512)
k_tail(const float* __restrict__ Wh,  const float* __restrict__ bh,
       const float* __restrict__ Wmu, const float* __restrict__ bmu,
       const float* __restrict__ Wk,  const float* __restrict__ bk,
       const float* __restrict__ M1,  const float* __restrict__ bM1,
       const float* __restrict__ M2,  const float* __restrict__ bM2,
       const float* __restrict__ M3,  const float* __restrict__ bM3,
       const float* __restrict__ M4,  const float* __restrict__ bM4,
       float* __restrict__ out, float* __restrict__ omu, float* __restrict__ okap) {
    __shared__ float p[256];
    __shared__ float h[512];
    __shared__ float redmu[16][32];
    __shared__ float mus[32];
    __shared__ float kapsh;
    __shared__ float s_w[10];
    __shared__ int   s_a[10];
    __shared__ float zs[32];
    __shared__ float y1[512];
    __shared__ float y2[512];
    __shared__ float red3[32][8];
    __shared__ float y3[32];
    int b = blockIdx.x, tid = threadIdx.x;

    if (tid < 256) {
        float sv = 0.0f;
        const float* pp = g_part + (size_t)b*7*256 + tid;
        #pragma unroll
        for (int tt = 0; tt < 7; tt++) sv += pp[tt*256];
        p[tid] = sv * (1.0f/784.0f);
    }
    __syncthreads();
    {
        float a0 = 0.f, a1 = 0.f, a2 = 0.f, a3 = 0.f;
        #pragma unroll 4
        for (int k = 0; k < 256; k += 4) {
            a0 = fmaf(p[k],   Wh[(k)*512 + tid],   a0);
            a1 = fmaf(p[k+1], Wh[(k+1)*512 + tid], a1);
            a2 = fmaf(p[k+2], Wh[(k+2)*512 + tid], a2);
            a3 = fmaf(p[k+3], Wh[(k+3)*512 + tid], a3);
        }
        h[tid] = bh[tid] + ((a0 + a1) + (a2 + a3));
    }
    __syncthreads();
    {
        int o = tid & 31, seg = tid >> 5;
        float a = 0.f;
        #pragma unroll 4
        for (int tt = 0; tt < 32; tt++) {
            int k = seg*32 + tt;
            a = fmaf(h[k], Wmu[k*32 + o], a);
        }
        redmu[seg][o] = a;
    }
    __syncthreads();
    if (tid < 32) {
        float acc = bmu[tid];
        #pragma unroll
        for (int s2 = 0; s2 < 16; s2++) acc += redmu[s2][tid];
        float ss = acc * acc;
        #pragma unroll
        for (int of = 16; of; of >>= 1) ss += __shfl_xor_sync(0xffffffffu, ss, of);
        float m = acc / sqrtf(fmaxf(ss, 1e-24f));
        mus[tid] = m;
        if (omu) omu[b*32 + tid] = m;
    } else if (tid < 64) {
        int l = tid - 32;
        float a = 0.f;
        #pragma unroll
        for (int tt = 0; tt < 16; tt++) {
            int k = l*16 + tt;
            a = fmaf(h[k], Wk[k], a);
        }
        #pragma unroll
        for (int of = 16; of; of >>= 1) a += __shfl_xor_sync(0xffffffffu, a, of);
        if (l == 0) {
            float acc = a + bk[0];
            float sp = fmaxf(acc, 0.0f) + log1pf(expf(-fabsf(acc)));
            float kap = sp + 1.0f;
            kapsh = kap;
            if (okap) okap[b] = kap;
        }
    }
    __syncthreads();
    if (tid < 32) {
        int lane = tid;
        unsigned a0,a1,c0,c1;
        { unsigned x0=0u, x1=0u; tf2(0u,42u,x0,x1); a0=x0; a1=x1; }   // k_w
        { unsigned x0=0u, x1=1u; tf2(0u,42u,x0,x1); c0=x0; c1=x1; }   // k_v
        float kap = kapsh;
        if (lane < 10) {
            unsigned f0,f1,h0,h1;
            { unsigned x0=0u, x1=(unsigned)(2*lane);   tf2(a0,a1,x0,x1); f0=x0; f1=x1; }
            { unsigned x0=0u, x1=(unsigned)(2*lane+1); tf2(a0,a1,x0,x1); h0=x0; h1=x1; }
            unsigned bw, br;
            { unsigned x0=0u, x1=(unsigned)b; tf2(f0,f1,x0,x1); bw = x0 ^ x1; }
            { unsigned x0=0u, x1=(unsigned)b; tf2(h0,h1,x0,x1); br = x0 ^ x1; }
            float wc = 2.0f*u01(bw) - 1.0f;
            float om = fmaxf(1.0f - wc*wc, 1e-40f);
            float lp = kap*wc + 14.5f*logf(om);
            float lr = logf(u01(br) + 1e-40f);
            s_w[lane] = wc;
            s_a[lane] = (lr + kap <= lp) ? 1 : 0;
        }
        __syncwarp();
        float w = 0.0f;
        #pragma unroll
        for (int i = 9; i >= 0; i--) if (s_a[i]) w = s_w[i];
        w = fminf(fmaxf(w, -1.0f), 1.0f);

        float vj = 0.0f;
        if (lane < 31) {
            int e = b*31 + lane;
            unsigned bits;
            { unsigned x0=0u, x1=(unsigned)e; tf2(c0,c1,x0,x1); bits = x0 ^ x1; }
            float u = u01(bits);
            const float LO = -0.99999994f;
            float un = fmaxf(LO, fmaf(u, 2.0f, LO));
            vj = 1.4142135623730951f * erfinv_f(un);
        }
        float ss = vj*vj;
        #pragma unroll
        for (int o = 16; o; o >>= 1) ss += __shfl_xor_sync(0xffffffffu, ss, o);
        vj /= sqrtf(fmaxf(ss, 1e-24f));

        float st = sqrtf(fmaxf(1.0f - w*w, 1e-40f));
        float zt = (lane < 31) ? st*vj : w;

        float mub = mus[lane];
        float uj = ((lane == 31) ? 1.0f : 0.0f) - mub;
        float us = uj*uj;
        #pragma unroll
        for (int o = 16; o; o >>= 1) us += __shfl_xor_sync(0xffffffffu, us, o);
        uj /= sqrtf(fmaxf(us, 1e-24f));
        float dp = zt*uj;
        #pragma unroll
        for (int o = 16; o; o >>= 1) dp += __shfl_xor_sync(0xffffffffu, dp, o);
        zs[lane] = zt - 2.0f*dp*uj;
    }
    __syncthreads();
    {
        float acc = bM1[tid];
        #pragma unroll
        for (int k = 0; k < 32; k++) acc = fmaf(zs[k], M1[k*512 + tid], acc);
        y1[tid] = fmaxf(acc, 0.0f);
    }
    __syncthreads();
    {
        float a0 = 0.f, a1 = 0.f, a2 = 0.f, a3 = 0.f;
        #pragma unroll 4
        for (int k = 0; k < 512; k += 4) {
            a0 = fmaf(y1[k],   M2[(k)*512 + tid],   a0);
            a1 = fmaf(y1[k+1], M2[(k+1)*512 + tid], a1);
            a2 = fmaf(y1[k+2], M2[(k+2)*512 + tid], a2);
            a3 = fmaf(y1[k+3], M2[(k+3)*512 + tid], a3);
        }
        y2[tid] = fmaxf(bM2[tid] + ((a0 + a1) + (a2 + a3)), 0.0f);
    }
    __syncthreads();
    if (tid < 256) {
        int o = tid >> 3, pp = tid & 7;
        float a = 0.f;
        #pragma unroll 4
        for (int tt = 0; tt < 64; tt++) {
            int k = pp*64 + tt;
            a = fmaf(y2[k], M3[k*32 + o], a);
        }
        red3[o][pp] = a;
    }
    __syncthreads();
    if (tid < 32) {
        float a = bM3[tid];
        #pragma unroll
        for (int pp = 0; pp < 8; pp++) a += red3[tid][pp];
        y3[tid] = fmaxf(a, 0.0f);
    }
    __syncthreads();
    if (tid < 7) {
        float acc = bM4[tid];
        #pragma unroll
        for (int k = 0; k < 32; k++) acc = fmaf(y3[k], M4[k*7 + tid], acc);
        out[b*7 + tid] = acc;
    }
}

// ---------------- launch ----------------
extern "C" void kernel_launch(void* const* d_in, const int* in_sizes, int n_in,
                              void* d_out, int out_size) {
    const float* x   = (const float*)d_in[0];
    const float* W1  = (const float*)d_in[1];
    const float* b1  = (const float*)d_in[2];
    const float* W2  = (const float*)d_in[3];
    const float* b2  = (const float*)d_in[4];
    const float* Wh  = (const float*)d_in[5];
    const float* bh  = (const float*)d_in[6];
    const float* Wmu = (const float*)d_in[7];
    const float* bmu = (const float*)d_in[8];
    const float* Wk  = (const float*)d_in[9];
    const float* bk  = (const float*)d_in[10];
    const float* M1  = (const float*)d_in[11];
    const float* bM1 = (const float*)d_in[12];
    const float* M2  = (const float*)d_in[13];
    const float* bM2 = (const float*)d_in[14];
    const float* M3  = (const float*)d_in[15];
    const float* bM3 = (const float*)d_in[16];
    const float* M4  = (const float*)d_in[17];
    const float* bM4 = (const float*)d_in[18];

    float* out  = (float*)d_out;
    float* omu  = (out_size >= 2560) ? out + 448  : nullptr;   // tuple order: out, mu, kappa
    float* okap = (out_size >= 2560) ? out + 2496 : nullptr;

    cudaFuncSetAttribute(k_conv1, cudaFuncAttributeMaxDynamicSharedMemorySize, C1_SMEM);
    cudaFuncSetAttribute(k_conv2, cudaFuncAttributeMaxDynamicSharedMemorySize, C2_SMEM);

    k_prew<<<128, 256>>>(W1, W2);
    k_prex<<<4704, 256>>>(x);
    k_conv1<<<dim3(28, 64), 256, C1_SMEM>>>(b1);
    k_conv2<<<dim3(7, 64, 2), 256, C2_SMEM>>>(b2);
    k_tail<<<64, 512>>>(Wh, bh, Wmu, bmu, Wk, bk, M1, bM1, M2, bM2, M3, bM3, M4, bM4,
                        out, omu, okap);
}

// round 16
// speedup vs baseline: 3.3291x; 1.0852x over previous
#include <cuda_runtime.h>
#include <cuda_bf16.h>

// ---------------- scratch (static device globals; no allocation) ----------------
__device__ __nv_bfloat16 g_xh[64*6*224*224];   // x hi bf16 (NCHW, same indexing as x)
__device__ __nv_bfloat16 g_xl[64*6*224*224];   // x lo
__device__ __nv_bfloat16 g_c1h[64*56*56*64];   // conv1 out hi, channels-last [n][y][x][oc]
__device__ __nv_bfloat16 g_c1l[64*56*56*64];   // conv1 out lo
__device__ __nv_bfloat16 g_wn1h[64*336];       // conv1 W [oc][k'] hi, k'=ic*56+kh*8+kw (kw7 pad)
__device__ __nv_bfloat16 g_wn1l[64*336];
__device__ __nv_bfloat16 g_wb2h[9*256*64];     // conv2 W [shift][oc][ic] hi
__device__ __nv_bfloat16 g_wb2l[9*256*64];
__device__ float g_part[64*7*256];             // pooled partials [n][rowgroup][oc]

// ---------------- helpers ----------------
static __device__ __forceinline__ void split_bf16(float v, __nv_bfloat16 &hi, __nv_bfloat16 &lo){
    hi = __float2bfloat16(v);
    lo = __float2bfloat16(v - __bfloat162float(hi));
}
static __device__ __forceinline__ unsigned pack2(__nv_bfloat16 a, __nv_bfloat16 b){
    return (unsigned)__bfloat16_as_ushort(a) | ((unsigned)__bfloat16_as_ushort(b) << 16);
}
// packed f32 pair -> bf16x2: result lo = bf16(lo_from), hi = bf16(hi_from)
static __device__ __forceinline__ unsigned cvt2(float lo_from, float hi_from){
    unsigned r; asm("cvt.rn.bf16x2.f32 %0, %1, %2;" : "=r"(r) : "f"(hi_from), "f"(lo_from)); return r;
}
static __device__ __forceinline__ unsigned smem_u32(const void* p){
    unsigned a; asm("{ .reg .u64 t; cvta.to.shared.u64 t, %1; cvt.u32.u64 %0, t; }" : "=r"(a) : "l"(p));
    return a;
}
static __device__ __forceinline__ void ldsm4(unsigned* r, unsigned addr){
    asm volatile("ldmatrix.sync.aligned.m8n8.x4.shared.b16 {%0,%1,%2,%3}, [%4];"
        : "=r"(r[0]), "=r"(r[1]), "=r"(r[2]), "=r"(r[3]) : "r"(addr));
}
static __device__ __forceinline__ void mma_bf16(float* d, const unsigned* a, const unsigned* b){
    asm volatile("mma.sync.aligned.m16n8k16.row.col.f32.bf16.bf16.f32 "
        "{%0,%1,%2,%3}, {%4,%5,%6,%7}, {%8,%9}, {%0,%1,%2,%3};"
        : "+f"(d[0]), "+f"(d[1]), "+f"(d[2]), "+f"(d[3])
        : "r"(a[0]), "r"(a[1]), "r"(a[2]), "r"(a[3]), "r"(b[0]), "r"(b[1]));
}
static __device__ __forceinline__ void cpa16(unsigned dst, const void* src, int n){
    asm volatile("cp.async.ca.shared.global [%0], [%1], 16, %2;"
        :: "r"(dst), "l"(src), "r"(n) : "memory");
}
#define CPA_COMMIT() asm volatile("cp.async.commit_group;" ::: "memory")
#define CPA_WAIT1()  asm volatile("cp.async.wait_group 1;" ::: "memory")
#define CPA_WAIT0()  asm volatile("cp.async.wait_group 0;" ::: "memory")

// ---------------- prep: weights -> bf16 hi/lo ----------------
__global__ void k_prew(const float* __restrict__ W1, const float* __restrict__ W2) {
    int stride = gridDim.x * blockDim.x;
    int i0 = blockIdx.x * blockDim.x + threadIdx.x;
    for (int i = i0; i < 64*336; i += stride) {
        int oc = i / 336, kq = i - oc*336;
        int ic = kq / 56, r = kq - ic*56, kh = r >> 3, kw = r & 7;
        float v = (kw < 7) ? W1[oc*294 + ic*49 + kh*7 + kw] : 0.0f;
        __nv_bfloat16 hi, lo; split_bf16(v, hi, lo);
        g_wn1h[i] = hi; g_wn1l[i] = lo;
    }
    for (int i = i0; i < 9*256*64; i += stride) {
        int ic = i & 63, oc = (i >> 6) & 255, s = i >> 14;
        int kh = s / 3, kw = s - kh*3;
        float v = W2[oc*576 + ic*9 + kh*3 + kw];
        __nv_bfloat16 hi, lo; split_bf16(v, hi, lo);
        g_wb2h[i] = hi; g_wb2l[i] = lo;
    }
}

// ---------------- prex: x -> bf16 hi/lo (16 floats/thread) ----------------
__global__ void __launch_bounds__(256) k_prex(const float* __restrict__ x) {
    size_t fidx = ((size_t)blockIdx.x*256 + threadIdx.x) * 16;
    const float4* xv = (const float4*)(x + fidx);
    unsigned hh[8], ll[8];
    #pragma unroll
    for (int q = 0; q < 4; q++) {
        float4 v = xv[q];
        unsigned h01 = cvt2(v.x, v.y);
        unsigned h23 = cvt2(v.z, v.w);
        float r0 = __uint_as_float(h01 << 16);
        float r1 = __uint_as_float(h01 & 0xFFFF0000u);
        float r2 = __uint_as_float(h23 << 16);
        float r3 = __uint_as_float(h23 & 0xFFFF0000u);
        hh[2*q] = h01; hh[2*q+1] = h23;
        ll[2*q]   = cvt2(v.x - r0, v.y - r1);
        ll[2*q+1] = cvt2(v.z - r2, v.w - r3);
    }
    uint4* oh = (uint4*)((unsigned*)g_xh + (fidx >> 1));
    uint4* ol = (uint4*)((unsigned*)g_xl + (fidx >> 1));
    oh[0] = make_uint4(hh[0],hh[1],hh[2],hh[3]);
    oh[1] = make_uint4(hh[4],hh[5],hh[6],hh[7]);
    ol[0] = make_uint4(ll[0],ll[1],ll[2],ll[3]);
    ol[1] = make_uint4(ll[4],ll[5],ll[6],ll[7]);
}

// ---------------- conv1: HMMA implicit GEMM, ldmatrix frags ----------------
// grid (28 row-pairs, 64 n), 256 thr (8 warps: 4M x 2N). M=128(112 used), K'=336 (3 chunks of 112), N=64.
#define C1_B1S  0        // 64 f32
#define C1_AH   1024     // 128x64 u32 = 32KB (256B rows)
#define C1_AL   33792
#define C1_BH   66560    // 64x64 u32 = 16KB
#define C1_BL   82944
#define C1_SMEM 99328
__global__ void __launch_bounds__(256, 2)
k_conv1(const float* __restrict__ b1) {
    extern __shared__ char smc[];
    float* b1s = (float*)(smc + C1_B1S);
    int pr = blockIdx.x, n = blockIdx.y;
    int tid = threadIdx.x, wid = tid >> 5, lane = tid & 31;
    int g = lane >> 2, t = lane & 3;
    int wm = wid >> 1, wn = wid & 1;
    int rowblk = wm*32, colblk = wn*32;

    if (tid < 64) b1s[tid] = b1[tid];

    // ldmatrix per-lane address precompute
    unsigned sb = smem_u32(smc);
    int rA = rowblk + (lane & 15);
    int r7A = rA & 7;
    unsigned aAH = sb + C1_AH + rA*256;            // + mi*4096 + ((cc^r7A)<<4)
    unsigned aAL = sb + C1_AL + rA*256;
    int ccA = lane >> 4;                            // + 2ks
    int ocB = colblk + (lane & 7) + 8*(lane >> 4);  // + 16p
    int r7B = lane & 7;
    unsigned aBH = sb + C1_BH + ocB*256;            // + p*4096 + ((cc^r7B)<<4)
    unsigned aBL = sb + C1_BL + ocB*256;
    int ccB = (lane >> 3) & 1;                      // + 2ks

    float acc[2][4][4];
    #pragma unroll
    for (int mi = 0; mi < 2; mi++)
        #pragma unroll
        for (int nj = 0; nj < 4; nj++)
            #pragma unroll
            for (int q = 0; q < 4; q++) acc[mi][nj][q] = 0.0f;

    for (int c = 0; c < 3; c++) {
        __syncthreads();
        // ---- stage A: items = (row, icL, kh); each item = 8 bf16 (kw 0..6 + pad) ----
        #pragma unroll 1
        for (int j = 0; j < 7; j++) {
            int it = tid + 256*j;            // [0, 1792)
            int row = it & 127;
            int icL = (it >> 7) & 1;
            int kh  = it >> 8;               // 0..6
            unsigned r0=0,r1=0,r2=0,r3=0, s0=0,s1=0,s2=0,s3=0;
            if (row < 112) {
                int hi56 = (row >= 56);
                int oy = pr*2 + hi56;
                int ox = row - (hi56 ? 56 : 0);
                int iy = 4*oy - 3 + kh;
                if (iy >= 0) {
                    int ic = c*2 + icL;
                    size_t base = (size_t)n*301056 + (size_t)(ic*224 + iy)*224;
                    if (ox > 0) {
                        const uint2* ph = (const uint2*)(g_xh + base + 4*ox - 4);
                        const uint2* pl = (const uint2*)(g_xl + base + 4*ox - 4);
                        uint2 a = ph[0], bq = ph[1];
                        uint2 e = pl[0], f = pl[1];
                        r0 = __funnelshift_r(a.x, a.y, 16);
                        r1 = __funnelshift_r(a.y, bq.x, 16);
                        r2 = __funnelshift_r(bq.x, bq.y, 16);
                        r3 = bq.y >> 16;
                        s0 = __funnelshift_r(e.x, e.y, 16);
                        s1 = __funnelshift_r(e.y, f.x, 16);
                        s2 = __funnelshift_r(f.x, f.y, 16);
                        s3 = f.y >> 16;
                    } else {
                        uint2 a = *(const uint2*)(g_xh + base);   // ix 0..3 -> kw 3..6
                        uint2 e = *(const uint2*)(g_xl + base);
                        r1 = (a.x & 0xFFFFu) << 16;
                        r2 = __funnelshift_r(a.x, a.y, 16);
                        r3 = a.y >> 16;
                        s1 = (e.x & 0xFFFFu) << 16;
                        s2 = __funnelshift_r(e.x, e.y, 16);
                        s3 = e.y >> 16;
                    }
                }
            }
            int kp0 = icL*28 + kh*4;
            unsigned dofs = (unsigned)(row*256 + (((kp0>>2) ^ (row & 7)) << 4));
            *(uint4*)(smc + C1_AH + dofs) = make_uint4(r0,r1,r2,r3);
            *(uint4*)(smc + C1_AL + dofs) = make_uint4(s0,s1,s2,s3);
        }
        // ---- stage B: 64 oc x 14 uint4 per array ----
        #pragma unroll 1
        for (int e = tid; e < 1792; e += 256) {
            int arr = (e >= 896);
            int e2 = arr ? e - 896 : e;
            int oc = e2 / 14, q = e2 - oc*14;
            const unsigned* src = (arr ? (const unsigned*)g_wn1l : (const unsigned*)g_wn1h)
                                  + oc*168 + c*56 + q*4;
            uint4 v = *(const uint4*)src;
            char* dst = smc + (arr ? C1_BL : C1_BH) + oc*256 + ((q ^ (oc & 7)) << 4);
            *(uint4*)dst = v;
        }
        __syncthreads();

        #pragma unroll
        for (int ks = 0; ks < 7; ks++) {
            unsigned offA = (unsigned)(((2*ks + ccA) ^ r7A) << 4);
            unsigned offB = (unsigned)(((2*ks + ccB) ^ r7B) << 4);
            unsigned ah0[4], ah1[4], al0[4], al1[4], bt[4];
            ldsm4(ah0, aAH + offA);
            ldsm4(ah1, aAH + 4096 + offA);
            #pragma unroll
            for (int p = 0; p < 2; p++) {        // ah . bh
                ldsm4(bt, aBH + p*4096 + offB);
                mma_bf16(acc[0][2*p],   ah0, bt);
                mma_bf16(acc[1][2*p],   ah1, bt);
                mma_bf16(acc[0][2*p+1], ah0, bt+2);
                mma_bf16(acc[1][2*p+1], ah1, bt+2);
            }
            #pragma unroll
            for (int p = 0; p < 2; p++) {        // ah . bl
                ldsm4(bt, aBL + p*4096 + offB);
                mma_bf16(acc[0][2*p],   ah0, bt);
                mma_bf16(acc[1][2*p],   ah1, bt);
                mma_bf16(acc[0][2*p+1], ah0, bt+2);
                mma_bf16(acc[1][2*p+1], ah1, bt+2);
            }
            ldsm4(al0, aAL + offA);
            ldsm4(al1, aAL + 4096 + offA);
            #pragma unroll
            for (int p = 0; p < 2; p++) {        // al . bh
                ldsm4(bt, aBH + p*4096 + offB);
                mma_bf16(acc[0][2*p],   al0, bt);
                mma_bf16(acc[1][2*p],   al1, bt);
                mma_bf16(acc[0][2*p+1], al0, bt+2);
                mma_bf16(acc[1][2*p+1], al1, bt+2);
            }
        }
    }

    // epilogue: bias + relu + split -> channels-last bf16 hi/lo
    #pragma unroll
    for (int mi = 0; mi < 2; mi++) {
        #pragma unroll
        for (int nj = 0; nj < 4; nj++) {
            int cc = colblk + nj*8 + 2*t;
            float bb0 = b1s[cc], bb1 = b1s[cc + 1];
            #pragma unroll
            for (int rh = 0; rh < 2; rh++) {
                int s = rowblk + mi*16 + g + rh*8;
                if (s < 112) {
                    float v0 = fmaxf(acc[mi][nj][rh*2]     + bb0, 0.0f);
                    float v1 = fmaxf(acc[mi][nj][rh*2 + 1] + bb1, 0.0f);
                    int hi56 = (s >= 56);
                    int oy = pr*2 + hi56, ox = s - (hi56 ? 56 : 0);
                    size_t ob = ((size_t)(n*56 + oy)*56 + ox)*64 + cc;
                    __nv_bfloat16 h0, l0, h1, l1;
                    split_bf16(v0, h0, l0); split_bf16(v1, h1, l1);
                    *(unsigned*)(g_c1h + ob) = pack2(h0, h1);
                    *(unsigned*)(g_c1l + ob) = pack2(l0, l1);
                }
            }
        }
    }
}

// ---------------- conv2: HMMA, cp.async double-buffered pipeline ----------------
// grid (7 rowgroups, 64 n, 2 oc-halves), 256 thr (8 warps: 4M x 2N).
// M=128(112 used: 4 rows x 28), K=64 per shift x 9 shifts, N=128 (this block's half).
// smem: 2 buffers x (AH 16K | AL 16K | BH 16K | BL 16K) = 128KB, 1 block/SM.
#define C2_B2S   0
#define C2_RED   1024
#define C2_BUF0  4096
#define C2_BUFSZ 65536
#define C2_SMEM  (4096 + 2*65536)
__global__ void __launch_bounds__(256, 1)
k_conv2(const float* __restrict__ b2) {
    extern __shared__ char smc[];
    float* b2s = (float*)(smc + C2_B2S);
    float* red = (float*)(smc + C2_RED);
    int rg = blockIdx.x, n = blockIdx.y, half = blockIdx.z;
    int tid = threadIdx.x, wid = tid >> 5, lane = tid & 31;
    int g = lane >> 2, t = lane & 3;
    int wm = wid >> 1, wn = wid & 1;
    int rowblk = wm*32, colblk = wn*64;
    unsigned sb = smem_u32(smc);

    if (tid < 128) b2s[tid] = b2[half*128 + tid];

    // ldmatrix per-lane offsets (within a buffer; 128B rows)
    int rA = rowblk + (lane & 15);
    int r7A = rA & 7;
    unsigned oA = rA*128u;                          // AH at +0, AL at +16384
    int ccA = lane >> 4;
    int ocB = colblk + (lane & 7) + 8*(lane >> 4);
    int r7B = lane & 7;
    unsigned oB = 32768u + ocB*128u;                // BH at +32768, BL at +49152
    int ccB = (lane >> 3) & 1;

    float acc[2][8][4];
    #pragma unroll
    for (int mi = 0; mi < 2; mi++)
        #pragma unroll
        for (int nj = 0; nj < 8; nj++)
            #pragma unroll
            for (int q = 0; q < 4; q++) acc[mi][nj][q] = 0.0f;

    // ---- staging (cp.async) for shift ss into buffer bb ----
    auto stage = [&](int ss, unsigned bb) {
        int kh = ss / 3, kw = ss - kh*3;
        #pragma unroll 1
        for (int e = tid; e < 2048; e += 256) {     // A: hi/lo x 128 rows x 8 q
            int arr = e >> 10, idx = e & 1023;
            int row = idx >> 3, q = idx & 7;
            const __nv_bfloat16* base = arr ? g_c1l : g_c1h;
            size_t si = 0; int nb = 0;
            if (row < 112) {
                int oy = rg*4 + row / 28, ox = row % 28;
                int iy = 2*oy - 1 + kh, ix = 2*ox - 1 + kw;
                if ((unsigned)iy < 56u && (unsigned)ix < 56u) {
                    si = ((size_t)(n*56 + iy)*56 + ix)*64 + q*8;
                    nb = 16;
                }
            }
            unsigned dst = sb + bb + (arr ? 16384u : 0u) + row*128u + ((unsigned)(q ^ (row & 7)) << 4);
            cpa16(dst, base + si, nb);
        }
        #pragma unroll 1
        for (int e = tid; e < 2048; e += 256) {     // B: hi/lo x 128 oc x 8 q
            int arr = e >> 10, idx = e & 1023;
            int oc = idx >> 3, q = idx & 7;
            const __nv_bfloat16* src = (arr ? g_wb2l : g_wb2h)
                + ((size_t)(ss*256 + half*128 + oc))*64 + q*8;
            unsigned dst = sb + bb + 32768u + (arr ? 16384u : 0u) + oc*128u + ((unsigned)(q ^ (oc & 7)) << 4);
            cpa16(dst, src, 16);
        }
        CPA_COMMIT();
    };

    stage(0, C2_BUF0);
    for (int s = 0; s < 9; s++) {
        __syncthreads();                            // all warps done with MMA s-1
        if (s + 1 < 9) {
            stage(s + 1, C2_BUF0 + (unsigned)((s + 1) & 1)*C2_BUFSZ);
            CPA_WAIT1();                            // group s landed
        } else {
            CPA_WAIT0();
        }
        __syncthreads();                            // staged data visible to all warps

        unsigned bb = C2_BUF0 + (unsigned)(s & 1)*C2_BUFSZ;
        unsigned aAH = sb + bb + oA, aAL = aAH + 16384u;
        unsigned aBH = sb + bb + oB, aBL = aBH + 16384u;
        #pragma unroll
        for (int ks = 0; ks < 4; ks++) {
            unsigned offA = (unsigned)(((2*ks + ccA) ^ r7A) << 4);
            unsigned offB = (unsigned)(((2*ks + ccB) ^ r7B) << 4);
            unsigned ah0[4], ah1[4], al0[4], al1[4], bt[4];
            ldsm4(ah0, aAH + offA);
            ldsm4(ah1, aAH + 2048 + offA);
            #pragma unroll
            for (int p = 0; p < 4; p++) {        // ah . bh
                ldsm4(bt, aBH + p*2048 + offB);
                mma_bf16(acc[0][2*p],   ah0, bt);
                mma_bf16(acc[1][2*p],   ah1, bt);
                mma_bf16(acc[0][2*p+1], ah0, bt+2);
                mma_bf16(acc[1][2*p+1], ah1, bt+2);
            }
            #pragma unroll
            for (int p = 0; p < 4; p++) {        // ah . bl
                ldsm4(bt, aBL + p*2048 + offB);
                mma_bf16(acc[0][2*p],   ah0, bt);
                mma_bf16(acc[1][2*p],   ah1, bt);
                mma_bf16(acc[0][2*p+1], ah0, bt+2);
                mma_bf16(acc[1][2*p+1], ah1, bt+2);
            }
            ldsm4(al0, aAL + offA);
            ldsm4(al1, aAL + 2048 + offA);
            #pragma unroll
            for (int p = 0; p < 4; p++) {        // al . bh
                ldsm4(bt, aBH + p*2048 + offB);
                mma_bf16(acc[0][2*p],   al0, bt);
                mma_bf16(acc[1][2*p],   al1, bt);
                mma_bf16(acc[0][2*p+1], al0, bt+2);
                mma_bf16(acc[1][2*p+1], al1, bt+2);
            }
        }
    }

    // epilogue: bias + relu + masked pool partials for this half
    __syncthreads();
    #pragma unroll
    for (int nj = 0; nj < 8; nj++) {
        int cl = colblk + nj*8 + 2*t;     // local col in this half [0,128)
        float bb0 = b2s[cl], bb1 = b2s[cl + 1];
        float p0 = 0.0f, p1 = 0.0f;
        #pragma unroll
        for (int mi = 0; mi < 2; mi++) {
            int s0 = rowblk + mi*16 + g;
            float m0 = (s0 < 112) ? 1.0f : 0.0f;
            float m1 = (s0 + 8 < 112) ? 1.0f : 0.0f;
            p0 += fmaxf(acc[mi][nj][0] + bb0, 0.0f)*m0 + fmaxf(acc[mi][nj][2] + bb0, 0.0f)*m1;
            p1 += fmaxf(acc[mi][nj][1] + bb1, 0.0f)*m0 + fmaxf(acc[mi][nj][3] + bb1, 0.0f)*m1;
        }
        p0 += __shfl_xor_sync(0xffffffffu, p0, 4);
        p0 += __shfl_xor_sync(0xffffffffu, p0, 8);
        p0 += __shfl_xor_sync(0xffffffffu, p0, 16);
        p1 += __shfl_xor_sync(0xffffffffu, p1, 4);
        p1 += __shfl_xor_sync(0xffffffffu, p1, 8);
        p1 += __shfl_xor_sync(0xffffffffu, p1, 16);
        if (g == 0) {
            red[wm*128 + cl]     = p0;
            red[wm*128 + cl + 1] = p1;
        }
    }
    __syncthreads();
    if (tid < 128) {
        float tsum = red[tid] + red[128 + tid] + red[256 + tid] + red[384 + tid];
        g_part[((size_t)n*7 + rg)*256 + half*128 + tid] = tsum;
    }
}

// ---------------- Threefry2x32 (exact JAX, partitionable) ----------------
static __device__ __forceinline__ void tf2(unsigned k0, unsigned k1, unsigned &x0, unsigned &x1) {
    unsigned ks2 = k0 ^ k1 ^ 0x1BD11BDAu;
    x0 += k0; x1 += k1;
#define TFR(r) { x0 += x1; x1 = __funnelshift_l(x1, x1, r); x1 ^= x0; }
    TFR(13) TFR(15) TFR(26) TFR(6)   x0 += k1;  x1 += ks2 + 1u;
    TFR(17) TFR(29) TFR(16) TFR(24)  x0 += ks2; x1 += k0 + 2u;
    TFR(13) TFR(15) TFR(26) TFR(6)   x0 += k0;  x1 += k1 + 3u;
    TFR(17) TFR(29) TFR(16) TFR(24)  x0 += k1;  x1 += ks2 + 4u;
    TFR(13) TFR(15) TFR(26) TFR(6)   x0 += ks2; x1 += k0 + 5u;
#undef TFR
}
static __device__ __forceinline__ float u01(unsigned bits) {
    return __uint_as_float((bits >> 9) | 0x3f800000u) - 1.0f;
}
static __device__ float erfinv_f(float x) {
    float w = -log1pf(-x*x);
    float p;
    if (w < 5.0f) {
        w -= 2.5f;
        p = 2.81022636e-08f;
        p = fmaf(p, w, 3.43273939e-07f);
        p = fmaf(p, w, -3.5233877e-06f);
        p = fmaf(p, w, -4.39150654e-06f);
        p = fmaf(p, w, 0.00021858087f);
        p = fmaf(p, w, -0.00125372503f);
        p = fmaf(p, w, -0.00417768164f);
        p = fmaf(p, w, 0.246640727f);
        p = fmaf(p, w, 1.50140941f);
    } else {
        w = sqrtf(w) - 3.0f;
        p = -0.000200214257f;
        p = fmaf(p, w, 0.000100950558f);
        p = fmaf(p, w, 0.00134934322f);
        p = fmaf(p, w, -0.00367342844f);
        p = fmaf(p, w, 0.00573950773f);
        p = fmaf(p, w, -0.0076224613f);
        p = fmaf(p, w, 0.00943887047f);
        p = fmaf(p, w, 1.00167406f);
        p = fmaf(p, w, 2.83297682f);
    }
    return p * x;
}

// ---------------- fused tail: fc + mu/kappa + vMF sample + MLP ----------------
// grid 64 (one per batch row), 512 threads
__global__ void __launch_bounds__(512)
k_tail(const float* __restrict__ Wh,  const float* __restrict__ bh,
       const float* __restrict__ Wmu, const float* __restrict__ bmu,
       const float* __restrict__ Wk,  const float* __restrict__ bk,
       const float* __restrict__ M1,  const float* __restrict__ bM1,
       const float* __restrict__ M2,  const float* __restrict__ bM2,
       const float* __restrict__ M3,  const float* __restrict__ bM3,
       const float* __restrict__ M4,  const float* __restrict__ bM4,
       float* __restrict__ out, float* __restrict__ omu, float* __restrict__ okap) {
    __shared__ float p[256];
    __shared__ float h[512];
    __shared__ float redmu[16][32];
    __shared__ float mus[32];
    __shared__ float kapsh;
    __shared__ float s_w[10];
    __shared__ int   s_a[10];
    __shared__ float zs[32];
    __shared__ float y1[512];
    __shared__ float y2[512];
    __shared__ float red3[32][8];
    __shared__ float y3[32];
    int b = blockIdx.x, tid = threadIdx.x;

    if (tid < 256) {
        float sv = 0.0f;
        const float* pp = g_part + (size_t)b*7*256 + tid;
        #pragma unroll
        for (int tt = 0; tt < 7; tt++) sv += pp[tt*256];
        p[tid] = sv * (1.0f/784.0f);
    }
    __syncthreads();
    {
        float a0 = 0.f, a1 = 0.f, a2 = 0.f, a3 = 0.f;
        #pragma unroll 4
        for (int k = 0; k < 256; k += 4) {
            a0 = fmaf(p[k],   Wh[(k)*512 + tid],   a0);
            a1 = fmaf(p[k+1], Wh[(k+1)*512 + tid], a1);
            a2 = fmaf(p[k+2], Wh[(k+2)*512 + tid], a2);
            a3 = fmaf(p[k+3], Wh[(k+3)*512 + tid], a3);
        }
        h[tid] = bh[tid] + ((a0 + a1) + (a2 + a3));
    }
    __syncthreads();
    {
        int o = tid & 31, seg = tid >> 5;
        float a = 0.f;
        #pragma unroll 4
        for (int tt = 0; tt < 32; tt++) {
            int k = seg*32 + tt;
            a = fmaf(h[k], Wmu[k*32 + o], a);
        }
        redmu[seg][o] = a;
    }
    __syncthreads();
    if (tid < 32) {
        float acc = bmu[tid];
        #pragma unroll
        for (int s2 = 0; s2 < 16; s2++) acc += redmu[s2][tid];
        float ss = acc * acc;
        #pragma unroll
        for (int of = 16; of; of >>= 1) ss += __shfl_xor_sync(0xffffffffu, ss, of);
        float m = acc / sqrtf(fmaxf(ss, 1e-24f));
        mus[tid] = m;
        if (omu) omu[b*32 + tid] = m;
    } else if (tid < 64) {
        int l = tid - 32;
        float a = 0.f;
        #pragma unroll
        for (int tt = 0; tt < 16; tt++) {
            int k = l*16 + tt;
            a = fmaf(h[k], Wk[k], a);
        }
        #pragma unroll
        for (int of = 16; of; of >>= 1) a += __shfl_xor_sync(0xffffffffu, a, of);
        if (l == 0) {
            float acc = a + bk[0];
            float sp = fmaxf(acc, 0.0f) + log1pf(expf(-fabsf(acc)));
            float kap = sp + 1.0f;
            kapsh = kap;
            if (okap) okap[b] = kap;
        }
    }
    __syncthreads();
    if (tid < 32) {
        int lane = tid;
        unsigned a0,a1,c0,c1;
        { unsigned x0=0u, x1=0u; tf2(0u,42u,x0,x1); a0=x0; a1=x1; }   // k_w
        { unsigned x0=0u, x1=1u; tf2(0u,42u,x0,x1); c0=x0; c1=x1; }   // k_v
        float kap = kapsh;
        if (lane < 10) {
            unsigned f0,f1,h0,h1;
            { unsigned x0=0u, x1=(unsigned)(2*lane);   tf2(a0,a1,x0,x1); f0=x0; f1=x1; }
            { unsigned x0=0u, x1=(unsigned)(2*lane+1); tf2(a0,a1,x0,x1); h0=x0; h1=x1; }
            unsigned bw, br;
            { unsigned x0=0u, x1=(unsigned)b; tf2(f0,f1,x0,x1); bw = x0 ^ x1; }
            { unsigned x0=0u, x1=(unsigned)b; tf2(h0,h1,x0,x1); br = x0 ^ x1; }
            float wc = 2.0f*u01(bw) - 1.0f;
            float om = fmaxf(1.0f - wc*wc, 1e-40f);
            float lp = kap*wc + 14.5f*logf(om);
            float lr = logf(u01(br) + 1e-40f);
            s_w[lane] = wc;
            s_a[lane] = (lr + kap <= lp) ? 1 : 0;
        }
        __syncwarp();
        float w = 0.0f;
        #pragma unroll
        for (int i = 9; i >= 0; i--) if (s_a[i]) w = s_w[i];
        w = fminf(fmaxf(w, -1.0f), 1.0f);

        float vj = 0.0f;
        if (lane < 31) {
            int e = b*31 + lane;
            unsigned bits;
            { unsigned x0=0u, x1=(unsigned)e; tf2(c0,c1,x0,x1); bits = x0 ^ x1; }
            float u = u01(bits);
            const float LO = -0.99999994f;
            float un = fmaxf(LO, fmaf(u, 2.0f, LO));
            vj = 1.4142135623730951f * erfinv_f(un);
        }
        float ss = vj*vj;
        #pragma unroll
        for (int o = 16; o; o >>= 1) ss += __shfl_xor_sync(0xffffffffu, ss, o);
        vj /= sqrtf(fmaxf(ss, 1e-24f));

        float st = sqrtf(fmaxf(1.0f - w*w, 1e-40f));
        float zt = (lane < 31) ? st*vj : w;

        float mub = mus[lane];
        float uj = ((lane == 31) ? 1.0f : 0.0f) - mub;
        float us = uj*uj;
        #pragma unroll
        for (int o = 16; o; o >>= 1) us += __shfl_xor_sync(0xffffffffu, us, o);
        uj /= sqrtf(fmaxf(us, 1e-24f));
        float dp = zt*uj;
        #pragma unroll
        for (int o = 16; o; o >>= 1) dp += __shfl_xor_sync(0xffffffffu, dp, o);
        zs[lane] = zt - 2.0f*dp*uj;
    }
    __syncthreads();
    {
        float acc = bM1[tid];
        #pragma unroll
        for (int k = 0; k < 32; k++) acc = fmaf(zs[k], M1[k*512 + tid], acc);
        y1[tid] = fmaxf(acc, 0.0f);
    }
    __syncthreads();
    {
        float a0 = 0.f, a1 = 0.f, a2 = 0.f, a3 = 0.f;
        #pragma unroll 4
        for (int k = 0; k < 512; k += 4) {
            a0 = fmaf(y1[k],   M2[(k)*512 + tid],   a0);
            a1 = fmaf(y1[k+1], M2[(k+1)*512 + tid], a1);
            a2 = fmaf(y1[k+2], M2[(k+2)*512 + tid], a2);
            a3 = fmaf(y1[k+3], M2[(k+3)*512 + tid], a3);
        }
        y2[tid] = fmaxf(bM2[tid] + ((a0 + a1) + (a2 + a3)), 0.0f);
    }
    __syncthreads();
    if (tid < 256) {
        int o = tid >> 3, pp = tid & 7;
        float a = 0.f;
        #pragma unroll 4
        for (int tt = 0; tt < 64; tt++) {
            int k = pp*64 + tt;
            a = fmaf(y2[k], M3[k*32 + o], a);
        }
        red3[o][pp] = a;
    }
    __syncthreads();
    if (tid < 32) {
        float a = bM3[tid];
        #pragma unroll
        for (int pp = 0; pp < 8; pp++) a += red3[tid][pp];
        y3[tid] = fmaxf(a, 0.0f);
    }
    __syncthreads();
    if (tid < 7) {
        float acc = bM4[tid];
        #pragma unroll
        for (int k = 0; k < 32; k++) acc = fmaf(y3[k], M4[k*7 + tid], acc);
        out[b*7 + tid] = acc;
    }
}

// ---------------- launch ----------------
extern "C" void kernel_launch(void* const* d_in, const int* in_sizes, int n_in,
                              void* d_out, int out_size) {
    const float* x   = (const float*)d_in[0];
    const float* W1  = (const float*)d_in[1];
    const float* b1  = (const float*)d_in[2];
    const float* W2  = (const float*)d_in[3];
    const float* b2  = (const float*)d_in[4];
    const float* Wh  = (const float*)d_in[5];
    const float* bh  = (const float*)d_in[6];
    const float* Wmu = (const float*)d_in[7];
    const float* bmu = (const float*)d_in[8];
    const float* Wk  = (const float*)d_in[9];
    const float* bk  = (const float*)d_in[10];
    const float* M1  = (const float*)d_in[11];
    const float* bM1 = (const float*)d_in[12];
    const float* M2  = (const float*)d_in[13];
    const float* bM2 = (const float*)d_in[14];
    const float* M3  = (const float*)d_in[15];
    const float* bM3 = (const float*)d_in[16];
    const float* M4  = (const float*)d_in[17];
    const float* bM4 = (const float*)d_in[18];

    float* out  = (float*)d_out;
    float* omu  = (out_size >= 2560) ? out + 448  : nullptr;   // tuple order: out, mu, kappa
    float* okap = (out_size >= 2560) ? out + 2496 : nullptr;

    cudaFuncSetAttribute(k_conv1, cudaFuncAttributeMaxDynamicSharedMemorySize, C1_SMEM);
    cudaFuncSetAttribute(k_conv2, cudaFuncAttributeMaxDynamicSharedMemorySize, C2_SMEM);

    k_prew<<<128, 256>>>(W1, W2);
    k_prex<<<4704, 256>>>(x);
    k_conv1<<<dim3(28, 64), 256, C1_SMEM>>>(b1);
    k_conv2<<<dim3(7, 64, 2), 256, C2_SMEM>>>(b2);
    k_tail<<<64, 512>>>(Wh, bh, Wmu, bmu, Wk, bk, M1, bM1, M2, bM2, M3, bM3, M4, bM4,
                        out, omu, okap);
}

// round 17
// speedup vs baseline: 3.4430x; 1.0342x over previous
#include <cuda_runtime.h>
#include <cuda_bf16.h>

// ---------------- scratch (static device globals; no allocation) ----------------
__device__ __nv_bfloat16 g_xh[64*6*224*224];   // x hi bf16 (NCHW, same indexing as x)
__device__ __nv_bfloat16 g_xl[64*6*224*224];   // x lo
__device__ __nv_bfloat16 g_c1h[64*56*56*64];   // conv1 out hi, channels-last [n][y][x][oc]
__device__ __nv_bfloat16 g_c1l[64*56*56*64];   // conv1 out lo
__device__ __nv_bfloat16 g_wn1h[64*336];       // conv1 W [oc][k'] hi, k'=ic*56+kh*8+kw (kw7 pad)
__device__ __nv_bfloat16 g_wn1l[64*336];
__device__ __nv_bfloat16 g_wb2h[9*256*64];     // conv2 W [shift][oc][ic] hi
__device__ __nv_bfloat16 g_wb2l[9*256*64];
__device__ float g_part[64*7*256];             // pooled partials [n][rowgroup][oc]

// ---------------- helpers ----------------
static __device__ __forceinline__ void split_bf16(float v, __nv_bfloat16 &hi, __nv_bfloat16 &lo){
    hi = __float2bfloat16(v);
    lo = __float2bfloat16(v - __bfloat162float(hi));
}
static __device__ __forceinline__ unsigned pack2(__nv_bfloat16 a, __nv_bfloat16 b){
    return (unsigned)__bfloat16_as_ushort(a) | ((unsigned)__bfloat16_as_ushort(b) << 16);
}
// packed f32 pair -> bf16x2: result lo = bf16(lo_from), hi = bf16(hi_from)
static __device__ __forceinline__ unsigned cvt2(float lo_from, float hi_from){
    unsigned r; asm("cvt.rn.bf16x2.f32 %0, %1, %2;" : "=r"(r) : "f"(hi_from), "f"(lo_from)); return r;
}
static __device__ __forceinline__ unsigned smem_u32(const void* p){
    unsigned a; asm("{ .reg .u64 t; cvta.to.shared.u64 t, %1; cvt.u32.u64 %0, t; }" : "=r"(a) : "l"(p));
    return a;
}
static __device__ __forceinline__ void ldsm4(unsigned* r, unsigned addr){
    asm volatile("ldmatrix.sync.aligned.m8n8.x4.shared.b16 {%0,%1,%2,%3}, [%4];"
        : "=r"(r[0]), "=r"(r[1]), "=r"(r[2]), "=r"(r[3]) : "r"(addr));
}
static __device__ __forceinline__ void mma_bf16(float* d, const unsigned* a, const unsigned* b){
    asm volatile("mma.sync.aligned.m16n8k16.row.col.f32.bf16.bf16.f32 "
        "{%0,%1,%2,%3}, {%4,%5,%6,%7}, {%8,%9}, {%0,%1,%2,%3};"
        : "+f"(d[0]), "+f"(d[1]), "+f"(d[2]), "+f"(d[3])
        : "r"(a[0]), "r"(a[1]), "r"(a[2]), "r"(a[3]), "r"(b[0]), "r"(b[1]));
}
static __device__ __forceinline__ void cpa16(unsigned dst, const void* src, int n){
    asm volatile("cp.async.ca.shared.global [%0], [%1], 16, %2;"
        :: "r"(dst), "l"(src), "r"(n) : "memory");
}
#define CPA_COMMIT() asm volatile("cp.async.commit_group;" ::: "memory")
#define CPA_WAIT1()  asm volatile("cp.async.wait_group 1;" ::: "memory")
#define CPA_WAIT0()  asm volatile("cp.async.wait_group 0;" ::: "memory")

// ---------------- prep: weights -> bf16 hi/lo ----------------
__global__ void k_prew(const float* __restrict__ W1, const float* __restrict__ W2) {
    int stride = gridDim.x * blockDim.x;
    int i0 = blockIdx.x * blockDim.x + threadIdx.x;
    for (int i = i0; i < 64*336; i += stride) {
        int oc = i / 336, kq = i - oc*336;
        int ic = kq / 56, r = kq - ic*56, kh = r >> 3, kw = r & 7;
        float v = (kw < 7) ? W1[oc*294 + ic*49 + kh*7 + kw] : 0.0f;
        __nv_bfloat16 hi, lo; split_bf16(v, hi, lo);
        g_wn1h[i] = hi; g_wn1l[i] = lo;
    }
    for (int i = i0; i < 9*256*64; i += stride) {
        int ic = i & 63, oc = (i >> 6) & 255, s = i >> 14;
        int kh = s / 3, kw = s - kh*3;
        float v = W2[oc*576 + ic*9 + kh*3 + kw];
        __nv_bfloat16 hi, lo; split_bf16(v, hi, lo);
        g_wb2h[i] = hi; g_wb2l[i] = lo;
    }
}

// ---------------- prex: x -> bf16 hi/lo (16 floats/thread) ----------------
__global__ void __launch_bounds__(256) k_prex(const float* __restrict__ x) {
    size_t fidx = ((size_t)blockIdx.x*256 + threadIdx.x) * 16;
    const float4* xv = (const float4*)(x + fidx);
    unsigned hh[8], ll[8];
    #pragma unroll
    for (int q = 0; q < 4; q++) {
        float4 v = xv[q];
        unsigned h01 = cvt2(v.x, v.y);
        unsigned h23 = cvt2(v.z, v.w);
        float r0 = __uint_as_float(h01 << 16);
        float r1 = __uint_as_float(h01 & 0xFFFF0000u);
        float r2 = __uint_as_float(h23 << 16);
        float r3 = __uint_as_float(h23 & 0xFFFF0000u);
        hh[2*q] = h01; hh[2*q+1] = h23;
        ll[2*q]   = cvt2(v.x - r0, v.y - r1);
        ll[2*q+1] = cvt2(v.z - r2, v.w - r3);
    }
    uint4* oh = (uint4*)((unsigned*)g_xh + (fidx >> 1));
    uint4* ol = (uint4*)((unsigned*)g_xl + (fidx >> 1));
    oh[0] = make_uint4(hh[0],hh[1],hh[2],hh[3]);
    oh[1] = make_uint4(hh[4],hh[5],hh[6],hh[7]);
    ol[0] = make_uint4(ll[0],ll[1],ll[2],ll[3]);
    ol[1] = make_uint4(ll[4],ll[5],ll[6],ll[7]);
}

// ---------------- conv1: HMMA implicit GEMM, ldmatrix frags ----------------
// grid (28 row-pairs, 64 n), 256 thr (8 warps: 4M x 2N). M=128(112 used), K'=336 (3 chunks of 112), N=64.
#define C1_B1S  0        // 64 f32
#define C1_AH   1024     // 128x64 u32 = 32KB (256B rows)
#define C1_AL   33792
#define C1_BH   66560    // 64x64 u32 = 16KB
#define C1_BL   82944
#define C1_SMEM 99328
__global__ void __launch_bounds__(256, 2)
k_conv1(const float* __restrict__ b1) {
    extern __shared__ char smc[];
    float* b1s = (float*)(smc + C1_B1S);
    int pr = blockIdx.x, n = blockIdx.y;
    int tid = threadIdx.x, wid = tid >> 5, lane = tid & 31;
    int g = lane >> 2, t = lane & 3;
    int wm = wid >> 1, wn = wid & 1;
    int rowblk = wm*32, colblk = wn*32;

    if (tid < 64) b1s[tid] = b1[tid];

    // ldmatrix per-lane address precompute
    unsigned sb = smem_u32(smc);
    int rA = rowblk + (lane & 15);
    int r7A = rA & 7;
    unsigned aAH = sb + C1_AH + rA*256;            // + mi*4096 + ((cc^r7A)<<4)
    unsigned aAL = sb + C1_AL + rA*256;
    int ccA = lane >> 4;                            // + 2ks
    int ocB = colblk + (lane & 7) + 8*(lane >> 4);  // + 16p
    int r7B = lane & 7;
    unsigned aBH = sb + C1_BH + ocB*256;            // + p*4096 + ((cc^r7B)<<4)
    unsigned aBL = sb + C1_BL + ocB*256;
    int ccB = (lane >> 3) & 1;                      // + 2ks

    float acc[2][4][4];
    #pragma unroll
    for (int mi = 0; mi < 2; mi++)
        #pragma unroll
        for (int nj = 0; nj < 4; nj++)
            #pragma unroll
            for (int q = 0; q < 4; q++) acc[mi][nj][q] = 0.0f;

    for (int c = 0; c < 3; c++) {
        __syncthreads();
        // ---- stage A: items = (row, icL, kh); each item = 8 bf16 (kw 0..6 + pad) ----
        #pragma unroll 1
        for (int j = 0; j < 7; j++) {
            int it = tid + 256*j;            // [0, 1792)
            int row = it & 127;
            int icL = (it >> 7) & 1;
            int kh  = it >> 8;               // 0..6
            unsigned r0=0,r1=0,r2=0,r3=0, s0=0,s1=0,s2=0,s3=0;
            if (row < 112) {
                int hi56 = (row >= 56);
                int oy = pr*2 + hi56;
                int ox = row - (hi56 ? 56 : 0);
                int iy = 4*oy - 3 + kh;
                if (iy >= 0) {
                    int ic = c*2 + icL;
                    size_t base = (size_t)n*301056 + (size_t)(ic*224 + iy)*224;
                    if (ox > 0) {
                        const uint2* ph = (const uint2*)(g_xh + base + 4*ox - 4);
                        const uint2* pl = (const uint2*)(g_xl + base + 4*ox - 4);
                        uint2 a = ph[0], bq = ph[1];
                        uint2 e = pl[0], f = pl[1];
                        r0 = __funnelshift_r(a.x, a.y, 16);
                        r1 = __funnelshift_r(a.y, bq.x, 16);
                        r2 = __funnelshift_r(bq.x, bq.y, 16);
                        r3 = bq.y >> 16;
                        s0 = __funnelshift_r(e.x, e.y, 16);
                        s1 = __funnelshift_r(e.y, f.x, 16);
                        s2 = __funnelshift_r(f.x, f.y, 16);
                        s3 = f.y >> 16;
                    } else {
                        uint2 a = *(const uint2*)(g_xh + base);   // ix 0..3 -> kw 3..6
                        uint2 e = *(const uint2*)(g_xl + base);
                        r1 = (a.x & 0xFFFFu) << 16;
                        r2 = __funnelshift_r(a.x, a.y, 16);
                        r3 = a.y >> 16;
                        s1 = (e.x & 0xFFFFu) << 16;
                        s2 = __funnelshift_r(e.x, e.y, 16);
                        s3 = e.y >> 16;
                    }
                }
            }
            int kp0 = icL*28 + kh*4;
            unsigned dofs = (unsigned)(row*256 + (((kp0>>2) ^ (row & 7)) << 4));
            *(uint4*)(smc + C1_AH + dofs) = make_uint4(r0,r1,r2,r3);
            *(uint4*)(smc + C1_AL + dofs) = make_uint4(s0,s1,s2,s3);
        }
        // ---- stage B: 64 oc x 14 uint4 per array ----
        #pragma unroll 1
        for (int e = tid; e < 1792; e += 256) {
            int arr = (e >= 896);
            int e2 = arr ? e - 896 : e;
            int oc = e2 / 14, q = e2 - oc*14;
            const unsigned* src = (arr ? (const unsigned*)g_wn1l : (const unsigned*)g_wn1h)
                                  + oc*168 + c*56 + q*4;
            uint4 v = *(const uint4*)src;
            char* dst = smc + (arr ? C1_BL : C1_BH) + oc*256 + ((q ^ (oc & 7)) << 4);
            *(uint4*)dst = v;
        }
        __syncthreads();

        #pragma unroll
        for (int ks = 0; ks < 7; ks++) {
            unsigned offA = (unsigned)(((2*ks + ccA) ^ r7A) << 4);
            unsigned offB = (unsigned)(((2*ks + ccB) ^ r7B) << 4);
            unsigned ah0[4], ah1[4], al0[4], al1[4], bt[4];
            ldsm4(ah0, aAH + offA);
            ldsm4(ah1, aAH + 4096 + offA);
            #pragma unroll
            for (int p = 0; p < 2; p++) {        // ah . bh
                ldsm4(bt, aBH + p*4096 + offB);
                mma_bf16(acc[0][2*p],   ah0, bt);
                mma_bf16(acc[1][2*p],   ah1, bt);
                mma_bf16(acc[0][2*p+1], ah0, bt+2);
                mma_bf16(acc[1][2*p+1], ah1, bt+2);
            }
            #pragma unroll
            for (int p = 0; p < 2; p++) {        // ah . bl
                ldsm4(bt, aBL + p*4096 + offB);
                mma_bf16(acc[0][2*p],   ah0, bt);
                mma_bf16(acc[1][2*p],   ah1, bt);
                mma_bf16(acc[0][2*p+1], ah0, bt+2);
                mma_bf16(acc[1][2*p+1], ah1, bt+2);
            }
            ldsm4(al0, aAL + offA);
            ldsm4(al1, aAL + 4096 + offA);
            #pragma unroll
            for (int p = 0; p < 2; p++) {        // al . bh
                ldsm4(bt, aBH + p*4096 + offB);
                mma_bf16(acc[0][2*p],   al0, bt);
                mma_bf16(acc[1][2*p],   al1, bt);
                mma_bf16(acc[0][2*p+1], al0, bt+2);
                mma_bf16(acc[1][2*p+1], al1, bt+2);
            }
        }
    }

    // epilogue: bias + relu + split -> channels-last bf16 hi/lo
    #pragma unroll
    for (int mi = 0; mi < 2; mi++) {
        #pragma unroll
        for (int nj = 0; nj < 4; nj++) {
            int cc = colblk + nj*8 + 2*t;
            float bb0 = b1s[cc], bb1 = b1s[cc + 1];
            #pragma unroll
            for (int rh = 0; rh < 2; rh++) {
                int s = rowblk + mi*16 + g + rh*8;
                if (s < 112) {
                    float v0 = fmaxf(acc[mi][nj][rh*2]     + bb0, 0.0f);
                    float v1 = fmaxf(acc[mi][nj][rh*2 + 1] + bb1, 0.0f);
                    int hi56 = (s >= 56);
                    int oy = pr*2 + hi56, ox = s - (hi56 ? 56 : 0);
                    size_t ob = ((size_t)(n*56 + oy)*56 + ox)*64 + cc;
                    __nv_bfloat16 h0, l0, h1, l1;
                    split_bf16(v0, h0, l0); split_bf16(v1, h1, l1);
                    *(unsigned*)(g_c1h + ob) = pack2(h0, h1);
                    *(unsigned*)(g_c1l + ob) = pack2(l0, l1);
                }
            }
        }
    }
}

// ---------------- conv2: HMMA, cp.async double-buffered pipeline, batched frags ----------------
// grid (7 rowgroups, 64 n, 2 oc-halves), 256 thr (8 warps: 4M x 2N).
// M=128(112 used: 4 rows x 28), K=64 per shift x 9 shifts, N=128 (this block's half).
// smem: 2 buffers x (AH 16K | AL 16K | BH 16K | BL 16K) = 128KB, 1 block/SM.
#define C2_B2S   0
#define C2_RED   1024
#define C2_RC    3072     // 128 ints: packed (2oy-1, 2ox-1) per A row
#define C2_BUF0  4096
#define C2_BUFSZ 65536
#define C2_SMEM  (4096 + 2*65536)
__global__ void __launch_bounds__(256, 1)
k_conv2(const float* __restrict__ b2) {
    extern __shared__ char smc[];
    float* b2s = (float*)(smc + C2_B2S);
    float* red = (float*)(smc + C2_RED);
    int*  rowco = (int*)(smc + C2_RC);
    int rg = blockIdx.x, n = blockIdx.y, half = blockIdx.z;
    int tid = threadIdx.x, wid = tid >> 5, lane = tid & 31;
    int g = lane >> 2, t = lane & 3;
    int wm = wid >> 1, wn = wid & 1;
    int rowblk = wm*32, colblk = wn*64;
    unsigned sb = smem_u32(smc);

    if (tid < 128) b2s[tid] = b2[half*128 + tid];
    if (tid < 128) {
        int rc;
        if (tid < 112) {
            int oy = rg*4 + tid / 28, ox = tid % 28;
            rc = ((2*oy - 1) << 16) | ((2*ox - 1) & 0xFFFF);
        } else {
            rc = (-1000 << 16) | ((-1000) & 0xFFFF);
        }
        rowco[tid] = rc;
    }
    __syncthreads();

    // ldmatrix per-lane offsets (within a buffer; 128B rows)
    int rA = rowblk + (lane & 15);
    int r7A = rA & 7;
    unsigned oA = rA*128u;                          // AH at +0, AL at +16384
    int ccA = lane >> 4;
    int ocB = colblk + (lane & 7) + 8*(lane >> 4);
    int r7B = lane & 7;
    unsigned oB = 32768u + ocB*128u;                // BH at +32768, BL at +49152
    int ccB = (lane >> 3) & 1;

    float acc[2][8][4];
    #pragma unroll
    for (int mi = 0; mi < 2; mi++)
        #pragma unroll
        for (int nj = 0; nj < 8; nj++)
            #pragma unroll
            for (int q = 0; q < 4; q++) acc[mi][nj][q] = 0.0f;

    const __nv_bfloat16* c1base = g_c1h;            // g_c1l = g_c1h + (g_c1l - g_c1h); use both ptrs
    size_t nbase = (size_t)n*56*56*64;

    // ---- staging (cp.async) for shift ss into buffer bb ----
    auto stage = [&](int ss, unsigned bb) {
        int kh = ss / 3, kw = ss - kh*3;
        #pragma unroll 1
        for (int e = tid; e < 2048; e += 256) {     // A: hi/lo x 128 rows x 8 q
            int arr = e >> 10, idx = e & 1023;
            int row = idx >> 3, q = idx & 7;
            int rc = rowco[row];
            int iy = (rc >> 16) + kh;
            int ix = (int)(short)(rc & 0xFFFF) + kw;
            const __nv_bfloat16* base = arr ? g_c1l : g_c1h;
            size_t si = 0; int nb = 0;
            if ((unsigned)iy < 56u && (unsigned)ix < 56u) {
                si = nbase + ((size_t)(iy*56 + ix))*64 + q*8;
                nb = 16;
            }
            unsigned dst = sb + bb + (arr ? 16384u : 0u) + row*128u + ((unsigned)(q ^ (row & 7)) << 4);
            cpa16(dst, base + si, nb);
        }
        #pragma unroll 1
        for (int e = tid; e < 2048; e += 256) {     // B: hi/lo x 128 oc x 8 q
            int arr = e >> 10, idx = e & 1023;
            int oc = idx >> 3, q = idx & 7;
            const __nv_bfloat16* src = (arr ? g_wb2l : g_wb2h)
                + ((size_t)(ss*256 + half*128 + oc))*64 + q*8;
            unsigned dst = sb + bb + 32768u + (arr ? 16384u : 0u) + oc*128u + ((unsigned)(q ^ (oc & 7)) << 4);
            cpa16(dst, src, 16);
        }
        CPA_COMMIT();
    };

    stage(0, C2_BUF0);
    for (int s = 0; s < 9; s++) {
        __syncthreads();                            // all warps done with MMA s-1
        if (s + 1 < 9) {
            stage(s + 1, C2_BUF0 + (unsigned)((s + 1) & 1)*C2_BUFSZ);
            CPA_WAIT1();                            // group s landed
        } else {
            CPA_WAIT0();
        }
        __syncthreads();                            // staged data visible to all warps

        unsigned bb = C2_BUF0 + (unsigned)(s & 1)*C2_BUFSZ;
        unsigned aAH = sb + bb + oA, aAL = aAH + 16384u;
        unsigned aBH = sb + bb + oB, aBL = aBH + 16384u;
        #pragma unroll
        for (int ks = 0; ks < 4; ks++) {
            unsigned offA = (unsigned)(((2*ks + ccA) ^ r7A) << 4);
            unsigned offB = (unsigned)(((2*ks + ccB) ^ r7B) << 4);
            // batched fragment loads: 12 ldsm up-front, frags held in regs
            unsigned ah0[4], ah1[4], al0[4], al1[4];
            unsigned bh[4][4], bl[4][4];
            ldsm4(ah0, aAH + offA);
            ldsm4(ah1, aAH + 2048 + offA);
            ldsm4(al0, aAL + offA);
            ldsm4(al1, aAL + 2048 + offA);
            #pragma unroll
            for (int p = 0; p < 4; p++) ldsm4(bh[p], aBH + p*2048 + offB);
            #pragma unroll
            for (int p = 0; p < 4; p++) ldsm4(bl[p], aBL + p*2048 + offB);
            #pragma unroll
            for (int p = 0; p < 4; p++) {
                mma_bf16(acc[0][2*p],   ah0, bh[p]);
                mma_bf16(acc[1][2*p],   ah1, bh[p]);
                mma_bf16(acc[0][2*p+1], ah0, bh[p]+2);
                mma_bf16(acc[1][2*p+1], ah1, bh[p]+2);
                mma_bf16(acc[0][2*p],   al0, bh[p]);
                mma_bf16(acc[1][2*p],   al1, bh[p]);
                mma_bf16(acc[0][2*p+1], al0, bh[p]+2);
                mma_bf16(acc[1][2*p+1], al1, bh[p]+2);
                mma_bf16(acc[0][2*p],   ah0, bl[p]);
                mma_bf16(acc[1][2*p],   ah1, bl[p]);
                mma_bf16(acc[0][2*p+1], ah0, bl[p]+2);
                mma_bf16(acc[1][2*p+1], ah1, bl[p]+2);
            }
        }
    }

    // epilogue: bias + relu + masked pool partials for this half
    __syncthreads();
    #pragma unroll
    for (int nj = 0; nj < 8; nj++) {
        int cl = colblk + nj*8 + 2*t;     // local col in this half [0,128)
        float bb0 = b2s[cl], bb1 = b2s[cl + 1];
        float p0 = 0.0f, p1 = 0.0f;
        #pragma unroll
        for (int mi = 0; mi < 2; mi++) {
            int s0 = rowblk + mi*16 + g;
            float m0 = (s0 < 112) ? 1.0f : 0.0f;
            float m1 = (s0 + 8 < 112) ? 1.0f : 0.0f;
            p0 += fmaxf(acc[mi][nj][0] + bb0, 0.0f)*m0 + fmaxf(acc[mi][nj][2] + bb0, 0.0f)*m1;
            p1 += fmaxf(acc[mi][nj][1] + bb1, 0.0f)*m0 + fmaxf(acc[mi][nj][3] + bb1, 0.0f)*m1;
        }
        p0 += __shfl_xor_sync(0xffffffffu, p0, 4);
        p0 += __shfl_xor_sync(0xffffffffu, p0, 8);
        p0 += __shfl_xor_sync(0xffffffffu, p0, 16);
        p1 += __shfl_xor_sync(0xffffffffu, p1, 4);
        p1 += __shfl_xor_sync(0xffffffffu, p1, 8);
        p1 += __shfl_xor_sync(0xffffffffu, p1, 16);
        if (g == 0) {
            red[wm*128 + cl]     = p0;
            red[wm*128 + cl + 1] = p1;
        }
    }
    __syncthreads();
    if (tid < 128) {
        float tsum = red[tid] + red[128 + tid] + red[256 + tid] + red[384 + tid];
        g_part[((size_t)n*7 + rg)*256 + half*128 + tid] = tsum;
    }
}

// ---------------- Threefry2x32 (exact JAX, partitionable) ----------------
static __device__ __forceinline__ void tf2(unsigned k0, unsigned k1, unsigned &x0, unsigned &x1) {
    unsigned ks2 = k0 ^ k1 ^ 0x1BD11BDAu;
    x0 += k0; x1 += k1;
#define TFR(r) { x0 += x1; x1 = __funnelshift_l(x1, x1, r); x1 ^= x0; }
    TFR(13) TFR(15) TFR(26) TFR(6)   x0 += k1;  x1 += ks2 + 1u;
    TFR(17) TFR(29) TFR(16) TFR(24)  x0 += ks2; x1 += k0 + 2u;
    TFR(13) TFR(15) TFR(26) TFR(6)   x0 += k0;  x1 += k1 + 3u;
    TFR(17) TFR(29) TFR(16) TFR(24)  x0 += k1;  x1 += ks2 + 4u;
    TFR(13) TFR(15) TFR(26) TFR(6)   x0 += ks2; x1 += k0 + 5u;
#undef TFR
}
static __device__ __forceinline__ float u01(unsigned bits) {
    return __uint_as_float((bits >> 9) | 0x3f800000u) - 1.0f;
}
static __device__ float erfinv_f(float x) {
    float w = -log1pf(-x*x);
    float p;
    if (w < 5.0f) {
        w -= 2.5f;
        p = 2.81022636e-08f;
        p = fmaf(p, w, 3.43273939e-07f);
        p = fmaf(p, w, -3.5233877e-06f);
        p = fmaf(p, w, -4.39150654e-06f);
        p = fmaf(p, w, 0.00021858087f);
        p = fmaf(p, w, -0.00125372503f);
        p = fmaf(p, w, -0.00417768164f);
        p = fmaf(p, w, 0.246640727f);
        p = fmaf(p, w, 1.50140941f);
    } else {
        w = sqrtf(w) - 3.0f;
        p = -0.000200214257f;
        p = fmaf(p, w, 0.000100950558f);
        p = fmaf(p, w, 0.00134934322f);
        p = fmaf(p, w, -0.00367342844f);
        p = fmaf(p, w, 0.00573950773f);
        p = fmaf(p, w, -0.0076224613f);
        p = fmaf(p, w, 0.00943887047f);
        p = fmaf(p, w, 1.00167406f);
        p = fmaf(p, w, 2.83297682f);
    }
    return p * x;
}

// ---------------- fused tail: fc + mu/kappa + vMF sample + MLP ----------------
// grid 64 (one per batch row), 512 threads
__global__ void __launch_bounds__(512)
k_tail(const float* __restrict__ Wh,  const float* __restrict__ bh,
       const float* __restrict__ Wmu, const float* __restrict__ bmu,
       const float* __restrict__ Wk,  const float* __restrict__ bk,
       const float* __restrict__ M1,  const float* __restrict__ bM1,
       const float* __restrict__ M2,  const float* __restrict__ bM2,
       const float* __restrict__ M3,  const float* __restrict__ bM3,
       const float* __restrict__ M4,  const float* __restrict__ bM4,
       float* __restrict__ out, float* __restrict__ omu, float* __restrict__ okap) {
    __shared__ float p[256];
    __shared__ float h[512];
    __shared__ float redmu[16][32];
    __shared__ float mus[32];
    __shared__ float kapsh;
    __shared__ float s_w[10];
    __shared__ int   s_a[10];
    __shared__ float zs[32];
    __shared__ float y1[512];
    __shared__ float y2[512];
    __shared__ float red3[32][8];
    __shared__ float y3[32];
    int b = blockIdx.x, tid = threadIdx.x;

    if (tid < 256) {
        float sv = 0.0f;
        const float* pp = g_part + (size_t)b*7*256 + tid;
        #pragma unroll
        for (int tt = 0; tt < 7; tt++) sv += pp[tt*256];
        p[tid] = sv * (1.0f/784.0f);
    }
    __syncthreads();
    {
        float a0 = 0.f, a1 = 0.f, a2 = 0.f, a3 = 0.f;
        #pragma unroll 4
        for (int k = 0; k < 256; k += 4) {
            a0 = fmaf(p[k],   Wh[(k)*512 + tid],   a0);
            a1 = fmaf(p[k+1], Wh[(k+1)*512 + tid], a1);
            a2 = fmaf(p[k+2], Wh[(k+2)*512 + tid], a2);
            a3 = fmaf(p[k+3], Wh[(k+3)*512 + tid], a3);
        }
        h[tid] = bh[tid] + ((a0 + a1) + (a2 + a3));
    }
    __syncthreads();
    {
        int o = tid & 31, seg = tid >> 5;
        float a = 0.f;
        #pragma unroll 4
        for (int tt = 0; tt < 32; tt++) {
            int k = seg*32 + tt;
            a = fmaf(h[k], Wmu[k*32 + o], a);
        }
        redmu[seg][o] = a;
    }
    __syncthreads();
    if (tid < 32) {
        float acc = bmu[tid];
        #pragma unroll
        for (int s2 = 0; s2 < 16; s2++) acc += redmu[s2][tid];
        float ss = acc * acc;
        #pragma unroll
        for (int of = 16; of; of >>= 1) ss += __shfl_xor_sync(0xffffffffu, ss, of);
        float m = acc / sqrtf(fmaxf(ss, 1e-24f));
        mus[tid] = m;
        if (omu) omu[b*32 + tid] = m;
    } else if (tid < 64) {
        int l = tid - 32;
        float a = 0.f;
        #pragma unroll
        for (int tt = 0; tt < 16; tt++) {
            int k = l*16 + tt;
            a = fmaf(h[k], Wk[k], a);
        }
        #pragma unroll
        for (int of = 16; of; of >>= 1) a += __shfl_xor_sync(0xffffffffu, a, of);
        if (l == 0) {
            float acc = a + bk[0];
            float sp = fmaxf(acc, 0.0f) + log1pf(expf(-fabsf(acc)));
            float kap = sp + 1.0f;
            kapsh = kap;
            if (okap) okap[b] = kap;
        }
    }
    __syncthreads();
    if (tid < 32) {
        int lane = tid;
        unsigned a0,a1,c0,c1;
        { unsigned x0=0u, x1=0u; tf2(0u,42u,x0,x1); a0=x0; a1=x1; }   // k_w
        { unsigned x0=0u, x1=1u; tf2(0u,42u,x0,x1); c0=x0; c1=x1; }   // k_v
        float kap = kapsh;
        if (lane < 10) {
            unsigned f0,f1,h0,h1;
            { unsigned x0=0u, x1=(unsigned)(2*lane);   tf2(a0,a1,x0,x1); f0=x0; f1=x1; }
            { unsigned x0=0u, x1=(unsigned)(2*lane+1); tf2(a0,a1,x0,x1); h0=x0; h1=x1; }
            unsigned bw, br;
            { unsigned x0=0u, x1=(unsigned)b; tf2(f0,f1,x0,x1); bw = x0 ^ x1; }
            { unsigned x0=0u, x1=(unsigned)b; tf2(h0,h1,x0,x1); br = x0 ^ x1; }
            float wc = 2.0f*u01(bw) - 1.0f;
            float om = fmaxf(1.0f - wc*wc, 1e-40f);
            float lp = kap*wc + 14.5f*logf(om);
            float lr = logf(u01(br) + 1e-40f);
            s_w[lane] = wc;
            s_a[lane] = (lr + kap <= lp) ? 1 : 0;
        }
        __syncwarp();
        float w = 0.0f;
        #pragma unroll
        for (int i = 9; i >= 0; i--) if (s_a[i]) w = s_w[i];
        w = fminf(fmaxf(w, -1.0f), 1.0f);

        float vj = 0.0f;
        if (lane < 31) {
            int e = b*31 + lane;
            unsigned bits;
            { unsigned x0=0u, x1=(unsigned)e; tf2(c0,c1,x0,x1); bits = x0 ^ x1; }
            float u = u01(bits);
            const float LO = -0.99999994f;
            float un = fmaxf(LO, fmaf(u, 2.0f, LO));
            vj = 1.4142135623730951f * erfinv_f(un);
        }
        float ss = vj*vj;
        #pragma unroll
        for (int o = 16; o; o >>= 1) ss += __shfl_xor_sync(0xffffffffu, ss, o);
        vj /= sqrtf(fmaxf(ss, 1e-24f));

        float st = sqrtf(fmaxf(1.0f - w*w, 1e-40f));
        float zt = (lane < 31) ? st*vj : w;

        float mub = mus[lane];
        float uj = ((lane == 31) ? 1.0f : 0.0f) - mub;
        float us = uj*uj;
        #pragma unroll
        for (int o = 16; o; o >>= 1) us += __shfl_xor_sync(0xffffffffu, us, o);
        uj /= sqrtf(fmaxf(us, 1e-24f));
        float dp = zt*uj;
        #pragma unroll
        for (int o = 16; o; o >>= 1) dp += __shfl_xor_sync(0xffffffffu, dp, o);
        zs[lane] = zt - 2.0f*dp*uj;
    }
    __syncthreads();
    {
        float acc = bM1[tid];
        #pragma unroll
        for (int k = 0; k < 32; k++) acc = fmaf(zs[k], M1[k*512 + tid], acc);
        y1[tid] = fmaxf(acc, 0.0f);
    }
    __syncthreads();
    {
        float a0 = 0.f, a1 = 0.f, a2 = 0.f, a3 = 0.f;
        #pragma unroll 4
        for (int k = 0; k < 512; k += 4) {
            a0 = fmaf(y1[k],   M2[(k)*512 + tid],   a0);
            a1 = fmaf(y1[k+1], M2[(k+1)*512 + tid], a1);
            a2 = fmaf(y1[k+2], M2[(k+2)*512 + tid], a2);
            a3 = fmaf(y1[k+3], M2[(k+3)*512 + tid], a3);
        }
        y2[tid] = fmaxf(bM2[tid] + ((a0 + a1) + (a2 + a3)), 0.0f);
    }
    __syncthreads();
    if (tid < 256) {
        int o = tid >> 3, pp = tid & 7;
        float a = 0.f;
        #pragma unroll 4
        for (int tt = 0; tt < 64; tt++) {
            int k = pp*64 + tt;
            a = fmaf(y2[k], M3[k*32 + o], a);
        }
        red3[o][pp] = a;
    }
    __syncthreads();
    if (tid < 32) {
        float a = bM3[tid];
        #pragma unroll
        for (int pp = 0; pp < 8; pp++) a += red3[tid][pp];
        y3[tid] = fmaxf(a, 0.0f);
    }
    __syncthreads();
    if (tid < 7) {
        float acc = bM4[tid];
        #pragma unroll
        for (int k = 0; k < 32; k++) acc = fmaf(y3[k], M4[k*7 + tid], acc);
        out[b*7 + tid] = acc;
    }
}

// ---------------- launch ----------------
extern "C" void kernel_launch(void* const* d_in, const int* in_sizes, int n_in,
                              void* d_out, int out_size) {
    const float* x   = (const float*)d_in[0];
    const float* W1  = (const float*)d_in[1];
    const float* b1  = (const float*)d_in[2];
    const float* W2  = (const float*)d_in[3];
    const float* b2  = (const float*)d_in[4];
    const float* Wh  = (const float*)d_in[5];
    const float* bh  = (const float*)d_in[6];
    const float* Wmu = (const float*)d_in[7];
    const float* bmu = (const float*)d_in[8];
    const float* Wk  = (const float*)d_in[9];
    const float* bk  = (const float*)d_in[10];
    const float* M1  = (const float*)d_in[11];
    const float* bM1 = (const float*)d_in[12];
    const float* M2  = (const float*)d_in[13];
    const float* bM2 = (const float*)d_in[14];
    const float* M3  = (const float*)d_in[15];
    const float* bM3 = (const float*)d_in[16];
    const float* M4  = (const float*)d_in[17];
    const float* bM4 = (const float*)d_in[18];

    float* out  = (float*)d_out;
    float* omu  = (out_size >= 2560) ? out + 448  : nullptr;   // tuple order: out, mu, kappa
    float* okap = (out_size >= 2560) ? out + 2496 : nullptr;

    cudaFuncSetAttribute(k_conv1, cudaFuncAttributeMaxDynamicSharedMemorySize, C1_SMEM);
    cudaFuncSetAttribute(k_conv2, cudaFuncAttributeMaxDynamicSharedMemorySize, C2_SMEM);

    k_prew<<<128, 256>>>(W1, W2);
    k_prex<<<4704, 256>>>(x);
    k_conv1<<<dim3(28, 64), 256, C1_SMEM>>>(b1);
    k_conv2<<<dim3(7, 64, 2), 256, C2_SMEM>>>(b2);
    k_tail<<<64, 512>>>(Wh, bh, Wmu, bmu, Wk, bk, M1, bM1, M2, bM2, M3, bM3, M4, bM4,
                        out, omu, okap);
}